// round 2
// baseline (speedup 1.0000x reference)
#include <cuda_runtime.h>
#include <math.h>

#define BATCH   2
#define SEQ     2048
#define DMODEL  1024
#define NHEADS  16
#define DK      64
#define NTOK    (BATCH*SEQ)      /* 4096 */
#define E3      (3*DMODEL)       /* 3072 */

// Scratch (allocation-free rule: __device__ globals)
__device__ float g_qkv[(size_t)NTOK * E3];      // ~50 MB
__device__ float g_attn[(size_t)NTOK * DMODEL]; // ~16.8 MB

// ---------------------------------------------------------------------------
// SGEMM core: C[M,N] = A[M,K] * B[N,K]^T   (both A and B are K-contiguous)
// BM=BN=64, BK=32, 256 threads, 4x4 per-thread microtile.
// ---------------------------------------------------------------------------
__device__ __forceinline__ void gemm_nt_body(const float* __restrict__ A,
                                             const float* __restrict__ B,
                                             float* __restrict__ C,
                                             int M, int N, int K)
{
    __shared__ float As[32][68];
    __shared__ float Bs[32][68];

    const int tid = threadIdx.x;            // 0..255
    const int m0  = blockIdx.y * 64;
    const int n0  = blockIdx.x * 64;
    const int tm  = tid >> 4;               // 0..15
    const int tn  = tid & 15;               // 0..15

    float acc[4][4] = {};

    for (int k0 = 0; k0 < K; k0 += 32) {
        // Load A tile (64x32) and B tile (64x32), 2 float4 per thread each.
#pragma unroll
        for (int i = 0; i < 2; i++) {
            int idx = tid + i * 256;        // 0..511
            int row = idx >> 3;             // 0..63
            int c4  = (idx & 7) << 2;       // 0,4,...,28
            float4 a = *(const float4*)&A[(size_t)(m0 + row) * K + k0 + c4];
            As[c4 + 0][row] = a.x; As[c4 + 1][row] = a.y;
            As[c4 + 2][row] = a.z; As[c4 + 3][row] = a.w;
            float4 b = *(const float4*)&B[(size_t)(n0 + row) * K + k0 + c4];
            Bs[c4 + 0][row] = b.x; Bs[c4 + 1][row] = b.y;
            Bs[c4 + 2][row] = b.z; Bs[c4 + 3][row] = b.w;
        }
        __syncthreads();

#pragma unroll
        for (int k = 0; k < 32; k++) {
            float4 a4 = *(const float4*)&As[k][tm * 4];
            float4 b4 = *(const float4*)&Bs[k][tn * 4];
            float av[4] = {a4.x, a4.y, a4.z, a4.w};
            float bv[4] = {b4.x, b4.y, b4.z, b4.w};
#pragma unroll
            for (int i = 0; i < 4; i++)
#pragma unroll
                for (int j = 0; j < 4; j++)
                    acc[i][j] += av[i] * bv[j];
        }
        __syncthreads();
    }

#pragma unroll
    for (int i = 0; i < 4; i++) {
        float4 v = make_float4(acc[i][0], acc[i][1], acc[i][2], acc[i][3]);
        *(float4*)&C[(size_t)(m0 + tm * 4 + i) * N + n0 + tn * 4] = v;
    }
}

__global__ __launch_bounds__(256)
void qkv_gemm_kernel(const float* __restrict__ x, const float* __restrict__ w_qkv)
{
    gemm_nt_body(x, w_qkv, g_qkv, NTOK, E3, DMODEL);
}

__global__ __launch_bounds__(256)
void out_gemm_kernel(const float* __restrict__ w_o, float* __restrict__ out)
{
    gemm_nt_body(g_attn, w_o, out, NTOK, DMODEL, DMODEL);
}

// ---------------------------------------------------------------------------
// RoPE applied in-place to Q and K halves of g_qkv.
// One thread per (token, head, freq-pair) -> handles both q and k pairs.
// ---------------------------------------------------------------------------
__global__ void rope_kernel(const int* __restrict__ pos)
{
    int t = blockIdx.x * blockDim.x + threadIdx.x;
    const int total = NTOK * NHEADS * (DK / 2);
    if (t >= total) return;

    int i = t & 31;                  // freq index 0..31
    int h = (t >> 5) & (NHEADS - 1);
    int n = t >> 9;                  // token index 0..4095
    int s = n & (SEQ - 1);

    float p = (float)pos[s];
    // inv_freq = 10000^{-i/32}
    float inv = expf(-((float)i / 32.0f) * 9.2103403719761836f);
    float ang = p * inv;
    float sn, cs;
    sincosf(ang, &sn, &cs);

    float* q = &g_qkv[(size_t)n * E3 + h * DK + 2 * i];
    float q1 = q[0], q2 = q[1];
    q[0] = q1 * cs - q2 * sn;
    q[1] = q1 * sn + q2 * cs;

    float* k = q + DMODEL;
    float k1 = k[0], k2 = k[1];
    k[0] = k1 * cs - k2 * sn;
    k[1] = k1 * sn + k2 * cs;
}

// ---------------------------------------------------------------------------
// Causal flash attention, fp32.
// Grid: (S/64, NHEADS, BATCH). 64 threads/block; thread r owns query row r
// of the 64-row Q tile. K/V tiles of 64 rows streamed through smem.
// Scores staged as Ss[c][r] (conflict-free: uniform c, r = lane).
// ---------------------------------------------------------------------------
__global__ __launch_bounds__(64)
void attn_kernel()
{
    const int qt = blockIdx.x;
    const int h  = blockIdx.y;
    const int b  = blockIdx.z;
    const int r  = threadIdx.x;           // 0..63
    const int qrow = qt * 64 + r;

    __shared__ float Ks[64][64];
    __shared__ float Vs[64][64];
    __shared__ float Ss[64][64];          // [c][r]

    const float scale = 0.125f;           // 1/sqrt(64)

    // Load this thread's q row (pre-scaled) into registers.
    float4 q[16];
    const float* qptr = &g_qkv[((size_t)(b * SEQ) + qrow) * E3 + h * DK];
#pragma unroll
    for (int i = 0; i < 16; i++) {
        float4 v = *(const float4*)&qptr[4 * i];
        v.x *= scale; v.y *= scale; v.z *= scale; v.w *= scale;
        q[i] = v;
    }

    float4 o[16];
#pragma unroll
    for (int i = 0; i < 16; i++) o[i] = make_float4(0.f, 0.f, 0.f, 0.f);
    float m = -1e30f, l = 0.f;

    for (int kt = 0; kt <= qt; kt++) {
        __syncthreads();   // previous tile fully consumed before overwrite
        const float* kbase = &g_qkv[((size_t)(b * SEQ) + kt * 64) * E3 + DMODEL + h * DK];
        const float* vbase = kbase + DMODEL;
#pragma unroll
        for (int i = 0; i < 16; i++) {
            int idx = r + i * 64;          // 0..1023
            int row = idx >> 4;            // 0..63
            int c4  = (idx & 15) << 2;     // 0..60
            *(float4*)&Ks[row][c4] = *(const float4*)&kbase[(size_t)row * E3 + c4];
            *(float4*)&Vs[row][c4] = *(const float4*)&vbase[(size_t)row * E3 + c4];
        }
        __syncthreads();

        // Scores for this thread's row against all 64 keys of the tile.
        float tmax = -1e30f;
        const bool diag = (kt == qt);
#pragma unroll 4
        for (int c = 0; c < 64; c++) {
            float ax = 0.f, ay = 0.f, az = 0.f, aw = 0.f;
#pragma unroll
            for (int i = 0; i < 16; i++) {
                float4 kv = *(const float4*)&Ks[c][4 * i];  // broadcast across lanes
                ax += q[i].x * kv.x; ay += q[i].y * kv.y;
                az += q[i].z * kv.z; aw += q[i].w * kv.w;
            }
            float s = (ax + ay) + (az + aw);
            if (diag && c > r) s = -1e30f;
            tmax = fmaxf(tmax, s);
            Ss[c][r] = s;
        }

        float mnew = fmaxf(m, tmax);
        float corr = __expf(m - mnew);
        m = mnew;
        l *= corr;
#pragma unroll
        for (int i = 0; i < 16; i++) {
            o[i].x *= corr; o[i].y *= corr; o[i].z *= corr; o[i].w *= corr;
        }

#pragma unroll 2
        for (int c = 0; c < 64; c++) {
            float p = __expf(Ss[c][r] - m);
            l += p;
#pragma unroll
            for (int i = 0; i < 16; i++) {
                float4 v = *(const float4*)&Vs[c][4 * i];   // broadcast
                o[i].x += p * v.x; o[i].y += p * v.y;
                o[i].z += p * v.z; o[i].w += p * v.w;
            }
        }
    }

    float inv = 1.f / l;
    float* op = &g_attn[((size_t)(b * SEQ) + qrow) * DMODEL + h * DK];
#pragma unroll
    for (int i = 0; i < 16; i++) {
        float4 v = o[i];
        v.x *= inv; v.y *= inv; v.z *= inv; v.w *= inv;
        *(float4*)&op[4 * i] = v;
    }
}

// ---------------------------------------------------------------------------
extern "C" void kernel_launch(void* const* d_in, const int* in_sizes, int n_in,
                              void* d_out, int out_size)
{
    const float* x      = (const float*)d_in[0];
    const int*   pos    = (const int*)d_in[1];
    const float* w_qkv  = (const float*)d_in[2];
    const float* w_o    = (const float*)d_in[3];
    float*       out    = (float*)d_out;

    // 1) QKV projection: [4096,3072] = [4096,1024] x [3072,1024]^T
    {
        dim3 grid(E3 / 64, NTOK / 64);
        qkv_gemm_kernel<<<grid, 256>>>(x, w_qkv);
    }
    // 2) RoPE on q and k, in place
    {
        int total = NTOK * NHEADS * (DK / 2);
        rope_kernel<<<(total + 255) / 256, 256>>>(pos);
    }
    // 3) Causal flash attention
    {
        dim3 grid(SEQ / 64, NHEADS, BATCH);
        attn_kernel<<<grid, 64>>>();
    }
    // 4) Output projection: [4096,1024] = [4096,1024] x [1024,1024]^T
    {
        dim3 grid(DMODEL / 64, NTOK / 64);
        out_gemm_kernel<<<grid, 256>>>(w_o, out);
    }
}

// round 4
// speedup vs baseline: 1.4411x; 1.4411x over previous
#include <cuda_runtime.h>
#include <cuda_fp16.h>
#include <math.h>

#define BATCH   2
#define SEQ     2048
#define DMODEL  1024
#define NHEADS  16
#define DK      64
#define NTOK    (BATCH*SEQ)      /* 4096 */
#define E3      (3*DMODEL)       /* 3072 */

// Scratch (allocation-free rule: __device__ globals)
__device__ float  g_qkv[(size_t)NTOK * E3];
__device__ float  g_attn[(size_t)NTOK * DMODEL];
// hi/lo fp16 split operands
__device__ __half g_xh[(size_t)NTOK * DMODEL],  g_xl[(size_t)NTOK * DMODEL];
__device__ __half g_wqh[(size_t)E3 * DMODEL],   g_wql[(size_t)E3 * DMODEL];
__device__ __half g_woh[(size_t)DMODEL*DMODEL], g_wol[(size_t)DMODEL*DMODEL];
__device__ __half g_ah[(size_t)NTOK * DMODEL],  g_al[(size_t)NTOK * DMODEL];

// ---------------------------------------------------------------------------
// hi/lo split conversion: 4 floats per thread
// ---------------------------------------------------------------------------
__device__ __forceinline__ void split_store(float4 v, __half* dh, __half* dl)
{
    __half2 h01 = __floats2half2_rn(v.x, v.y);
    __half2 h23 = __floats2half2_rn(v.z, v.w);
    float2 f01 = __half22float2(h01);
    float2 f23 = __half22float2(h23);
    __half2 l01 = __floats2half2_rn(v.x - f01.x, v.y - f01.y);
    __half2 l23 = __floats2half2_rn(v.z - f23.x, v.w - f23.y);
    *(__half2*)&dh[0] = h01;  *(__half2*)&dh[2] = h23;
    *(__half2*)&dl[0] = l01;  *(__half2*)&dl[2] = l23;
}

__global__ void cvt_x_kernel(const float* __restrict__ x) {
    int i = blockIdx.x * blockDim.x + threadIdx.x;
    if (i >= NTOK * DMODEL / 4) return;
    split_store(((const float4*)x)[i], g_xh + (size_t)i*4, g_xl + (size_t)i*4);
}
__global__ void cvt_wq_kernel(const float* __restrict__ w) {
    int i = blockIdx.x * blockDim.x + threadIdx.x;
    if (i >= E3 * DMODEL / 4) return;
    split_store(((const float4*)w)[i], g_wqh + (size_t)i*4, g_wql + (size_t)i*4);
}
__global__ void cvt_wo_kernel(const float* __restrict__ w) {
    int i = blockIdx.x * blockDim.x + threadIdx.x;
    if (i >= DMODEL * DMODEL / 4) return;
    split_store(((const float4*)w)[i], g_woh + (size_t)i*4, g_wol + (size_t)i*4);
}
__global__ void cvt_attn_kernel() {
    int i = blockIdx.x * blockDim.x + threadIdx.x;
    if (i >= NTOK * DMODEL / 4) return;
    split_store(((const float4*)g_attn)[i], g_ah + (size_t)i*4, g_al + (size_t)i*4);
}

// ---------------------------------------------------------------------------
// fp16 (hi/lo) tensor-core GEMM: C[M,N] = A[M,K] * B[N,K]^T, fp32 accumulate.
// Block 128x128, BK=32, 256 threads, warp tile 32x64, mma.m16n8k16.
// C = Ah*Bh + Al*Bh + Ah*Bl  (lo*lo term ~2^-22, dropped).
// Smem rows padded to 40 halves (20 words): frag LDS words (20g+tg) mod 32
// cover all 32 banks -> conflict-free.
// ---------------------------------------------------------------------------
#define MMA16816(d, a, b0, b1)                                                 \
    asm volatile("mma.sync.aligned.m16n8k16.row.col.f32.f16.f16.f32 "          \
                 "{%0,%1,%2,%3}, {%4,%5,%6,%7}, {%8,%9}, {%0,%1,%2,%3};"       \
                 : "+f"(d[0]), "+f"(d[1]), "+f"(d[2]), "+f"(d[3])              \
                 : "r"(a[0]), "r"(a[1]), "r"(a[2]), "r"(a[3]), "r"(b0), "r"(b1))

template<int M, int N, int K>
__device__ __forceinline__ void gemm_hl_body(const __half* __restrict__ Ah,
                                             const __half* __restrict__ Al,
                                             const __half* __restrict__ Bh,
                                             const __half* __restrict__ Bl,
                                             float* __restrict__ C)
{
    __shared__ __half sAh[128*40], sAl[128*40], sBh[128*40], sBl[128*40];

    const int tid  = threadIdx.x;
    const int lane = tid & 31;
    const int wid  = tid >> 5;
    const int warpM = wid & 3;
    const int warpN = wid >> 2;
    const int m0 = blockIdx.y * 128;
    const int n0 = blockIdx.x * 128;
    const int g  = lane >> 2;
    const int tg = lane & 3;

    float acc[2][8][4] = {};

    uint4 pah[2], pal[2], pbh[2], pbl[2];

    // prefetch one BK=32 chunk: 128 rows x 32 halves per matrix = 512 uint4
    #define GL(k0)                                                              \
        _Pragma("unroll")                                                       \
        for (int i = 0; i < 2; i++) {                                           \
            int idx = tid + i * 256;                                            \
            int r = idx >> 2, c = (idx & 3) << 3;                               \
            size_t ao = (size_t)(m0 + r) * K + (k0) + c;                        \
            size_t bo = (size_t)(n0 + r) * K + (k0) + c;                        \
            pah[i] = *(const uint4*)&Ah[ao];  pal[i] = *(const uint4*)&Al[ao];  \
            pbh[i] = *(const uint4*)&Bh[bo];  pbl[i] = *(const uint4*)&Bl[bo];  \
        }

    GL(0);

    const int nch = K / 32;
    for (int ch = 0; ch < nch; ch++) {
        #pragma unroll
        for (int i = 0; i < 2; i++) {
            int idx = tid + i * 256;
            int r = idx >> 2, c = (idx & 3) << 3;
            *(uint4*)&sAh[r*40 + c] = pah[i];
            *(uint4*)&sAl[r*40 + c] = pal[i];
            *(uint4*)&sBh[r*40 + c] = pbh[i];
            *(uint4*)&sBl[r*40 + c] = pbl[i];
        }
        __syncthreads();

        if (ch + 1 < nch) { GL((ch + 1) * 32); }

        #pragma unroll
        for (int ks = 0; ks < 2; ks++) {
            const int kb = ks * 16;
            unsigned ah[2][4], al[2][4];
            #pragma unroll
            for (int mi = 0; mi < 2; mi++) {
                int r0 = (warpM*32 + mi*16 + g) * 40 + kb + 2*tg;
                int r8 = r0 + 8*40;
                ah[mi][0] = *(const unsigned*)&sAh[r0];
                ah[mi][1] = *(const unsigned*)&sAh[r8];
                ah[mi][2] = *(const unsigned*)&sAh[r0 + 8];
                ah[mi][3] = *(const unsigned*)&sAh[r8 + 8];
                al[mi][0] = *(const unsigned*)&sAl[r0];
                al[mi][1] = *(const unsigned*)&sAl[r8];
                al[mi][2] = *(const unsigned*)&sAl[r0 + 8];
                al[mi][3] = *(const unsigned*)&sAl[r8 + 8];
            }
            #pragma unroll
            for (int ni = 0; ni < 8; ni++) {
                int nb = (warpN*64 + ni*8 + g) * 40 + kb + 2*tg;
                unsigned bh0 = *(const unsigned*)&sBh[nb];
                unsigned bh1 = *(const unsigned*)&sBh[nb + 8];
                unsigned bl0 = *(const unsigned*)&sBl[nb];
                unsigned bl1 = *(const unsigned*)&sBl[nb + 8];
                #pragma unroll
                for (int mi = 0; mi < 2; mi++) {
                    MMA16816(acc[mi][ni], ah[mi], bh0, bh1);
                    MMA16816(acc[mi][ni], al[mi], bh0, bh1);
                    MMA16816(acc[mi][ni], ah[mi], bl0, bl1);
                }
            }
        }
        __syncthreads();
    }
    #undef GL

    #pragma unroll
    for (int mi = 0; mi < 2; mi++) {
        int r0 = m0 + warpM*32 + mi*16 + g;
        #pragma unroll
        for (int ni = 0; ni < 8; ni++) {
            int c = n0 + warpN*64 + ni*8 + tg*2;
            *(float2*)&C[(size_t)r0 * N + c] =
                make_float2(acc[mi][ni][0], acc[mi][ni][1]);
            *(float2*)&C[(size_t)(r0+8) * N + c] =
                make_float2(acc[mi][ni][2], acc[mi][ni][3]);
        }
    }
}

__global__ __launch_bounds__(256)
void qkv_gemm_kernel() {
    gemm_hl_body<NTOK, E3, DMODEL>(g_xh, g_xl, g_wqh, g_wql, g_qkv);
}
__global__ __launch_bounds__(256)
void out_gemm_kernel(float* __restrict__ out) {
    gemm_hl_body<NTOK, DMODEL, DMODEL>(g_ah, g_al, g_woh, g_wol, out);
}

// ---------------------------------------------------------------------------
// RoPE applied in-place to Q and K halves of g_qkv (unchanged, known-good).
// ---------------------------------------------------------------------------
__global__ void rope_kernel(const int* __restrict__ pos)
{
    int t = blockIdx.x * blockDim.x + threadIdx.x;
    const int total = NTOK * NHEADS * (DK / 2);
    if (t >= total) return;

    int i = t & 31;
    int h = (t >> 5) & (NHEADS - 1);
    int n = t >> 9;
    int s = n & (SEQ - 1);

    float p = (float)pos[s];
    float inv = expf(-((float)i / 32.0f) * 9.2103403719761836f);
    float ang = p * inv;
    float sn, cs;
    sincosf(ang, &sn, &cs);

    float* q = &g_qkv[(size_t)n * E3 + h * DK + 2 * i];
    float q1 = q[0], q2 = q[1];
    q[0] = q1 * cs - q2 * sn;
    q[1] = q1 * sn + q2 * cs;

    float* k = q + DMODEL;
    float k1 = k[0], k2 = k[1];
    k[0] = k1 * cs - k2 * sn;
    k[1] = k1 * sn + k2 * cs;
}

// ---------------------------------------------------------------------------
// Causal flash attention, fp32 (unchanged, known-good).
// ---------------------------------------------------------------------------
__global__ __launch_bounds__(64)
void attn_kernel()
{
    const int qt = blockIdx.x;
    const int h  = blockIdx.y;
    const int b  = blockIdx.z;
    const int r  = threadIdx.x;
    const int qrow = qt * 64 + r;

    __shared__ float Ks[64][64];
    __shared__ float Vs[64][64];
    __shared__ float Ss[64][64];

    const float scale = 0.125f;

    float4 q[16];
    const float* qptr = &g_qkv[((size_t)(b * SEQ) + qrow) * E3 + h * DK];
#pragma unroll
    for (int i = 0; i < 16; i++) {
        float4 v = *(const float4*)&qptr[4 * i];
        v.x *= scale; v.y *= scale; v.z *= scale; v.w *= scale;
        q[i] = v;
    }

    float4 o[16];
#pragma unroll
    for (int i = 0; i < 16; i++) o[i] = make_float4(0.f, 0.f, 0.f, 0.f);
    float m = -1e30f, l = 0.f;

    for (int kt = 0; kt <= qt; kt++) {
        __syncthreads();
        const float* kbase = &g_qkv[((size_t)(b * SEQ) + kt * 64) * E3 + DMODEL + h * DK];
        const float* vbase = kbase + DMODEL;
#pragma unroll
        for (int i = 0; i < 16; i++) {
            int idx = r + i * 64;
            int row = idx >> 4;
            int c4  = (idx & 15) << 2;
            *(float4*)&Ks[row][c4] = *(const float4*)&kbase[(size_t)row * E3 + c4];
            *(float4*)&Vs[row][c4] = *(const float4*)&vbase[(size_t)row * E3 + c4];
        }
        __syncthreads();

        float tmax = -1e30f;
        const bool diag = (kt == qt);
#pragma unroll 4
        for (int c = 0; c < 64; c++) {
            float ax = 0.f, ay = 0.f, az = 0.f, aw = 0.f;
#pragma unroll
            for (int i = 0; i < 16; i++) {
                float4 kv = *(const float4*)&Ks[c][4 * i];
                ax += q[i].x * kv.x; ay += q[i].y * kv.y;
                az += q[i].z * kv.z; aw += q[i].w * kv.w;
            }
            float s = (ax + ay) + (az + aw);
            if (diag && c > r) s = -1e30f;
            tmax = fmaxf(tmax, s);
            Ss[c][r] = s;
        }

        float mnew = fmaxf(m, tmax);
        float corr = __expf(m - mnew);
        m = mnew;
        l *= corr;
#pragma unroll
        for (int i = 0; i < 16; i++) {
            o[i].x *= corr; o[i].y *= corr; o[i].z *= corr; o[i].w *= corr;
        }

#pragma unroll 2
        for (int c = 0; c < 64; c++) {
            float p = __expf(Ss[c][r] - m);
            l += p;
#pragma unroll
            for (int i = 0; i < 16; i++) {
                float4 v = *(const float4*)&Vs[c][4 * i];
                o[i].x += p * v.x; o[i].y += p * v.y;
                o[i].z += p * v.z; o[i].w += p * v.w;
            }
        }
    }

    float inv = 1.f / l;
    float* op = &g_attn[((size_t)(b * SEQ) + qrow) * DMODEL + h * DK];
#pragma unroll
    for (int i = 0; i < 16; i++) {
        float4 v = o[i];
        v.x *= inv; v.y *= inv; v.z *= inv; v.w *= inv;
        *(float4*)&op[4 * i] = v;
    }
}

// ---------------------------------------------------------------------------
extern "C" void kernel_launch(void* const* d_in, const int* in_sizes, int n_in,
                              void* d_out, int out_size)
{
    const float* x      = (const float*)d_in[0];
    const int*   pos    = (const int*)d_in[1];
    const float* w_qkv  = (const float*)d_in[2];
    const float* w_o    = (const float*)d_in[3];
    float*       out    = (float*)d_out;

    // 0) hi/lo fp16 splits of inputs
    cvt_x_kernel <<<(NTOK*DMODEL/4 + 255)/256, 256>>>(x);
    cvt_wq_kernel<<<(E3*DMODEL/4   + 255)/256, 256>>>(w_qkv);
    cvt_wo_kernel<<<(DMODEL*DMODEL/4 + 255)/256, 256>>>(w_o);

    // 1) QKV projection (fp16 hi/lo tensor cores)
    {
        dim3 grid(E3 / 128, NTOK / 128);
        qkv_gemm_kernel<<<grid, 256>>>();
    }
    // 2) RoPE
    {
        int total = NTOK * NHEADS * (DK / 2);
        rope_kernel<<<(total + 255) / 256, 256>>>(pos);
    }
    // 3) Causal flash attention (fp32)
    {
        dim3 grid(SEQ / 64, NHEADS, BATCH);
        attn_kernel<<<grid, 64>>>();
    }
    // 4) Output projection (fp16 hi/lo tensor cores)
    cvt_attn_kernel<<<(NTOK*DMODEL/4 + 255)/256, 256>>>();
    {
        dim3 grid(DMODEL / 128, NTOK / 128);
        out_gemm_kernel<<<grid, 256>>>(out);
    }
}

// round 5
// speedup vs baseline: 2.4440x; 1.6959x over previous
#include <cuda_runtime.h>
#include <cuda_fp16.h>
#include <math.h>

#define BATCH   2
#define SEQ     2048
#define DMODEL  1024
#define NHEADS  16
#define DK      64
#define NTOK    (BATCH*SEQ)      /* 4096 */
#define E3      (3*DMODEL)       /* 3072 */

// Scratch (allocation-free rule: __device__ globals)
__device__ float  g_qkv[(size_t)NTOK * E3];
__device__ float  g_attn[(size_t)NTOK * DMODEL];
// hi/lo fp16 split operands
__device__ __half g_xh[(size_t)NTOK * DMODEL],  g_xl[(size_t)NTOK * DMODEL];
__device__ __half g_wqh[(size_t)E3 * DMODEL],   g_wql[(size_t)E3 * DMODEL];
__device__ __half g_woh[(size_t)DMODEL*DMODEL], g_wol[(size_t)DMODEL*DMODEL];
__device__ __half g_ah[(size_t)NTOK * DMODEL],  g_al[(size_t)NTOK * DMODEL];

// ---------------------------------------------------------------------------
// fp16 hi/lo helpers
// ---------------------------------------------------------------------------
__device__ __forceinline__ void split_store(float4 v, __half* dh, __half* dl)
{
    __half2 h01 = __floats2half2_rn(v.x, v.y);
    __half2 h23 = __floats2half2_rn(v.z, v.w);
    float2 f01 = __half22float2(h01);
    float2 f23 = __half22float2(h23);
    __half2 l01 = __floats2half2_rn(v.x - f01.x, v.y - f01.y);
    __half2 l23 = __floats2half2_rn(v.z - f23.x, v.w - f23.y);
    *(__half2*)&dh[0] = h01;  *(__half2*)&dh[2] = h23;
    *(__half2*)&dl[0] = l01;  *(__half2*)&dl[2] = l23;
}

__device__ __forceinline__ unsigned split_pack(float a, float b, unsigned& lo)
{
    __half2 h = __floats2half2_rn(a, b);
    float2 f = __half22float2(h);
    __half2 l = __floats2half2_rn(a - f.x, b - f.y);
    lo = *reinterpret_cast<unsigned*>(&l);
    return *reinterpret_cast<unsigned*>(&h);
}

__device__ __forceinline__ unsigned pack_h(float a, float b)
{
    __half2 h = __floats2half2_rn(a, b);
    return *reinterpret_cast<unsigned*>(&h);
}

__global__ void cvt_x_kernel(const float* __restrict__ x) {
    int i = blockIdx.x * blockDim.x + threadIdx.x;
    if (i >= NTOK * DMODEL / 4) return;
    split_store(((const float4*)x)[i], g_xh + (size_t)i*4, g_xl + (size_t)i*4);
}
__global__ void cvt_wq_kernel(const float* __restrict__ w) {
    int i = blockIdx.x * blockDim.x + threadIdx.x;
    if (i >= E3 * DMODEL / 4) return;
    split_store(((const float4*)w)[i], g_wqh + (size_t)i*4, g_wql + (size_t)i*4);
}
__global__ void cvt_wo_kernel(const float* __restrict__ w) {
    int i = blockIdx.x * blockDim.x + threadIdx.x;
    if (i >= DMODEL * DMODEL / 4) return;
    split_store(((const float4*)w)[i], g_woh + (size_t)i*4, g_wol + (size_t)i*4);
}
__global__ void cvt_attn_kernel() {
    int i = blockIdx.x * blockDim.x + threadIdx.x;
    if (i >= NTOK * DMODEL / 4) return;
    split_store(((const float4*)g_attn)[i], g_ah + (size_t)i*4, g_al + (size_t)i*4);
}

// ---------------------------------------------------------------------------
#define MMA16816(d, a, b0, b1)                                                 \
    asm volatile("mma.sync.aligned.m16n8k16.row.col.f32.f16.f16.f32 "          \
                 "{%0,%1,%2,%3}, {%4,%5,%6,%7}, {%8,%9}, {%0,%1,%2,%3};"       \
                 : "+f"(d[0]), "+f"(d[1]), "+f"(d[2]), "+f"(d[3])              \
                 : "r"(a[0]), "r"(a[1]), "r"(a[2]), "r"(a[3]), "r"(b0), "r"(b1))

// ---------------------------------------------------------------------------
// fp16 (hi/lo) tensor-core GEMM: C[M,N] = A[M,K] * B[N,K]^T, fp32 accumulate.
// (unchanged from R3 — known good)
// ---------------------------------------------------------------------------
template<int M, int N, int K>
__device__ __forceinline__ void gemm_hl_body(const __half* __restrict__ Ah,
                                             const __half* __restrict__ Al,
                                             const __half* __restrict__ Bh,
                                             const __half* __restrict__ Bl,
                                             float* __restrict__ C)
{
    __shared__ __half sAh[128*40], sAl[128*40], sBh[128*40], sBl[128*40];

    const int tid  = threadIdx.x;
    const int lane = tid & 31;
    const int wid  = tid >> 5;
    const int warpM = wid & 3;
    const int warpN = wid >> 2;
    const int m0 = blockIdx.y * 128;
    const int n0 = blockIdx.x * 128;
    const int g  = lane >> 2;
    const int tg = lane & 3;

    float acc[2][8][4] = {};
    uint4 pah[2], pal[2], pbh[2], pbl[2];

    #define GL(k0)                                                              \
        _Pragma("unroll")                                                       \
        for (int i = 0; i < 2; i++) {                                           \
            int idx = tid + i * 256;                                            \
            int r = idx >> 2, c = (idx & 3) << 3;                               \
            size_t ao = (size_t)(m0 + r) * K + (k0) + c;                        \
            size_t bo = (size_t)(n0 + r) * K + (k0) + c;                        \
            pah[i] = *(const uint4*)&Ah[ao];  pal[i] = *(const uint4*)&Al[ao];  \
            pbh[i] = *(const uint4*)&Bh[bo];  pbl[i] = *(const uint4*)&Bl[bo];  \
        }

    GL(0);

    const int nch = K / 32;
    for (int ch = 0; ch < nch; ch++) {
        #pragma unroll
        for (int i = 0; i < 2; i++) {
            int idx = tid + i * 256;
            int r = idx >> 2, c = (idx & 3) << 3;
            *(uint4*)&sAh[r*40 + c] = pah[i];
            *(uint4*)&sAl[r*40 + c] = pal[i];
            *(uint4*)&sBh[r*40 + c] = pbh[i];
            *(uint4*)&sBl[r*40 + c] = pbl[i];
        }
        __syncthreads();

        if (ch + 1 < nch) { GL((ch + 1) * 32); }

        #pragma unroll
        for (int ks = 0; ks < 2; ks++) {
            const int kb = ks * 16;
            unsigned ah[2][4], al[2][4];
            #pragma unroll
            for (int mi = 0; mi < 2; mi++) {
                int r0 = (warpM*32 + mi*16 + g) * 40 + kb + 2*tg;
                int r8 = r0 + 8*40;
                ah[mi][0] = *(const unsigned*)&sAh[r0];
                ah[mi][1] = *(const unsigned*)&sAh[r8];
                ah[mi][2] = *(const unsigned*)&sAh[r0 + 8];
                ah[mi][3] = *(const unsigned*)&sAh[r8 + 8];
                al[mi][0] = *(const unsigned*)&sAl[r0];
                al[mi][1] = *(const unsigned*)&sAl[r8];
                al[mi][2] = *(const unsigned*)&sAl[r0 + 8];
                al[mi][3] = *(const unsigned*)&sAl[r8 + 8];
            }
            #pragma unroll
            for (int ni = 0; ni < 8; ni++) {
                int nb = (warpN*64 + ni*8 + g) * 40 + kb + 2*tg;
                unsigned bh0 = *(const unsigned*)&sBh[nb];
                unsigned bh1 = *(const unsigned*)&sBh[nb + 8];
                unsigned bl0 = *(const unsigned*)&sBl[nb];
                unsigned bl1 = *(const unsigned*)&sBl[nb + 8];
                #pragma unroll
                for (int mi = 0; mi < 2; mi++) {
                    MMA16816(acc[mi][ni], ah[mi], bh0, bh1);
                    MMA16816(acc[mi][ni], al[mi], bh0, bh1);
                    MMA16816(acc[mi][ni], ah[mi], bl0, bl1);
                }
            }
        }
        __syncthreads();
    }
    #undef GL

    #pragma unroll
    for (int mi = 0; mi < 2; mi++) {
        int r0 = m0 + warpM*32 + mi*16 + g;
        #pragma unroll
        for (int ni = 0; ni < 8; ni++) {
            int c = n0 + warpN*64 + ni*8 + tg*2;
            *(float2*)&C[(size_t)r0 * N + c] =
                make_float2(acc[mi][ni][0], acc[mi][ni][1]);
            *(float2*)&C[(size_t)(r0+8) * N + c] =
                make_float2(acc[mi][ni][2], acc[mi][ni][3]);
        }
    }
}

__global__ __launch_bounds__(256)
void qkv_gemm_kernel() {
    gemm_hl_body<NTOK, E3, DMODEL>(g_xh, g_xl, g_wqh, g_wql, g_qkv);
}
__global__ __launch_bounds__(256)
void out_gemm_kernel(float* __restrict__ out) {
    gemm_hl_body<NTOK, DMODEL, DMODEL>(g_ah, g_al, g_woh, g_wol, out);
}

// ---------------------------------------------------------------------------
// RoPE applied in-place to Q and K halves of g_qkv (unchanged, known-good).
// ---------------------------------------------------------------------------
__global__ void rope_kernel(const int* __restrict__ pos)
{
    int t = blockIdx.x * blockDim.x + threadIdx.x;
    const int total = NTOK * NHEADS * (DK / 2);
    if (t >= total) return;

    int i = t & 31;
    int h = (t >> 5) & (NHEADS - 1);
    int n = t >> 9;
    int s = n & (SEQ - 1);

    float p = (float)pos[s];
    float inv = expf(-((float)i / 32.0f) * 9.2103403719761836f);
    float ang = p * inv;
    float sn, cs;
    sincosf(ang, &sn, &cs);

    float* q = &g_qkv[(size_t)n * E3 + h * DK + 2 * i];
    float q1 = q[0], q2 = q[1];
    q[0] = q1 * cs - q2 * sn;
    q[1] = q1 * sn + q2 * cs;

    float* k = q + DMODEL;
    float k1 = k[0], k2 = k[1];
    k[0] = k1 * cs - k2 * sn;
    k[1] = k1 * sn + k2 * cs;
}

// ---------------------------------------------------------------------------
// Causal flash attention, fp16 hi/lo tensor cores (FA2-style).
// Block: 128 q rows of one (b,h); 8 warps, each owns m16 of the q tile.
// KV streamed in 64-row tiles: K as [kv][d] (stride 72 halves), V transposed
// as [d][kv] (stride 72). B-fragment LDS word index = 4g+tg mod 32 -> no
// bank conflicts. QK^T: 3-pass hi/lo (accurate scores). PV: Ph*Vh + Ph*Vl.
// ---------------------------------------------------------------------------
__global__ __launch_bounds__(256)
void attn_mma_kernel()
{
    const int qt  = blockIdx.x;          // q tile (128 rows)
    const int h   = blockIdx.y;
    const int b   = blockIdx.z;
    const int tid = threadIdx.x;
    const int lane = tid & 31;
    const int w   = tid >> 5;            // warp 0..7
    const int g   = lane >> 2;           // 0..7
    const int tg  = lane & 3;            // 0..3

    __shared__ __half sKh[64*72], sKl[64*72], sVh[64*72], sVl[64*72];

    const int qbase = qt * 128;
    const int row0 = qbase + w*16 + g;
    const int row1 = row0 + 8;
    const int wrowmax = qbase + w*16 + 15;
    const float scale = 0.125f;          // 1/sqrt(64)

    // Q fragments hi/lo (A-frags for 4 k16 steps), scale folded in.
    unsigned qh[4][4], ql[4][4];
    {
        const float* q0 = &g_qkv[((size_t)(b*SEQ) + row0)*E3 + h*DK];
        const float* q1 = &g_qkv[((size_t)(b*SEQ) + row1)*E3 + h*DK];
        #pragma unroll
        for (int kk = 0; kk < 4; kk++) {
            int d0 = kk*16 + 2*tg;
            float2 a0 = *(const float2*)&q0[d0];
            float2 a1 = *(const float2*)&q1[d0];
            float2 a2 = *(const float2*)&q0[d0+8];
            float2 a3 = *(const float2*)&q1[d0+8];
            qh[kk][0] = split_pack(a0.x*scale, a0.y*scale, ql[kk][0]);
            qh[kk][1] = split_pack(a1.x*scale, a1.y*scale, ql[kk][1]);
            qh[kk][2] = split_pack(a2.x*scale, a2.y*scale, ql[kk][2]);
            qh[kk][3] = split_pack(a3.x*scale, a3.y*scale, ql[kk][3]);
        }
    }

    float o[8][4] = {};
    float m0 = -1e30f, m1 = -1e30f, l0 = 0.f, l1 = 0.f;

    const int ntiles = 2*qt + 2;
    float4 pk[4], pv[4];

    #define GLT(kt_)                                                           \
        _Pragma("unroll")                                                      \
        for (int i = 0; i < 4; i++) {                                          \
            int idx = tid + i*256;                                             \
            int r = idx >> 4, c4 = (idx & 15) << 2;                            \
            size_t base = ((size_t)(b*SEQ) + (kt_)*64 + r)*E3 + h*DK + c4;     \
            pk[i] = *(const float4*)&g_qkv[base + DMODEL];                     \
            pv[i] = *(const float4*)&g_qkv[base + 2*DMODEL];                   \
        }

    GLT(0);

    for (int kt = 0; kt < ntiles; kt++) {
        const int kvbase = kt * 64;

        // stage prefetched tile into smem (hi/lo split; V transposed)
        #pragma unroll
        for (int i = 0; i < 4; i++) {
            int idx = tid + i*256;
            int r = idx >> 4, c4 = (idx & 15) << 2;
            unsigned lo;
            unsigned hi01 = split_pack(pk[i].x, pk[i].y, lo);
            *(unsigned*)&sKh[r*72 + c4]     = hi01;
            *(unsigned*)&sKl[r*72 + c4]     = lo;
            unsigned hi23 = split_pack(pk[i].z, pk[i].w, lo);
            *(unsigned*)&sKh[r*72 + c4 + 2] = hi23;
            *(unsigned*)&sKl[r*72 + c4 + 2] = lo;
            float vf[4] = {pv[i].x, pv[i].y, pv[i].z, pv[i].w};
            #pragma unroll
            for (int j = 0; j < 4; j++) {
                __half vh = __float2half_rn(vf[j]);
                __half vl = __float2half_rn(vf[j] - __half2float(vh));
                sVh[(c4+j)*72 + r] = vh;
                sVl[(c4+j)*72 + r] = vl;
            }
        }
        __syncthreads();

        if (kt + 1 < ntiles) { GLT(kt + 1); }

        if (kvbase <= wrowmax) {          // warp has unmasked rows in tile
            float sc[8][4] = {};

            // QK^T: 3-pass hi/lo
            #pragma unroll
            for (int kk = 0; kk < 4; kk++) {
                int ko = kk*16 + 2*tg;
                #pragma unroll
                for (int ni = 0; ni < 8; ni++) {
                    int rb = (ni*8 + g)*72 + ko;
                    unsigned b0h = *(const unsigned*)&sKh[rb];
                    unsigned b1h = *(const unsigned*)&sKh[rb + 8];
                    unsigned b0l = *(const unsigned*)&sKl[rb];
                    unsigned b1l = *(const unsigned*)&sKl[rb + 8];
                    MMA16816(sc[ni], qh[kk], b0h, b1h);
                    MMA16816(sc[ni], ql[kk], b0h, b1h);
                    MMA16816(sc[ni], qh[kk], b0l, b1l);
                }
            }

            // causal mask
            if (kvbase + 63 > row0) {
                #pragma unroll
                for (int ni = 0; ni < 8; ni++) {
                    int c = kvbase + ni*8 + 2*tg;
                    if (c     > row0) sc[ni][0] = -1e30f;
                    if (c + 1 > row0) sc[ni][1] = -1e30f;
                    if (c     > row1) sc[ni][2] = -1e30f;
                    if (c + 1 > row1) sc[ni][3] = -1e30f;
                }
            }

            // online softmax (row stats across the quad)
            float t0 = -1e30f, t1 = -1e30f;
            #pragma unroll
            for (int ni = 0; ni < 8; ni++) {
                t0 = fmaxf(t0, fmaxf(sc[ni][0], sc[ni][1]));
                t1 = fmaxf(t1, fmaxf(sc[ni][2], sc[ni][3]));
            }
            t0 = fmaxf(t0, __shfl_xor_sync(0xffffffffu, t0, 1));
            t0 = fmaxf(t0, __shfl_xor_sync(0xffffffffu, t0, 2));
            t1 = fmaxf(t1, __shfl_xor_sync(0xffffffffu, t1, 1));
            t1 = fmaxf(t1, __shfl_xor_sync(0xffffffffu, t1, 2));

            float m0n = fmaxf(m0, t0), m1n = fmaxf(m1, t1);
            float c0 = __expf(m0 - m0n), c1 = __expf(m1 - m1n);
            m0 = m0n; m1 = m1n;
            l0 *= c0;  l1 *= c1;
            #pragma unroll
            for (int ni = 0; ni < 8; ni++) {
                o[ni][0] *= c0; o[ni][1] *= c0;
                o[ni][2] *= c1; o[ni][3] *= c1;
            }

            #pragma unroll
            for (int ni = 0; ni < 8; ni++) {
                sc[ni][0] = __expf(sc[ni][0] - m0);
                sc[ni][1] = __expf(sc[ni][1] - m0);
                sc[ni][2] = __expf(sc[ni][2] - m1);
                sc[ni][3] = __expf(sc[ni][3] - m1);
                l0 += sc[ni][0] + sc[ni][1];
                l1 += sc[ni][2] + sc[ni][3];
            }

            // PV: P_h * (V_h + V_l)
            #pragma unroll
            for (int kk = 0; kk < 4; kk++) {
                unsigned ph[4];
                ph[0] = pack_h(sc[2*kk][0],   sc[2*kk][1]);
                ph[1] = pack_h(sc[2*kk][2],   sc[2*kk][3]);
                ph[2] = pack_h(sc[2*kk+1][0], sc[2*kk+1][1]);
                ph[3] = pack_h(sc[2*kk+1][2], sc[2*kk+1][3]);
                int ko = kk*16 + 2*tg;
                #pragma unroll
                for (int nd = 0; nd < 8; nd++) {
                    int rb = (nd*8 + g)*72 + ko;
                    unsigned b0h = *(const unsigned*)&sVh[rb];
                    unsigned b1h = *(const unsigned*)&sVh[rb + 8];
                    unsigned b0l = *(const unsigned*)&sVl[rb];
                    unsigned b1l = *(const unsigned*)&sVl[rb + 8];
                    MMA16816(o[nd], ph, b0h, b1h);
                    MMA16816(o[nd], ph, b0l, b1l);
                }
            }
        }
        __syncthreads();
    }
    #undef GLT

    // finalize
    l0 += __shfl_xor_sync(0xffffffffu, l0, 1);
    l0 += __shfl_xor_sync(0xffffffffu, l0, 2);
    l1 += __shfl_xor_sync(0xffffffffu, l1, 1);
    l1 += __shfl_xor_sync(0xffffffffu, l1, 2);
    float inv0 = 1.f / l0, inv1 = 1.f / l1;

    float* op0 = &g_attn[((size_t)(b*SEQ) + row0)*DMODEL + h*DK];
    float* op1 = &g_attn[((size_t)(b*SEQ) + row1)*DMODEL + h*DK];
    #pragma unroll
    for (int nd = 0; nd < 8; nd++) {
        int c = nd*8 + 2*tg;
        *(float2*)&op0[c] = make_float2(o[nd][0]*inv0, o[nd][1]*inv0);
        *(float2*)&op1[c] = make_float2(o[nd][2]*inv1, o[nd][3]*inv1);
    }
}

// ---------------------------------------------------------------------------
extern "C" void kernel_launch(void* const* d_in, const int* in_sizes, int n_in,
                              void* d_out, int out_size)
{
    const float* x      = (const float*)d_in[0];
    const int*   pos    = (const int*)d_in[1];
    const float* w_qkv  = (const float*)d_in[2];
    const float* w_o    = (const float*)d_in[3];
    float*       out    = (float*)d_out;

    // 0) hi/lo fp16 splits of inputs
    cvt_x_kernel <<<(NTOK*DMODEL/4 + 255)/256, 256>>>(x);
    cvt_wq_kernel<<<(E3*DMODEL/4   + 255)/256, 256>>>(w_qkv);
    cvt_wo_kernel<<<(DMODEL*DMODEL/4 + 255)/256, 256>>>(w_o);

    // 1) QKV projection (fp16 hi/lo tensor cores)
    {
        dim3 grid(E3 / 128, NTOK / 128);
        qkv_gemm_kernel<<<grid, 256>>>();
    }
    // 2) RoPE
    {
        int total = NTOK * NHEADS * (DK / 2);
        rope_kernel<<<(total + 255) / 256, 256>>>(pos);
    }
    // 3) Causal flash attention (fp16 hi/lo tensor cores)
    {
        dim3 grid(SEQ / 128, NHEADS, BATCH);
        attn_mma_kernel<<<grid, 256>>>();
    }
    // 4) Output projection (fp16 hi/lo tensor cores)
    cvt_attn_kernel<<<(NTOK*DMODEL/4 + 255)/256, 256>>>();
    {
        dim3 grid(DMODEL / 128, NTOK / 128);
        out_gemm_kernel<<<grid, 256>>>(out);
    }
}

// round 6
// speedup vs baseline: 2.8174x; 1.1528x over previous
#include <cuda_runtime.h>
#include <cuda_fp16.h>
#include <math.h>

#define BATCH   2
#define SEQ     2048
#define DMODEL  1024
#define NHEADS  16
#define DK      64
#define NTOK    (BATCH*SEQ)      /* 4096 */
#define E3      (3*DMODEL)       /* 3072 */

// Scratch (allocation-free rule: __device__ globals)
__device__ float  g_qkv[(size_t)NTOK * E3];
__device__ float  g_attn[(size_t)NTOK * DMODEL];
// hi/lo fp16 split operands (B-side lo no longer needed: 2-pass GEMM)
__device__ __half g_xh[(size_t)NTOK * DMODEL],  g_xl[(size_t)NTOK * DMODEL];
__device__ __half g_wqh[(size_t)E3 * DMODEL];
__device__ __half g_woh[(size_t)DMODEL*DMODEL];
__device__ __half g_ah[(size_t)NTOK * DMODEL],  g_al[(size_t)NTOK * DMODEL];

// ---------------------------------------------------------------------------
// fp16 hi/lo helpers
// ---------------------------------------------------------------------------
__device__ __forceinline__ void split_store(float4 v, __half* dh, __half* dl)
{
    __half2 h01 = __floats2half2_rn(v.x, v.y);
    __half2 h23 = __floats2half2_rn(v.z, v.w);
    float2 f01 = __half22float2(h01);
    float2 f23 = __half22float2(h23);
    __half2 l01 = __floats2half2_rn(v.x - f01.x, v.y - f01.y);
    __half2 l23 = __floats2half2_rn(v.z - f23.x, v.w - f23.y);
    *(__half2*)&dh[0] = h01;  *(__half2*)&dh[2] = h23;
    *(__half2*)&dl[0] = l01;  *(__half2*)&dl[2] = l23;
}

__device__ __forceinline__ unsigned split_pack(float a, float b, unsigned& lo)
{
    __half2 h = __floats2half2_rn(a, b);
    float2 f = __half22float2(h);
    __half2 l = __floats2half2_rn(a - f.x, b - f.y);
    lo = *reinterpret_cast<unsigned*>(&l);
    return *reinterpret_cast<unsigned*>(&h);
}

__device__ __forceinline__ unsigned pack_h(float a, float b)
{
    __half2 h = __floats2half2_rn(a, b);
    return *reinterpret_cast<unsigned*>(&h);
}

__global__ void cvt_x_kernel(const float* __restrict__ x) {
    int i = blockIdx.x * blockDim.x + threadIdx.x;
    if (i >= NTOK * DMODEL / 4) return;
    split_store(((const float4*)x)[i], g_xh + (size_t)i*4, g_xl + (size_t)i*4);
}
__global__ void cvt_wq_kernel(const float* __restrict__ w) {
    int i = blockIdx.x * blockDim.x + threadIdx.x;
    if (i >= E3 * DMODEL / 4) return;
    float4 v = ((const float4*)w)[i];
    __half2 h01 = __floats2half2_rn(v.x, v.y);
    __half2 h23 = __floats2half2_rn(v.z, v.w);
    *(__half2*)&g_wqh[(size_t)i*4]     = h01;
    *(__half2*)&g_wqh[(size_t)i*4 + 2] = h23;
}
__global__ void cvt_wo_kernel(const float* __restrict__ w) {
    int i = blockIdx.x * blockDim.x + threadIdx.x;
    if (i >= DMODEL * DMODEL / 4) return;
    float4 v = ((const float4*)w)[i];
    __half2 h01 = __floats2half2_rn(v.x, v.y);
    __half2 h23 = __floats2half2_rn(v.z, v.w);
    *(__half2*)&g_woh[(size_t)i*4]     = h01;
    *(__half2*)&g_woh[(size_t)i*4 + 2] = h23;
}
__global__ void cvt_attn_kernel() {
    int i = blockIdx.x * blockDim.x + threadIdx.x;
    if (i >= NTOK * DMODEL / 4) return;
    split_store(((const float4*)g_attn)[i], g_ah + (size_t)i*4, g_al + (size_t)i*4);
}

// ---------------------------------------------------------------------------
#define MMA16816(d, a, b0, b1)                                                 \
    asm volatile("mma.sync.aligned.m16n8k16.row.col.f32.f16.f16.f32 "          \
                 "{%0,%1,%2,%3}, {%4,%5,%6,%7}, {%8,%9}, {%0,%1,%2,%3};"       \
                 : "+f"(d[0]), "+f"(d[1]), "+f"(d[2]), "+f"(d[3])              \
                 : "r"(a[0]), "r"(a[1]), "r"(a[2]), "r"(a[3]), "r"(b0), "r"(b1))

// ---------------------------------------------------------------------------
// fp16 (hi/lo A, hi B) tensor-core GEMM: C = A * B^T, fp32 accumulate.
// 2-pass: C ~= (Ah + Al) * Bh.  Double-buffered smem (dynamic, 60KB),
// one __syncthreads per BK=32 chunk: LDG prefetch -> mma(buf) -> STS(buf^1).
// ---------------------------------------------------------------------------
#define ARR_HALVES (128*40)
#define BUF_HALVES (3*ARR_HALVES)
#define GEMM_SMEM  (2*BUF_HALVES*2)   /* bytes = 61440 */

template<int M, int N, int K>
__device__ __forceinline__ void gemm_hl_body(const __half* __restrict__ Ah,
                                             const __half* __restrict__ Al,
                                             const __half* __restrict__ Bh,
                                             float* __restrict__ C)
{
    extern __shared__ __half dynsmem[];

    const int tid  = threadIdx.x;
    const int lane = tid & 31;
    const int wid  = tid >> 5;
    const int warpM = wid & 3;
    const int warpN = wid >> 2;
    const int m0 = blockIdx.y * 128;
    const int n0 = blockIdx.x * 128;
    const int g  = lane >> 2;
    const int tg = lane & 3;

    float acc[2][8][4] = {};
    uint4 pah[2], pal[2], pbh[2];

    // per-thread store coordinates (same every chunk)
    const int r_st[2] = { (tid)       >> 2, (tid + 256) >> 2 };
    const int c_st[2] = { (tid & 3) << 3,   (tid & 3) << 3 };

    #define GL(k0)                                                              \
        _Pragma("unroll")                                                       \
        for (int i = 0; i < 2; i++) {                                           \
            size_t ao = (size_t)(m0 + r_st[i]) * K + (k0) + c_st[i];            \
            size_t bo = (size_t)(n0 + r_st[i]) * K + (k0) + c_st[i];            \
            pah[i] = *(const uint4*)&Ah[ao];                                    \
            pal[i] = *(const uint4*)&Al[ao];                                    \
            pbh[i] = *(const uint4*)&Bh[bo];                                    \
        }

    #define STS_BUF(buf_)                                                       \
        _Pragma("unroll")                                                       \
        for (int i = 0; i < 2; i++) {                                           \
            __half* base = dynsmem + (buf_) * BUF_HALVES;                       \
            int off = r_st[i]*40 + c_st[i];                                     \
            *(uint4*)&base[off]                = pah[i];                        \
            *(uint4*)&base[ARR_HALVES + off]   = pal[i];                        \
            *(uint4*)&base[2*ARR_HALVES + off] = pbh[i];                        \
        }

    GL(0);
    STS_BUF(0);
    __syncthreads();

    const int nch = K / 32;
    for (int ch = 0; ch < nch; ch++) {
        const int buf = ch & 1;
        const __half* sAh_ = dynsmem + buf * BUF_HALVES;
        const __half* sAl_ = sAh_ + ARR_HALVES;
        const __half* sBh_ = sAh_ + 2*ARR_HALVES;

        if (ch + 1 < nch) { GL((ch + 1) * 32); }

        #pragma unroll
        for (int ks = 0; ks < 2; ks++) {
            const int kb = ks * 16;
            unsigned ah[2][4], al[2][4];
            #pragma unroll
            for (int mi = 0; mi < 2; mi++) {
                int r0 = (warpM*32 + mi*16 + g) * 40 + kb + 2*tg;
                int r8 = r0 + 8*40;
                ah[mi][0] = *(const unsigned*)&sAh_[r0];
                ah[mi][1] = *(const unsigned*)&sAh_[r8];
                ah[mi][2] = *(const unsigned*)&sAh_[r0 + 8];
                ah[mi][3] = *(const unsigned*)&sAh_[r8 + 8];
                al[mi][0] = *(const unsigned*)&sAl_[r0];
                al[mi][1] = *(const unsigned*)&sAl_[r8];
                al[mi][2] = *(const unsigned*)&sAl_[r0 + 8];
                al[mi][3] = *(const unsigned*)&sAl_[r8 + 8];
            }
            #pragma unroll
            for (int ni = 0; ni < 8; ni++) {
                int nb = (warpN*64 + ni*8 + g) * 40 + kb + 2*tg;
                unsigned b0 = *(const unsigned*)&sBh_[nb];
                unsigned b1 = *(const unsigned*)&sBh_[nb + 8];
                #pragma unroll
                for (int mi = 0; mi < 2; mi++) {
                    MMA16816(acc[mi][ni], ah[mi], b0, b1);
                    MMA16816(acc[mi][ni], al[mi], b0, b1);
                }
            }
        }

        if (ch + 1 < nch) { STS_BUF(buf ^ 1); }
        __syncthreads();
    }
    #undef GL
    #undef STS_BUF

    #pragma unroll
    for (int mi = 0; mi < 2; mi++) {
        int r0 = m0 + warpM*32 + mi*16 + g;
        #pragma unroll
        for (int ni = 0; ni < 8; ni++) {
            int c = n0 + warpN*64 + ni*8 + tg*2;
            *(float2*)&C[(size_t)r0 * N + c] =
                make_float2(acc[mi][ni][0], acc[mi][ni][1]);
            *(float2*)&C[(size_t)(r0+8) * N + c] =
                make_float2(acc[mi][ni][2], acc[mi][ni][3]);
        }
    }
}

__global__ __launch_bounds__(256)
void qkv_gemm_kernel() {
    gemm_hl_body<NTOK, E3, DMODEL>(g_xh, g_xl, g_wqh, g_qkv);
}
__global__ __launch_bounds__(256)
void out_gemm_kernel(float* __restrict__ out) {
    gemm_hl_body<NTOK, DMODEL, DMODEL>(g_ah, g_al, g_woh, out);
}

// ---------------------------------------------------------------------------
// RoPE applied in-place to Q and K halves of g_qkv (unchanged, known-good).
// ---------------------------------------------------------------------------
__global__ void rope_kernel(const int* __restrict__ pos)
{
    int t = blockIdx.x * blockDim.x + threadIdx.x;
    const int total = NTOK * NHEADS * (DK / 2);
    if (t >= total) return;

    int i = t & 31;
    int h = (t >> 5) & (NHEADS - 1);
    int n = t >> 9;
    int s = n & (SEQ - 1);

    float p = (float)pos[s];
    float inv = expf(-((float)i / 32.0f) * 9.2103403719761836f);
    float ang = p * inv;
    float sn, cs;
    sincosf(ang, &sn, &cs);

    float* q = &g_qkv[(size_t)n * E3 + h * DK + 2 * i];
    float q1 = q[0], q2 = q[1];
    q[0] = q1 * cs - q2 * sn;
    q[1] = q1 * sn + q2 * cs;

    float* k = q + DMODEL;
    float k1 = k[0], k2 = k[1];
    k[0] = k1 * cs - k2 * sn;
    k[1] = k1 * sn + k2 * cs;
}

// ---------------------------------------------------------------------------
// Causal flash attention, fp16 hi/lo tensor cores (unchanged from R4).
// ---------------------------------------------------------------------------
__global__ __launch_bounds__(256)
void attn_mma_kernel()
{
    const int qt  = blockIdx.x;
    const int h   = blockIdx.y;
    const int b   = blockIdx.z;
    const int tid = threadIdx.x;
    const int lane = tid & 31;
    const int w   = tid >> 5;
    const int g   = lane >> 2;
    const int tg  = lane & 3;

    __shared__ __half sKh[64*72], sKl[64*72], sVh[64*72], sVl[64*72];

    const int qbase = qt * 128;
    const int row0 = qbase + w*16 + g;
    const int row1 = row0 + 8;
    const int wrowmax = qbase + w*16 + 15;
    const float scale = 0.125f;

    unsigned qh[4][4], ql[4][4];
    {
        const float* q0 = &g_qkv[((size_t)(b*SEQ) + row0)*E3 + h*DK];
        const float* q1 = &g_qkv[((size_t)(b*SEQ) + row1)*E3 + h*DK];
        #pragma unroll
        for (int kk = 0; kk < 4; kk++) {
            int d0 = kk*16 + 2*tg;
            float2 a0 = *(const float2*)&q0[d0];
            float2 a1 = *(const float2*)&q1[d0];
            float2 a2 = *(const float2*)&q0[d0+8];
            float2 a3 = *(const float2*)&q1[d0+8];
            qh[kk][0] = split_pack(a0.x*scale, a0.y*scale, ql[kk][0]);
            qh[kk][1] = split_pack(a1.x*scale, a1.y*scale, ql[kk][1]);
            qh[kk][2] = split_pack(a2.x*scale, a2.y*scale, ql[kk][2]);
            qh[kk][3] = split_pack(a3.x*scale, a3.y*scale, ql[kk][3]);
        }
    }

    float o[8][4] = {};
    float m0 = -1e30f, m1 = -1e30f, l0 = 0.f, l1 = 0.f;

    const int ntiles = 2*qt + 2;
    float4 pk[4], pv[4];

    #define GLT(kt_)                                                           \
        _Pragma("unroll")                                                      \
        for (int i = 0; i < 4; i++) {                                          \
            int idx = tid + i*256;                                             \
            int r = idx >> 4, c4 = (idx & 15) << 2;                            \
            size_t base = ((size_t)(b*SEQ) + (kt_)*64 + r)*E3 + h*DK + c4;     \
            pk[i] = *(const float4*)&g_qkv[base + DMODEL];                     \
            pv[i] = *(const float4*)&g_qkv[base + 2*DMODEL];                   \
        }

    GLT(0);

    for (int kt = 0; kt < ntiles; kt++) {
        const int kvbase = kt * 64;

        #pragma unroll
        for (int i = 0; i < 4; i++) {
            int idx = tid + i*256;
            int r = idx >> 4, c4 = (idx & 15) << 2;
            unsigned lo;
            unsigned hi01 = split_pack(pk[i].x, pk[i].y, lo);
            *(unsigned*)&sKh[r*72 + c4]     = hi01;
            *(unsigned*)&sKl[r*72 + c4]     = lo;
            unsigned hi23 = split_pack(pk[i].z, pk[i].w, lo);
            *(unsigned*)&sKh[r*72 + c4 + 2] = hi23;
            *(unsigned*)&sKl[r*72 + c4 + 2] = lo;
            float vf[4] = {pv[i].x, pv[i].y, pv[i].z, pv[i].w};
            #pragma unroll
            for (int j = 0; j < 4; j++) {
                __half vh = __float2half_rn(vf[j]);
                __half vl = __float2half_rn(vf[j] - __half2float(vh));
                sVh[(c4+j)*72 + r] = vh;
                sVl[(c4+j)*72 + r] = vl;
            }
        }
        __syncthreads();

        if (kt + 1 < ntiles) { GLT(kt + 1); }

        if (kvbase <= wrowmax) {
            float sc[8][4] = {};

            #pragma unroll
            for (int kk = 0; kk < 4; kk++) {
                int ko = kk*16 + 2*tg;
                #pragma unroll
                for (int ni = 0; ni < 8; ni++) {
                    int rb = (ni*8 + g)*72 + ko;
                    unsigned b0h = *(const unsigned*)&sKh[rb];
                    unsigned b1h = *(const unsigned*)&sKh[rb + 8];
                    unsigned b0l = *(const unsigned*)&sKl[rb];
                    unsigned b1l = *(const unsigned*)&sKl[rb + 8];
                    MMA16816(sc[ni], qh[kk], b0h, b1h);
                    MMA16816(sc[ni], ql[kk], b0h, b1h);
                    MMA16816(sc[ni], qh[kk], b0l, b1l);
                }
            }

            if (kvbase + 63 > row0) {
                #pragma unroll
                for (int ni = 0; ni < 8; ni++) {
                    int c = kvbase + ni*8 + 2*tg;
                    if (c     > row0) sc[ni][0] = -1e30f;
                    if (c + 1 > row0) sc[ni][1] = -1e30f;
                    if (c     > row1) sc[ni][2] = -1e30f;
                    if (c + 1 > row1) sc[ni][3] = -1e30f;
                }
            }

            float t0 = -1e30f, t1 = -1e30f;
            #pragma unroll
            for (int ni = 0; ni < 8; ni++) {
                t0 = fmaxf(t0, fmaxf(sc[ni][0], sc[ni][1]));
                t1 = fmaxf(t1, fmaxf(sc[ni][2], sc[ni][3]));
            }
            t0 = fmaxf(t0, __shfl_xor_sync(0xffffffffu, t0, 1));
            t0 = fmaxf(t0, __shfl_xor_sync(0xffffffffu, t0, 2));
            t1 = fmaxf(t1, __shfl_xor_sync(0xffffffffu, t1, 1));
            t1 = fmaxf(t1, __shfl_xor_sync(0xffffffffu, t1, 2));

            float m0n = fmaxf(m0, t0), m1n = fmaxf(m1, t1);
            float c0 = __expf(m0 - m0n), c1 = __expf(m1 - m1n);
            m0 = m0n; m1 = m1n;
            l0 *= c0;  l1 *= c1;
            #pragma unroll
            for (int ni = 0; ni < 8; ni++) {
                o[ni][0] *= c0; o[ni][1] *= c0;
                o[ni][2] *= c1; o[ni][3] *= c1;
            }

            #pragma unroll
            for (int ni = 0; ni < 8; ni++) {
                sc[ni][0] = __expf(sc[ni][0] - m0);
                sc[ni][1] = __expf(sc[ni][1] - m0);
                sc[ni][2] = __expf(sc[ni][2] - m1);
                sc[ni][3] = __expf(sc[ni][3] - m1);
                l0 += sc[ni][0] + sc[ni][1];
                l1 += sc[ni][2] + sc[ni][3];
            }

            #pragma unroll
            for (int kk = 0; kk < 4; kk++) {
                unsigned ph[4];
                ph[0] = pack_h(sc[2*kk][0],   sc[2*kk][1]);
                ph[1] = pack_h(sc[2*kk][2],   sc[2*kk][3]);
                ph[2] = pack_h(sc[2*kk+1][0], sc[2*kk+1][1]);
                ph[3] = pack_h(sc[2*kk+1][2], sc[2*kk+1][3]);
                int ko = kk*16 + 2*tg;
                #pragma unroll
                for (int nd = 0; nd < 8; nd++) {
                    int rb = (nd*8 + g)*72 + ko;
                    unsigned b0h = *(const unsigned*)&sVh[rb];
                    unsigned b1h = *(const unsigned*)&sVh[rb + 8];
                    unsigned b0l = *(const unsigned*)&sVl[rb];
                    unsigned b1l = *(const unsigned*)&sVl[rb + 8];
                    MMA16816(o[nd], ph, b0h, b1h);
                    MMA16816(o[nd], ph, b0l, b1l);
                }
            }
        }
        __syncthreads();
    }
    #undef GLT

    l0 += __shfl_xor_sync(0xffffffffu, l0, 1);
    l0 += __shfl_xor_sync(0xffffffffu, l0, 2);
    l1 += __shfl_xor_sync(0xffffffffu, l1, 1);
    l1 += __shfl_xor_sync(0xffffffffu, l1, 2);
    float inv0 = 1.f / l0, inv1 = 1.f / l1;

    float* op0 = &g_attn[((size_t)(b*SEQ) + row0)*DMODEL + h*DK];
    float* op1 = &g_attn[((size_t)(b*SEQ) + row1)*DMODEL + h*DK];
    #pragma unroll
    for (int nd = 0; nd < 8; nd++) {
        int c = nd*8 + 2*tg;
        *(float2*)&op0[c] = make_float2(o[nd][0]*inv0, o[nd][1]*inv0);
        *(float2*)&op1[c] = make_float2(o[nd][2]*inv1, o[nd][3]*inv1);
    }
}

// ---------------------------------------------------------------------------
extern "C" void kernel_launch(void* const* d_in, const int* in_sizes, int n_in,
                              void* d_out, int out_size)
{
    const float* x      = (const float*)d_in[0];
    const int*   pos    = (const int*)d_in[1];
    const float* w_qkv  = (const float*)d_in[2];
    const float* w_o    = (const float*)d_in[3];
    float*       out    = (float*)d_out;

    // allow 60KB dynamic smem for the GEMMs (host attr set, not a stream op)
    cudaFuncSetAttribute(qkv_gemm_kernel,
                         cudaFuncAttributeMaxDynamicSharedMemorySize, GEMM_SMEM);
    cudaFuncSetAttribute(out_gemm_kernel,
                         cudaFuncAttributeMaxDynamicSharedMemorySize, GEMM_SMEM);

    // 0) fp16 splits (x hi/lo; weights hi only)
    cvt_x_kernel <<<(NTOK*DMODEL/4 + 255)/256, 256>>>(x);
    cvt_wq_kernel<<<(E3*DMODEL/4   + 255)/256, 256>>>(w_qkv);
    cvt_wo_kernel<<<(DMODEL*DMODEL/4 + 255)/256, 256>>>(w_o);

    // 1) QKV projection
    {
        dim3 grid(E3 / 128, NTOK / 128);
        qkv_gemm_kernel<<<grid, 256, GEMM_SMEM>>>();
    }
    // 2) RoPE
    {
        int total = NTOK * NHEADS * (DK / 2);
        rope_kernel<<<(total + 255) / 256, 256>>>(pos);
    }
    // 3) Causal flash attention
    {
        dim3 grid(SEQ / 128, NHEADS, BATCH);
        attn_mma_kernel<<<grid, 256>>>();
    }
    // 4) Output projection
    cvt_attn_kernel<<<(NTOK*DMODEL/4 + 255)/256, 256>>>();
    {
        dim3 grid(DMODEL / 128, NTOK / 128);
        out_gemm_kernel<<<grid, 256, GEMM_SMEM>>>(out);
    }
}

// round 7
// speedup vs baseline: 2.9955x; 1.0632x over previous
#include <cuda_runtime.h>
#include <cuda_fp16.h>
#include <math.h>

#define BATCH   2
#define SEQ     2048
#define DMODEL  1024
#define NHEADS  16
#define DK      64
#define NTOK    (BATCH*SEQ)      /* 4096 */
#define E3      (3*DMODEL)       /* 3072 */

// Scratch (allocation-free rule: __device__ globals)
__device__ float  g_qkv[(size_t)NTOK * E3];
// hi/lo fp16 split operands (B-side lo not needed: 2-pass GEMM)
__device__ __half g_xh[(size_t)NTOK * DMODEL],  g_xl[(size_t)NTOK * DMODEL];
__device__ __half g_wqh[(size_t)E3 * DMODEL];
__device__ __half g_woh[(size_t)DMODEL*DMODEL];
__device__ __half g_ah[(size_t)NTOK * DMODEL],  g_al[(size_t)NTOK * DMODEL];

// ---------------------------------------------------------------------------
// fp16 hi/lo helpers
// ---------------------------------------------------------------------------
__device__ __forceinline__ void split_store(float4 v, __half* dh, __half* dl)
{
    __half2 h01 = __floats2half2_rn(v.x, v.y);
    __half2 h23 = __floats2half2_rn(v.z, v.w);
    float2 f01 = __half22float2(h01);
    float2 f23 = __half22float2(h23);
    __half2 l01 = __floats2half2_rn(v.x - f01.x, v.y - f01.y);
    __half2 l23 = __floats2half2_rn(v.z - f23.x, v.w - f23.y);
    *(__half2*)&dh[0] = h01;  *(__half2*)&dh[2] = h23;
    *(__half2*)&dl[0] = l01;  *(__half2*)&dl[2] = l23;
}

__device__ __forceinline__ unsigned split_pack(float a, float b, unsigned& lo)
{
    __half2 h = __floats2half2_rn(a, b);
    float2 f = __half22float2(h);
    __half2 l = __floats2half2_rn(a - f.x, b - f.y);
    lo = *reinterpret_cast<unsigned*>(&l);
    return *reinterpret_cast<unsigned*>(&h);
}

__device__ __forceinline__ unsigned pack_h(float a, float b)
{
    __half2 h = __floats2half2_rn(a, b);
    return *reinterpret_cast<unsigned*>(&h);
}

__global__ void cvt_x_kernel(const float* __restrict__ x) {
    int i = blockIdx.x * blockDim.x + threadIdx.x;
    if (i >= NTOK * DMODEL / 4) return;
    split_store(((const float4*)x)[i], g_xh + (size_t)i*4, g_xl + (size_t)i*4);
}
__global__ void cvt_wq_kernel(const float* __restrict__ w) {
    int i = blockIdx.x * blockDim.x + threadIdx.x;
    if (i >= E3 * DMODEL / 4) return;
    float4 v = ((const float4*)w)[i];
    __half2 h01 = __floats2half2_rn(v.x, v.y);
    __half2 h23 = __floats2half2_rn(v.z, v.w);
    *(__half2*)&g_wqh[(size_t)i*4]     = h01;
    *(__half2*)&g_wqh[(size_t)i*4 + 2] = h23;
}
__global__ void cvt_wo_kernel(const float* __restrict__ w) {
    int i = blockIdx.x * blockDim.x + threadIdx.x;
    if (i >= DMODEL * DMODEL / 4) return;
    float4 v = ((const float4*)w)[i];
    __half2 h01 = __floats2half2_rn(v.x, v.y);
    __half2 h23 = __floats2half2_rn(v.z, v.w);
    *(__half2*)&g_woh[(size_t)i*4]     = h01;
    *(__half2*)&g_woh[(size_t)i*4 + 2] = h23;
}

// ---------------------------------------------------------------------------
#define MMA16816(d, a, b0, b1)                                                 \
    asm volatile("mma.sync.aligned.m16n8k16.row.col.f32.f16.f16.f32 "          \
                 "{%0,%1,%2,%3}, {%4,%5,%6,%7}, {%8,%9}, {%0,%1,%2,%3};"       \
                 : "+f"(d[0]), "+f"(d[1]), "+f"(d[2]), "+f"(d[3])              \
                 : "r"(a[0]), "r"(a[1]), "r"(a[2]), "r"(a[3]), "r"(b0), "r"(b1))

// ---------------------------------------------------------------------------
// fp16 (hi/lo A, hi B) tensor-core GEMM: C = A * B^T, fp32 accumulate.
// 2-pass: C ~= (Ah + Al) * Bh.  Double-buffered smem (dynamic, 60KB),
// one __syncthreads per BK=32 chunk. __launch_bounds__(256,2) caps regs at
// 128 -> 2 CTAs/SM (occupancy was the R5 limiter).
// ---------------------------------------------------------------------------
#define ARR_HALVES (128*40)
#define BUF_HALVES (3*ARR_HALVES)
#define GEMM_SMEM  (2*BUF_HALVES*2)   /* bytes = 61440 */

template<int M, int N, int K>
__device__ __forceinline__ void gemm_hl_body(const __half* __restrict__ Ah,
                                             const __half* __restrict__ Al,
                                             const __half* __restrict__ Bh,
                                             float* __restrict__ C)
{
    extern __shared__ __half dynsmem[];

    const int tid  = threadIdx.x;
    const int lane = tid & 31;
    const int wid  = tid >> 5;
    const int warpM = wid & 3;
    const int warpN = wid >> 2;
    const int m0 = blockIdx.y * 128;
    const int n0 = blockIdx.x * 128;
    const int g  = lane >> 2;
    const int tg = lane & 3;

    float acc[2][8][4] = {};
    uint4 pah[2], pal[2], pbh[2];

    const int r_st[2] = { (tid)       >> 2, (tid + 256) >> 2 };
    const int c_st[2] = { (tid & 3) << 3,   (tid & 3) << 3 };

    #define GL(k0)                                                              \
        _Pragma("unroll")                                                       \
        for (int i = 0; i < 2; i++) {                                           \
            size_t ao = (size_t)(m0 + r_st[i]) * K + (k0) + c_st[i];            \
            size_t bo = (size_t)(n0 + r_st[i]) * K + (k0) + c_st[i];            \
            pah[i] = *(const uint4*)&Ah[ao];                                    \
            pal[i] = *(const uint4*)&Al[ao];                                    \
            pbh[i] = *(const uint4*)&Bh[bo];                                    \
        }

    #define STS_BUF(buf_)                                                       \
        _Pragma("unroll")                                                       \
        for (int i = 0; i < 2; i++) {                                           \
            __half* base = dynsmem + (buf_) * BUF_HALVES;                       \
            int off = r_st[i]*40 + c_st[i];                                     \
            *(uint4*)&base[off]                = pah[i];                        \
            *(uint4*)&base[ARR_HALVES + off]   = pal[i];                        \
            *(uint4*)&base[2*ARR_HALVES + off] = pbh[i];                        \
        }

    GL(0);
    STS_BUF(0);
    __syncthreads();

    const int nch = K / 32;
    for (int ch = 0; ch < nch; ch++) {
        const int buf = ch & 1;
        const __half* sAh_ = dynsmem + buf * BUF_HALVES;
        const __half* sAl_ = sAh_ + ARR_HALVES;
        const __half* sBh_ = sAh_ + 2*ARR_HALVES;

        if (ch + 1 < nch) { GL((ch + 1) * 32); }

        #pragma unroll
        for (int ks = 0; ks < 2; ks++) {
            const int kb = ks * 16;
            unsigned ah[2][4], al[2][4];
            #pragma unroll
            for (int mi = 0; mi < 2; mi++) {
                int r0 = (warpM*32 + mi*16 + g) * 40 + kb + 2*tg;
                int r8 = r0 + 8*40;
                ah[mi][0] = *(const unsigned*)&sAh_[r0];
                ah[mi][1] = *(const unsigned*)&sAh_[r8];
                ah[mi][2] = *(const unsigned*)&sAh_[r0 + 8];
                ah[mi][3] = *(const unsigned*)&sAh_[r8 + 8];
                al[mi][0] = *(const unsigned*)&sAl_[r0];
                al[mi][1] = *(const unsigned*)&sAl_[r8];
                al[mi][2] = *(const unsigned*)&sAl_[r0 + 8];
                al[mi][3] = *(const unsigned*)&sAl_[r8 + 8];
            }
            #pragma unroll
            for (int ni = 0; ni < 8; ni++) {
                int nb = (warpN*64 + ni*8 + g) * 40 + kb + 2*tg;
                unsigned b0 = *(const unsigned*)&sBh_[nb];
                unsigned b1 = *(const unsigned*)&sBh_[nb + 8];
                #pragma unroll
                for (int mi = 0; mi < 2; mi++) {
                    MMA16816(acc[mi][ni], ah[mi], b0, b1);
                    MMA16816(acc[mi][ni], al[mi], b0, b1);
                }
            }
        }

        if (ch + 1 < nch) { STS_BUF(buf ^ 1); }
        __syncthreads();
    }
    #undef GL
    #undef STS_BUF

    #pragma unroll
    for (int mi = 0; mi < 2; mi++) {
        int r0 = m0 + warpM*32 + mi*16 + g;
        #pragma unroll
        for (int ni = 0; ni < 8; ni++) {
            int c = n0 + warpN*64 + ni*8 + tg*2;
            *(float2*)&C[(size_t)r0 * N + c] =
                make_float2(acc[mi][ni][0], acc[mi][ni][1]);
            *(float2*)&C[(size_t)(r0+8) * N + c] =
                make_float2(acc[mi][ni][2], acc[mi][ni][3]);
        }
    }
}

__global__ __launch_bounds__(256, 2)
void qkv_gemm_kernel() {
    gemm_hl_body<NTOK, E3, DMODEL>(g_xh, g_xl, g_wqh, g_qkv);
}
__global__ __launch_bounds__(256, 2)
void out_gemm_kernel(float* __restrict__ out) {
    gemm_hl_body<NTOK, DMODEL, DMODEL>(g_ah, g_al, g_woh, out);
}

// ---------------------------------------------------------------------------
// RoPE applied in-place to Q and K halves of g_qkv (unchanged, known-good).
// ---------------------------------------------------------------------------
__global__ void rope_kernel(const int* __restrict__ pos)
{
    int t = blockIdx.x * blockDim.x + threadIdx.x;
    const int total = NTOK * NHEADS * (DK / 2);
    if (t >= total) return;

    int i = t & 31;
    int h = (t >> 5) & (NHEADS - 1);
    int n = t >> 9;
    int s = n & (SEQ - 1);

    float p = (float)pos[s];
    float inv = expf(-((float)i / 32.0f) * 9.2103403719761836f);
    float ang = p * inv;
    float sn, cs;
    sincosf(ang, &sn, &cs);

    float* q = &g_qkv[(size_t)n * E3 + h * DK + 2 * i];
    float q1 = q[0], q2 = q[1];
    q[0] = q1 * cs - q2 * sn;
    q[1] = q1 * sn + q2 * cs;

    float* k = q + DMODEL;
    float k1 = k[0], k2 = k[1];
    k[0] = k1 * cs - k2 * sn;
    k[1] = k1 * sn + k2 * cs;
}

// ---------------------------------------------------------------------------
// Causal flash attention, fp16 hi/lo tensor cores.
// Epilogue now writes hi/lo fp16 split directly (g_ah/g_al) so the separate
// cvt_attn pass is gone. Mainloop unchanged from R4/R5 (known-good).
// ---------------------------------------------------------------------------
__global__ __launch_bounds__(256)
void attn_mma_kernel()
{
    const int qt  = blockIdx.x;
    const int h   = blockIdx.y;
    const int b   = blockIdx.z;
    const int tid = threadIdx.x;
    const int lane = tid & 31;
    const int w   = tid >> 5;
    const int g   = lane >> 2;
    const int tg  = lane & 3;

    __shared__ __half sKh[64*72], sKl[64*72], sVh[64*72], sVl[64*72];

    const int qbase = qt * 128;
    const int row0 = qbase + w*16 + g;
    const int row1 = row0 + 8;
    const int wrowmax = qbase + w*16 + 15;
    const float scale = 0.125f;

    unsigned qh[4][4], ql[4][4];
    {
        const float* q0 = &g_qkv[((size_t)(b*SEQ) + row0)*E3 + h*DK];
        const float* q1 = &g_qkv[((size_t)(b*SEQ) + row1)*E3 + h*DK];
        #pragma unroll
        for (int kk = 0; kk < 4; kk++) {
            int d0 = kk*16 + 2*tg;
            float2 a0 = *(const float2*)&q0[d0];
            float2 a1 = *(const float2*)&q1[d0];
            float2 a2 = *(const float2*)&q0[d0+8];
            float2 a3 = *(const float2*)&q1[d0+8];
            qh[kk][0] = split_pack(a0.x*scale, a0.y*scale, ql[kk][0]);
            qh[kk][1] = split_pack(a1.x*scale, a1.y*scale, ql[kk][1]);
            qh[kk][2] = split_pack(a2.x*scale, a2.y*scale, ql[kk][2]);
            qh[kk][3] = split_pack(a3.x*scale, a3.y*scale, ql[kk][3]);
        }
    }

    float o[8][4] = {};
    float m0 = -1e30f, m1 = -1e30f, l0 = 0.f, l1 = 0.f;

    const int ntiles = 2*qt + 2;
    float4 pk[4], pv[4];

    #define GLT(kt_)                                                           \
        _Pragma("unroll")                                                      \
        for (int i = 0; i < 4; i++) {                                          \
            int idx = tid + i*256;                                             \
            int r = idx >> 4, c4 = (idx & 15) << 2;                            \
            size_t base = ((size_t)(b*SEQ) + (kt_)*64 + r)*E3 + h*DK + c4;     \
            pk[i] = *(const float4*)&g_qkv[base + DMODEL];                     \
            pv[i] = *(const float4*)&g_qkv[base + 2*DMODEL];                   \
        }

    GLT(0);

    for (int kt = 0; kt < ntiles; kt++) {
        const int kvbase = kt * 64;

        #pragma unroll
        for (int i = 0; i < 4; i++) {
            int idx = tid + i*256;
            int r = idx >> 4, c4 = (idx & 15) << 2;
            unsigned lo;
            unsigned hi01 = split_pack(pk[i].x, pk[i].y, lo);
            *(unsigned*)&sKh[r*72 + c4]     = hi01;
            *(unsigned*)&sKl[r*72 + c4]     = lo;
            unsigned hi23 = split_pack(pk[i].z, pk[i].w, lo);
            *(unsigned*)&sKh[r*72 + c4 + 2] = hi23;
            *(unsigned*)&sKl[r*72 + c4 + 2] = lo;
            float vf[4] = {pv[i].x, pv[i].y, pv[i].z, pv[i].w};
            #pragma unroll
            for (int j = 0; j < 4; j++) {
                __half vh = __float2half_rn(vf[j]);
                __half vl = __float2half_rn(vf[j] - __half2float(vh));
                sVh[(c4+j)*72 + r] = vh;
                sVl[(c4+j)*72 + r] = vl;
            }
        }
        __syncthreads();

        if (kt + 1 < ntiles) { GLT(kt + 1); }

        if (kvbase <= wrowmax) {
            float sc[8][4] = {};

            #pragma unroll
            for (int kk = 0; kk < 4; kk++) {
                int ko = kk*16 + 2*tg;
                #pragma unroll
                for (int ni = 0; ni < 8; ni++) {
                    int rb = (ni*8 + g)*72 + ko;
                    unsigned b0h = *(const unsigned*)&sKh[rb];
                    unsigned b1h = *(const unsigned*)&sKh[rb + 8];
                    unsigned b0l = *(const unsigned*)&sKl[rb];
                    unsigned b1l = *(const unsigned*)&sKl[rb + 8];
                    MMA16816(sc[ni], qh[kk], b0h, b1h);
                    MMA16816(sc[ni], ql[kk], b0h, b1h);
                    MMA16816(sc[ni], qh[kk], b0l, b1l);
                }
            }

            if (kvbase + 63 > row0) {
                #pragma unroll
                for (int ni = 0; ni < 8; ni++) {
                    int c = kvbase + ni*8 + 2*tg;
                    if (c     > row0) sc[ni][0] = -1e30f;
                    if (c + 1 > row0) sc[ni][1] = -1e30f;
                    if (c     > row1) sc[ni][2] = -1e30f;
                    if (c + 1 > row1) sc[ni][3] = -1e30f;
                }
            }

            float t0 = -1e30f, t1 = -1e30f;
            #pragma unroll
            for (int ni = 0; ni < 8; ni++) {
                t0 = fmaxf(t0, fmaxf(sc[ni][0], sc[ni][1]));
                t1 = fmaxf(t1, fmaxf(sc[ni][2], sc[ni][3]));
            }
            t0 = fmaxf(t0, __shfl_xor_sync(0xffffffffu, t0, 1));
            t0 = fmaxf(t0, __shfl_xor_sync(0xffffffffu, t0, 2));
            t1 = fmaxf(t1, __shfl_xor_sync(0xffffffffu, t1, 1));
            t1 = fmaxf(t1, __shfl_xor_sync(0xffffffffu, t1, 2));

            float m0n = fmaxf(m0, t0), m1n = fmaxf(m1, t1);
            float c0 = __expf(m0 - m0n), c1 = __expf(m1 - m1n);
            m0 = m0n; m1 = m1n;
            l0 *= c0;  l1 *= c1;
            #pragma unroll
            for (int ni = 0; ni < 8; ni++) {
                o[ni][0] *= c0; o[ni][1] *= c0;
                o[ni][2] *= c1; o[ni][3] *= c1;
            }

            #pragma unroll
            for (int ni = 0; ni < 8; ni++) {
                sc[ni][0] = __expf(sc[ni][0] - m0);
                sc[ni][1] = __expf(sc[ni][1] - m0);
                sc[ni][2] = __expf(sc[ni][2] - m1);
                sc[ni][3] = __expf(sc[ni][3] - m1);
                l0 += sc[ni][0] + sc[ni][1];
                l1 += sc[ni][2] + sc[ni][3];
            }

            #pragma unroll
            for (int kk = 0; kk < 4; kk++) {
                unsigned ph[4];
                ph[0] = pack_h(sc[2*kk][0],   sc[2*kk][1]);
                ph[1] = pack_h(sc[2*kk][2],   sc[2*kk][3]);
                ph[2] = pack_h(sc[2*kk+1][0], sc[2*kk+1][1]);
                ph[3] = pack_h(sc[2*kk+1][2], sc[2*kk+1][3]);
                int ko = kk*16 + 2*tg;
                #pragma unroll
                for (int nd = 0; nd < 8; nd++) {
                    int rb = (nd*8 + g)*72 + ko;
                    unsigned b0h = *(const unsigned*)&sVh[rb];
                    unsigned b1h = *(const unsigned*)&sVh[rb + 8];
                    unsigned b0l = *(const unsigned*)&sVl[rb];
                    unsigned b1l = *(const unsigned*)&sVl[rb + 8];
                    MMA16816(o[nd], ph, b0h, b1h);
                    MMA16816(o[nd], ph, b0l, b1l);
                }
            }
        }
        __syncthreads();
    }
    #undef GLT

    l0 += __shfl_xor_sync(0xffffffffu, l0, 1);
    l0 += __shfl_xor_sync(0xffffffffu, l0, 2);
    l1 += __shfl_xor_sync(0xffffffffu, l1, 1);
    l1 += __shfl_xor_sync(0xffffffffu, l1, 2);
    float inv0 = 1.f / l0, inv1 = 1.f / l1;

    // fused hi/lo epilogue (replaces g_attn + cvt_attn)
    size_t base0 = ((size_t)(b*SEQ) + row0)*DMODEL + h*DK;
    size_t base1 = ((size_t)(b*SEQ) + row1)*DMODEL + h*DK;
    #pragma unroll
    for (int nd = 0; nd < 8; nd++) {
        int c = nd*8 + 2*tg;
        unsigned lo;
        unsigned hi = split_pack(o[nd][0]*inv0, o[nd][1]*inv0, lo);
        *(unsigned*)&g_ah[base0 + c] = hi;
        *(unsigned*)&g_al[base0 + c] = lo;
        hi = split_pack(o[nd][2]*inv1, o[nd][3]*inv1, lo);
        *(unsigned*)&g_ah[base1 + c] = hi;
        *(unsigned*)&g_al[base1 + c] = lo;
    }
}

// ---------------------------------------------------------------------------
extern "C" void kernel_launch(void* const* d_in, const int* in_sizes, int n_in,
                              void* d_out, int out_size)
{
    const float* x      = (const float*)d_in[0];
    const int*   pos    = (const int*)d_in[1];
    const float* w_qkv  = (const float*)d_in[2];
    const float* w_o    = (const float*)d_in[3];
    float*       out    = (float*)d_out;

    cudaFuncSetAttribute(qkv_gemm_kernel,
                         cudaFuncAttributeMaxDynamicSharedMemorySize, GEMM_SMEM);
    cudaFuncSetAttribute(out_gemm_kernel,
                         cudaFuncAttributeMaxDynamicSharedMemorySize, GEMM_SMEM);

    // 0) fp16 splits (x hi/lo; weights hi only)
    cvt_x_kernel <<<(NTOK*DMODEL/4 + 255)/256, 256>>>(x);
    cvt_wq_kernel<<<(E3*DMODEL/4   + 255)/256, 256>>>(w_qkv);
    cvt_wo_kernel<<<(DMODEL*DMODEL/4 + 255)/256, 256>>>(w_o);

    // 1) QKV projection
    {
        dim3 grid(E3 / 128, NTOK / 128);
        qkv_gemm_kernel<<<grid, 256, GEMM_SMEM>>>();
    }
    // 2) RoPE
    {
        int total = NTOK * NHEADS * (DK / 2);
        rope_kernel<<<(total + 255) / 256, 256>>>(pos);
    }
    // 3) Causal flash attention (writes hi/lo split directly)
    {
        dim3 grid(SEQ / 128, NHEADS, BATCH);
        attn_mma_kernel<<<grid, 256>>>();
    }
    // 4) Output projection
    {
        dim3 grid(DMODEL / 128, NTOK / 128);
        out_gemm_kernel<<<grid, 256, GEMM_SMEM>>>(out);
    }
}

// round 8
// speedup vs baseline: 3.4989x; 1.1681x over previous
#include <cuda_runtime.h>
#include <cuda_fp16.h>
#include <math.h>

#define BATCH   2
#define SEQ     2048
#define DMODEL  1024
#define NHEADS  16
#define DK      64
#define NTOK    (BATCH*SEQ)      /* 4096 */
#define E3      (3*DMODEL)       /* 3072 */

// Scratch (allocation-free rule: __device__ globals)
__device__ float  g_qkv[(size_t)NTOK * E3];
// hi/lo fp16 split operands (B-side lo not needed: 2-pass GEMM)
__device__ __half g_xh[(size_t)NTOK * DMODEL],  g_xl[(size_t)NTOK * DMODEL];
__device__ __half g_wqh[(size_t)E3 * DMODEL];
__device__ __half g_woh[(size_t)DMODEL*DMODEL];
__device__ __half g_ah[(size_t)NTOK * DMODEL],  g_al[(size_t)NTOK * DMODEL];

// ---------------------------------------------------------------------------
// fp16 hi/lo helpers
// ---------------------------------------------------------------------------
__device__ __forceinline__ void split_store(float4 v, __half* dh, __half* dl)
{
    __half2 h01 = __floats2half2_rn(v.x, v.y);
    __half2 h23 = __floats2half2_rn(v.z, v.w);
    float2 f01 = __half22float2(h01);
    float2 f23 = __half22float2(h23);
    __half2 l01 = __floats2half2_rn(v.x - f01.x, v.y - f01.y);
    __half2 l23 = __floats2half2_rn(v.z - f23.x, v.w - f23.y);
    *(__half2*)&dh[0] = h01;  *(__half2*)&dh[2] = h23;
    *(__half2*)&dl[0] = l01;  *(__half2*)&dl[2] = l23;
}

__device__ __forceinline__ unsigned split_pack(float a, float b, unsigned& lo)
{
    __half2 h = __floats2half2_rn(a, b);
    float2 f = __half22float2(h);
    __half2 l = __floats2half2_rn(a - f.x, b - f.y);
    lo = *reinterpret_cast<unsigned*>(&l);
    return *reinterpret_cast<unsigned*>(&h);
}

__device__ __forceinline__ unsigned pack_h(float a, float b)
{
    __half2 h = __floats2half2_rn(a, b);
    return *reinterpret_cast<unsigned*>(&h);
}

__global__ void cvt_x_kernel(const float* __restrict__ x) {
    int i = blockIdx.x * blockDim.x + threadIdx.x;
    if (i >= NTOK * DMODEL / 4) return;
    split_store(((const float4*)x)[i], g_xh + (size_t)i*4, g_xl + (size_t)i*4);
}
__global__ void cvt_wq_kernel(const float* __restrict__ w) {
    int i = blockIdx.x * blockDim.x + threadIdx.x;
    if (i >= E3 * DMODEL / 4) return;
    float4 v = ((const float4*)w)[i];
    __half2 h01 = __floats2half2_rn(v.x, v.y);
    __half2 h23 = __floats2half2_rn(v.z, v.w);
    *(__half2*)&g_wqh[(size_t)i*4]     = h01;
    *(__half2*)&g_wqh[(size_t)i*4 + 2] = h23;
}
__global__ void cvt_wo_kernel(const float* __restrict__ w) {
    int i = blockIdx.x * blockDim.x + threadIdx.x;
    if (i >= DMODEL * DMODEL / 4) return;
    float4 v = ((const float4*)w)[i];
    __half2 h01 = __floats2half2_rn(v.x, v.y);
    __half2 h23 = __floats2half2_rn(v.z, v.w);
    *(__half2*)&g_woh[(size_t)i*4]     = h01;
    *(__half2*)&g_woh[(size_t)i*4 + 2] = h23;
}

// ---------------------------------------------------------------------------
#define MMA16816(d, a, b0, b1)                                                 \
    asm volatile("mma.sync.aligned.m16n8k16.row.col.f32.f16.f16.f32 "          \
                 "{%0,%1,%2,%3}, {%4,%5,%6,%7}, {%8,%9}, {%0,%1,%2,%3};"       \
                 : "+f"(d[0]), "+f"(d[1]), "+f"(d[2]), "+f"(d[3])              \
                 : "r"(a[0]), "r"(a[1]), "r"(a[2]), "r"(a[3]), "r"(b0), "r"(b1))

// ---------------------------------------------------------------------------
// fp16 (hi/lo A, hi B) tensor-core GEMM (unchanged from R6 — known good).
// ---------------------------------------------------------------------------
#define ARR_HALVES (128*40)
#define BUF_HALVES (3*ARR_HALVES)
#define GEMM_SMEM  (2*BUF_HALVES*2)   /* bytes = 61440 */

template<int M, int N, int K>
__device__ __forceinline__ void gemm_hl_body(const __half* __restrict__ Ah,
                                             const __half* __restrict__ Al,
                                             const __half* __restrict__ Bh,
                                             float* __restrict__ C)
{
    extern __shared__ __half dynsmem[];

    const int tid  = threadIdx.x;
    const int lane = tid & 31;
    const int wid  = tid >> 5;
    const int warpM = wid & 3;
    const int warpN = wid >> 2;
    const int m0 = blockIdx.y * 128;
    const int n0 = blockIdx.x * 128;
    const int g  = lane >> 2;
    const int tg = lane & 3;

    float acc[2][8][4] = {};
    uint4 pah[2], pal[2], pbh[2];

    const int r_st[2] = { (tid)       >> 2, (tid + 256) >> 2 };
    const int c_st[2] = { (tid & 3) << 3,   (tid & 3) << 3 };

    #define GL(k0)                                                              \
        _Pragma("unroll")                                                       \
        for (int i = 0; i < 2; i++) {                                           \
            size_t ao = (size_t)(m0 + r_st[i]) * K + (k0) + c_st[i];            \
            size_t bo = (size_t)(n0 + r_st[i]) * K + (k0) + c_st[i];            \
            pah[i] = *(const uint4*)&Ah[ao];                                    \
            pal[i] = *(const uint4*)&Al[ao];                                    \
            pbh[i] = *(const uint4*)&Bh[bo];                                    \
        }

    #define STS_BUF(buf_)                                                       \
        _Pragma("unroll")                                                       \
        for (int i = 0; i < 2; i++) {                                           \
            __half* base = dynsmem + (buf_) * BUF_HALVES;                       \
            int off = r_st[i]*40 + c_st[i];                                     \
            *(uint4*)&base[off]                = pah[i];                        \
            *(uint4*)&base[ARR_HALVES + off]   = pal[i];                        \
            *(uint4*)&base[2*ARR_HALVES + off] = pbh[i];                        \
        }

    GL(0);
    STS_BUF(0);
    __syncthreads();

    const int nch = K / 32;
    for (int ch = 0; ch < nch; ch++) {
        const int buf = ch & 1;
        const __half* sAh_ = dynsmem + buf * BUF_HALVES;
        const __half* sAl_ = sAh_ + ARR_HALVES;
        const __half* sBh_ = sAh_ + 2*ARR_HALVES;

        if (ch + 1 < nch) { GL((ch + 1) * 32); }

        #pragma unroll
        for (int ks = 0; ks < 2; ks++) {
            const int kb = ks * 16;
            unsigned ah[2][4], al[2][4];
            #pragma unroll
            for (int mi = 0; mi < 2; mi++) {
                int r0 = (warpM*32 + mi*16 + g) * 40 + kb + 2*tg;
                int r8 = r0 + 8*40;
                ah[mi][0] = *(const unsigned*)&sAh_[r0];
                ah[mi][1] = *(const unsigned*)&sAh_[r8];
                ah[mi][2] = *(const unsigned*)&sAh_[r0 + 8];
                ah[mi][3] = *(const unsigned*)&sAh_[r8 + 8];
                al[mi][0] = *(const unsigned*)&sAl_[r0];
                al[mi][1] = *(const unsigned*)&sAl_[r8];
                al[mi][2] = *(const unsigned*)&sAl_[r0 + 8];
                al[mi][3] = *(const unsigned*)&sAl_[r8 + 8];
            }
            #pragma unroll
            for (int ni = 0; ni < 8; ni++) {
                int nb = (warpN*64 + ni*8 + g) * 40 + kb + 2*tg;
                unsigned b0 = *(const unsigned*)&sBh_[nb];
                unsigned b1 = *(const unsigned*)&sBh_[nb + 8];
                #pragma unroll
                for (int mi = 0; mi < 2; mi++) {
                    MMA16816(acc[mi][ni], ah[mi], b0, b1);
                    MMA16816(acc[mi][ni], al[mi], b0, b1);
                }
            }
        }

        if (ch + 1 < nch) { STS_BUF(buf ^ 1); }
        __syncthreads();
    }
    #undef GL
    #undef STS_BUF

    #pragma unroll
    for (int mi = 0; mi < 2; mi++) {
        int r0 = m0 + warpM*32 + mi*16 + g;
        #pragma unroll
        for (int ni = 0; ni < 8; ni++) {
            int c = n0 + warpN*64 + ni*8 + tg*2;
            *(float2*)&C[(size_t)r0 * N + c] =
                make_float2(acc[mi][ni][0], acc[mi][ni][1]);
            *(float2*)&C[(size_t)(r0+8) * N + c] =
                make_float2(acc[mi][ni][2], acc[mi][ni][3]);
        }
    }
}

__global__ __launch_bounds__(256, 2)
void qkv_gemm_kernel() {
    gemm_hl_body<NTOK, E3, DMODEL>(g_xh, g_xl, g_wqh, g_qkv);
}
__global__ __launch_bounds__(256, 2)
void out_gemm_kernel(float* __restrict__ out) {
    gemm_hl_body<NTOK, DMODEL, DMODEL>(g_ah, g_al, g_woh, out);
}

// ---------------------------------------------------------------------------
// RoPE applied in-place to Q and K halves of g_qkv (unchanged, known-good).
// ---------------------------------------------------------------------------
__global__ void rope_kernel(const int* __restrict__ pos)
{
    int t = blockIdx.x * blockDim.x + threadIdx.x;
    const int total = NTOK * NHEADS * (DK / 2);
    if (t >= total) return;

    int i = t & 31;
    int h = (t >> 5) & (NHEADS - 1);
    int n = t >> 9;
    int s = n & (SEQ - 1);

    float p = (float)pos[s];
    float inv = expf(-((float)i / 32.0f) * 9.2103403719761836f);
    float ang = p * inv;
    float sn, cs;
    sincosf(ang, &sn, &cs);

    float* q = &g_qkv[(size_t)n * E3 + h * DK + 2 * i];
    float q1 = q[0], q2 = q[1];
    q[0] = q1 * cs - q2 * sn;
    q[1] = q1 * sn + q2 * cs;

    float* k = q + DMODEL;
    float k1 = k[0], k2 = k[1];
    k[0] = k1 * cs - k2 * sn;
    k[1] = k1 * sn + k2 * cs;
}

// ---------------------------------------------------------------------------
// Causal flash attention, fp16 hi/lo tensor cores.
// R7: QK^T 2-pass (Q hi/lo x K hi; sKl deleted) + double-buffered KV smem
// (one __syncthreads per tile). Epilogue writes hi/lo split directly.
// ---------------------------------------------------------------------------
__global__ __launch_bounds__(256)
void attn_mma_kernel()
{
    const int qt  = blockIdx.x;
    const int h   = blockIdx.y;
    const int b   = blockIdx.z;
    const int tid = threadIdx.x;
    const int lane = tid & 31;
    const int w   = tid >> 5;
    const int g   = lane >> 2;
    const int tg  = lane & 3;

    __shared__ __half sKh[2][64*72], sVh[2][64*72], sVl[2][64*72];

    const int qbase = qt * 128;
    const int row0 = qbase + w*16 + g;
    const int row1 = row0 + 8;
    const int wrowmax = qbase + w*16 + 15;
    const float scale = 0.125f;

    unsigned qh[4][4], ql[4][4];
    {
        const float* q0 = &g_qkv[((size_t)(b*SEQ) + row0)*E3 + h*DK];
        const float* q1 = &g_qkv[((size_t)(b*SEQ) + row1)*E3 + h*DK];
        #pragma unroll
        for (int kk = 0; kk < 4; kk++) {
            int d0 = kk*16 + 2*tg;
            float2 a0 = *(const float2*)&q0[d0];
            float2 a1 = *(const float2*)&q1[d0];
            float2 a2 = *(const float2*)&q0[d0+8];
            float2 a3 = *(const float2*)&q1[d0+8];
            qh[kk][0] = split_pack(a0.x*scale, a0.y*scale, ql[kk][0]);
            qh[kk][1] = split_pack(a1.x*scale, a1.y*scale, ql[kk][1]);
            qh[kk][2] = split_pack(a2.x*scale, a2.y*scale, ql[kk][2]);
            qh[kk][3] = split_pack(a3.x*scale, a3.y*scale, ql[kk][3]);
        }
    }

    float o[8][4] = {};
    float m0 = -1e30f, m1 = -1e30f, l0 = 0.f, l1 = 0.f;

    const int ntiles = 2*qt + 2;
    float4 pk[4], pv[4];

    #define GLT(kt_)                                                           \
        _Pragma("unroll")                                                      \
        for (int i = 0; i < 4; i++) {                                          \
            int idx = tid + i*256;                                             \
            int r = idx >> 4, c4 = (idx & 15) << 2;                            \
            size_t base = ((size_t)(b*SEQ) + (kt_)*64 + r)*E3 + h*DK + c4;     \
            pk[i] = *(const float4*)&g_qkv[base + DMODEL];                     \
            pv[i] = *(const float4*)&g_qkv[base + 2*DMODEL];                   \
        }

    // stage tile into smem buffer buf_: K hi only; V hi+lo transposed
    #define STS_T(buf_)                                                        \
        _Pragma("unroll")                                                      \
        for (int i = 0; i < 4; i++) {                                          \
            int idx = tid + i*256;                                             \
            int r = idx >> 4, c4 = (idx & 15) << 2;                            \
            *(unsigned*)&sKh[buf_][r*72 + c4]     = pack_h(pk[i].x, pk[i].y);  \
            *(unsigned*)&sKh[buf_][r*72 + c4 + 2] = pack_h(pk[i].z, pk[i].w);  \
            float vf[4] = {pv[i].x, pv[i].y, pv[i].z, pv[i].w};                \
            _Pragma("unroll")                                                  \
            for (int j = 0; j < 4; j++) {                                      \
                __half vh = __float2half_rn(vf[j]);                            \
                __half vl = __float2half_rn(vf[j] - __half2float(vh));         \
                sVh[buf_][(c4+j)*72 + r] = vh;                                 \
                sVl[buf_][(c4+j)*72 + r] = vl;                                 \
            }                                                                  \
        }

    GLT(0);
    STS_T(0);
    __syncthreads();

    for (int kt = 0; kt < ntiles; kt++) {
        const int kvbase = kt * 64;
        const int buf = kt & 1;

        if (kt + 1 < ntiles) { GLT(kt + 1); }

        if (kvbase <= wrowmax) {
            float sc[8][4] = {};

            // QK^T: 2-pass (Q hi + Q lo) x K hi
            #pragma unroll
            for (int kk = 0; kk < 4; kk++) {
                int ko = kk*16 + 2*tg;
                #pragma unroll
                for (int ni = 0; ni < 8; ni++) {
                    int rb = (ni*8 + g)*72 + ko;
                    unsigned b0h = *(const unsigned*)&sKh[buf][rb];
                    unsigned b1h = *(const unsigned*)&sKh[buf][rb + 8];
                    MMA16816(sc[ni], qh[kk], b0h, b1h);
                    MMA16816(sc[ni], ql[kk], b0h, b1h);
                }
            }

            if (kvbase + 63 > row0) {
                #pragma unroll
                for (int ni = 0; ni < 8; ni++) {
                    int c = kvbase + ni*8 + 2*tg;
                    if (c     > row0) sc[ni][0] = -1e30f;
                    if (c + 1 > row0) sc[ni][1] = -1e30f;
                    if (c     > row1) sc[ni][2] = -1e30f;
                    if (c + 1 > row1) sc[ni][3] = -1e30f;
                }
            }

            float t0 = -1e30f, t1 = -1e30f;
            #pragma unroll
            for (int ni = 0; ni < 8; ni++) {
                t0 = fmaxf(t0, fmaxf(sc[ni][0], sc[ni][1]));
                t1 = fmaxf(t1, fmaxf(sc[ni][2], sc[ni][3]));
            }
            t0 = fmaxf(t0, __shfl_xor_sync(0xffffffffu, t0, 1));
            t0 = fmaxf(t0, __shfl_xor_sync(0xffffffffu, t0, 2));
            t1 = fmaxf(t1, __shfl_xor_sync(0xffffffffu, t1, 1));
            t1 = fmaxf(t1, __shfl_xor_sync(0xffffffffu, t1, 2));

            float m0n = fmaxf(m0, t0), m1n = fmaxf(m1, t1);
            float c0 = __expf(m0 - m0n), c1 = __expf(m1 - m1n);
            m0 = m0n; m1 = m1n;
            l0 *= c0;  l1 *= c1;
            #pragma unroll
            for (int ni = 0; ni < 8; ni++) {
                o[ni][0] *= c0; o[ni][1] *= c0;
                o[ni][2] *= c1; o[ni][3] *= c1;
            }

            #pragma unroll
            for (int ni = 0; ni < 8; ni++) {
                sc[ni][0] = __expf(sc[ni][0] - m0);
                sc[ni][1] = __expf(sc[ni][1] - m0);
                sc[ni][2] = __expf(sc[ni][2] - m1);
                sc[ni][3] = __expf(sc[ni][3] - m1);
                l0 += sc[ni][0] + sc[ni][1];
                l1 += sc[ni][2] + sc[ni][3];
            }

            // PV: P_h * (V_h + V_l)
            #pragma unroll
            for (int kk = 0; kk < 4; kk++) {
                unsigned ph[4];
                ph[0] = pack_h(sc[2*kk][0],   sc[2*kk][1]);
                ph[1] = pack_h(sc[2*kk][2],   sc[2*kk][3]);
                ph[2] = pack_h(sc[2*kk+1][0], sc[2*kk+1][1]);
                ph[3] = pack_h(sc[2*kk+1][2], sc[2*kk+1][3]);
                int ko = kk*16 + 2*tg;
                #pragma unroll
                for (int nd = 0; nd < 8; nd++) {
                    int rb = (nd*8 + g)*72 + ko;
                    unsigned b0h = *(const unsigned*)&sVh[buf][rb];
                    unsigned b1h = *(const unsigned*)&sVh[buf][rb + 8];
                    unsigned b0l = *(const unsigned*)&sVl[buf][rb];
                    unsigned b1l = *(const unsigned*)&sVl[buf][rb + 8];
                    MMA16816(o[nd], ph, b0h, b1h);
                    MMA16816(o[nd], ph, b0l, b1l);
                }
            }
        }

        if (kt + 1 < ntiles) { STS_T(buf ^ 1); }
        __syncthreads();
    }
    #undef GLT
    #undef STS_T

    l0 += __shfl_xor_sync(0xffffffffu, l0, 1);
    l0 += __shfl_xor_sync(0xffffffffu, l0, 2);
    l1 += __shfl_xor_sync(0xffffffffu, l1, 1);
    l1 += __shfl_xor_sync(0xffffffffu, l1, 2);
    float inv0 = 1.f / l0, inv1 = 1.f / l1;

    // fused hi/lo epilogue
    size_t base0 = ((size_t)(b*SEQ) + row0)*DMODEL + h*DK;
    size_t base1 = ((size_t)(b*SEQ) + row1)*DMODEL + h*DK;
    #pragma unroll
    for (int nd = 0; nd < 8; nd++) {
        int c = nd*8 + 2*tg;
        unsigned lo;
        unsigned hi = split_pack(o[nd][0]*inv0, o[nd][1]*inv0, lo);
        *(unsigned*)&g_ah[base0 + c] = hi;
        *(unsigned*)&g_al[base0 + c] = lo;
        hi = split_pack(o[nd][2]*inv1, o[nd][3]*inv1, lo);
        *(unsigned*)&g_ah[base1 + c] = hi;
        *(unsigned*)&g_al[base1 + c] = lo;
    }
}

// ---------------------------------------------------------------------------
extern "C" void kernel_launch(void* const* d_in, const int* in_sizes, int n_in,
                              void* d_out, int out_size)
{
    const float* x      = (const float*)d_in[0];
    const int*   pos    = (const int*)d_in[1];
    const float* w_qkv  = (const float*)d_in[2];
    const float* w_o    = (const float*)d_in[3];
    float*       out    = (float*)d_out;

    cudaFuncSetAttribute(qkv_gemm_kernel,
                         cudaFuncAttributeMaxDynamicSharedMemorySize, GEMM_SMEM);
    cudaFuncSetAttribute(out_gemm_kernel,
                         cudaFuncAttributeMaxDynamicSharedMemorySize, GEMM_SMEM);

    // 0) fp16 splits (x hi/lo; weights hi only)
    cvt_x_kernel <<<(NTOK*DMODEL/4 + 255)/256, 256>>>(x);
    cvt_wq_kernel<<<(E3*DMODEL/4   + 255)/256, 256>>>(w_qkv);
    cvt_wo_kernel<<<(DMODEL*DMODEL/4 + 255)/256, 256>>>(w_o);

    // 1) QKV projection
    {
        dim3 grid(E3 / 128, NTOK / 128);
        qkv_gemm_kernel<<<grid, 256, GEMM_SMEM>>>();
    }
    // 2) RoPE
    {
        int total = NTOK * NHEADS * (DK / 2);
        rope_kernel<<<(total + 255) / 256, 256>>>(pos);
    }
    // 3) Causal flash attention (writes hi/lo split directly)
    {
        dim3 grid(SEQ / 128, NHEADS, BATCH);
        attn_mma_kernel<<<grid, 256>>>();
    }
    // 4) Output projection
    {
        dim3 grid(DMODEL / 128, NTOK / 128);
        out_gemm_kernel<<<grid, 256, GEMM_SMEM>>>(out);
    }
}

// round 9
// speedup vs baseline: 3.6634x; 1.0470x over previous
#include <cuda_runtime.h>
#include <cuda_fp16.h>
#include <math.h>

#define BATCH   2
#define SEQ     2048
#define DMODEL  1024
#define NHEADS  16
#define DK      64
#define NTOK    (BATCH*SEQ)      /* 4096 */
#define E3      (3*DMODEL)       /* 3072 */

// Scratch (allocation-free rule: __device__ globals)
__device__ float  g_qkv[(size_t)NTOK * E3];
__device__ __half g_xh[(size_t)NTOK * DMODEL],  g_xl[(size_t)NTOK * DMODEL];
__device__ __half g_wqh[(size_t)E3 * DMODEL];
__device__ __half g_woh[(size_t)DMODEL*DMODEL];
__device__ __half g_ah[(size_t)NTOK * DMODEL],  g_al[(size_t)NTOK * DMODEL];

// ---------------------------------------------------------------------------
// fp16 hi/lo helpers
// ---------------------------------------------------------------------------
__device__ __forceinline__ void split_store(float4 v, __half* dh, __half* dl)
{
    __half2 h01 = __floats2half2_rn(v.x, v.y);
    __half2 h23 = __floats2half2_rn(v.z, v.w);
    float2 f01 = __half22float2(h01);
    float2 f23 = __half22float2(h23);
    __half2 l01 = __floats2half2_rn(v.x - f01.x, v.y - f01.y);
    __half2 l23 = __floats2half2_rn(v.z - f23.x, v.w - f23.y);
    *(__half2*)&dh[0] = h01;  *(__half2*)&dh[2] = h23;
    *(__half2*)&dl[0] = l01;  *(__half2*)&dl[2] = l23;
}

__device__ __forceinline__ unsigned split_pack(float a, float b, unsigned& lo)
{
    __half2 h = __floats2half2_rn(a, b);
    float2 f = __half22float2(h);
    __half2 l = __floats2half2_rn(a - f.x, b - f.y);
    lo = *reinterpret_cast<unsigned*>(&l);
    return *reinterpret_cast<unsigned*>(&h);
}

__device__ __forceinline__ unsigned pack_h(float a, float b)
{
    __half2 h = __floats2half2_rn(a, b);
    return *reinterpret_cast<unsigned*>(&h);
}

__global__ void cvt_x_kernel(const float* __restrict__ x) {
    int i = blockIdx.x * blockDim.x + threadIdx.x;
    if (i >= NTOK * DMODEL / 4) return;
    split_store(((const float4*)x)[i], g_xh + (size_t)i*4, g_xl + (size_t)i*4);
}
__global__ void cvt_wq_kernel(const float* __restrict__ w) {
    int i = blockIdx.x * blockDim.x + threadIdx.x;
    if (i >= E3 * DMODEL / 4) return;
    float4 v = ((const float4*)w)[i];
    *(__half2*)&g_wqh[(size_t)i*4]     = __floats2half2_rn(v.x, v.y);
    *(__half2*)&g_wqh[(size_t)i*4 + 2] = __floats2half2_rn(v.z, v.w);
}
__global__ void cvt_wo_kernel(const float* __restrict__ w) {
    int i = blockIdx.x * blockDim.x + threadIdx.x;
    if (i >= DMODEL * DMODEL / 4) return;
    float4 v = ((const float4*)w)[i];
    *(__half2*)&g_woh[(size_t)i*4]     = __floats2half2_rn(v.x, v.y);
    *(__half2*)&g_woh[(size_t)i*4 + 2] = __floats2half2_rn(v.z, v.w);
}

// ---------------------------------------------------------------------------
#define MMA16816(d, a, b0, b1)                                                 \
    asm volatile("mma.sync.aligned.m16n8k16.row.col.f32.f16.f16.f32 "          \
                 "{%0,%1,%2,%3}, {%4,%5,%6,%7}, {%8,%9}, {%0,%1,%2,%3};"       \
                 : "+f"(d[0]), "+f"(d[1]), "+f"(d[2]), "+f"(d[3])              \
                 : "r"(a[0]), "r"(a[1]), "r"(a[2]), "r"(a[3]), "r"(b0), "r"(b1))

#define LDSM4(r0, r1, r2, r3, addr)                                            \
    asm volatile("ldmatrix.sync.aligned.m8n8.x4.shared.b16 {%0,%1,%2,%3}, [%4];" \
                 : "=r"(r0), "=r"(r1), "=r"(r2), "=r"(r3) : "r"(addr))

#define CP16(dst_u32, gptr)                                                    \
    asm volatile("cp.async.cg.shared.global [%0], [%1], 16;"                   \
                 :: "r"(dst_u32), "l"(gptr))
#define CP_COMMIT() asm volatile("cp.async.commit_group;" ::: "memory")
#define CP_WAIT1()  asm volatile("cp.async.wait_group 1;" ::: "memory")

// ---------------------------------------------------------------------------
// fp16 (hi/lo A, hi B) tensor-core GEMM: C = A*B^T, fp32 accum, 2-pass.
// R8: 3-stage cp.async pipeline (no register staging / no mainloop STS) and
// ldmatrix.x4 fragment loads. Row stride 40 halves (80B) keeps both cp.async
// stores and LDSM reads conflict-free (i*20 mod 32 covers all banks).
// ---------------------------------------------------------------------------
#define ARR_HALVES (128*40)
#define STG_HALVES (3*ARR_HALVES)
#define GEMM_SMEM  (3*STG_HALVES*2)   /* 92160 bytes */

template<int M, int N, int K>
__device__ __forceinline__ void gemm_hl_body(const __half* __restrict__ Ah,
                                             const __half* __restrict__ Al,
                                             const __half* __restrict__ Bh,
                                             float* __restrict__ C)
{
    extern __shared__ __half dynsmem[];
    const unsigned sbase = (unsigned)__cvta_generic_to_shared(dynsmem);

    const int tid  = threadIdx.x;
    const int lane = tid & 31;
    const int wid  = tid >> 5;
    const int warpM = wid & 3;
    const int warpN = wid >> 2;
    const int m0 = blockIdx.y * 128;
    const int n0 = blockIdx.x * 128;
    const int g  = lane >> 2;
    const int tg = lane & 3;

    float acc[2][8][4] = {};

    // cp.async per-thread coordinates: 2 rows x 16B per array per chunk
    const int r0c = tid >> 2, r1c = (tid + 256) >> 2;
    const int cc  = (tid & 3) << 3;                       // halves

    // ldmatrix per-lane offset within a tile: row = lane&15, colhalf = (lane>>4)*8
    const unsigned lm_off = ((unsigned)((lane & 15) * 40 + ((lane >> 4) << 3))) * 2;
    const unsigned a_base = sbase + (unsigned)(warpM * 32) * 80 + lm_off;
    const unsigned b_base = sbase + (unsigned)(warpN * 64) * 80 + lm_off;

    // issue one chunk's cp.async copies into stage s
    #define ISSUE(k0, s)                                                        \
        do {                                                                    \
            unsigned sb = sbase + (unsigned)(s) * (STG_HALVES * 2);             \
            size_t a0o = (size_t)(m0 + r0c) * K + (k0) + cc;                    \
            size_t a1o = (size_t)(m0 + r1c) * K + (k0) + cc;                    \
            size_t b0o = (size_t)(n0 + r0c) * K + (k0) + cc;                    \
            size_t b1o = (size_t)(n0 + r1c) * K + (k0) + cc;                    \
            unsigned d0 = sb + (unsigned)(r0c * 40 + cc) * 2;                   \
            unsigned d1 = sb + (unsigned)(r1c * 40 + cc) * 2;                   \
            CP16(d0,                    &Ah[a0o]);                              \
            CP16(d1,                    &Ah[a1o]);                              \
            CP16(d0 + ARR_HALVES*2,     &Al[a0o]);                              \
            CP16(d1 + ARR_HALVES*2,     &Al[a1o]);                              \
            CP16(d0 + 2*ARR_HALVES*2,   &Bh[b0o]);                              \
            CP16(d1 + 2*ARR_HALVES*2,   &Bh[b1o]);                              \
        } while (0)

    const int nch = K / 32;
    ISSUE(0, 0);  CP_COMMIT();
    ISSUE(32, 1); CP_COMMIT();

    for (int ch = 0; ch < nch; ch++) {
        CP_WAIT1();
        __syncthreads();

        if (ch + 2 < nch) { ISSUE((ch + 2) * 32, (ch + 2) % 3); }
        CP_COMMIT();   // empty group near tail keeps wait_group invariant

        const unsigned st = (unsigned)(ch % 3) * (STG_HALVES * 2);

        #pragma unroll
        for (int ks = 0; ks < 2; ks++) {
            const unsigned kb2 = (unsigned)(ks * 16) * 2;   // bytes
            unsigned ah[2][4], al[2][4];
            #pragma unroll
            for (int mi = 0; mi < 2; mi++) {
                unsigned aa = a_base + st + (unsigned)(mi * 16) * 80 + kb2;
                LDSM4(ah[mi][0], ah[mi][1], ah[mi][2], ah[mi][3], aa);
                LDSM4(al[mi][0], al[mi][1], al[mi][2], al[mi][3],
                      aa + ARR_HALVES * 2);
            }
            #pragma unroll
            for (int nip = 0; nip < 4; nip++) {
                unsigned ba = b_base + st + 2*ARR_HALVES*2
                            + (unsigned)(nip * 16) * 80 + kb2;
                unsigned b0e, b0o_, b1e, b1o_;
                LDSM4(b0e, b0o_, b1e, b1o_, ba);
                #pragma unroll
                for (int mi = 0; mi < 2; mi++) {
                    MMA16816(acc[mi][2*nip],   ah[mi], b0e, b1e);
                    MMA16816(acc[mi][2*nip],   al[mi], b0e, b1e);
                    MMA16816(acc[mi][2*nip+1], ah[mi], b0o_, b1o_);
                    MMA16816(acc[mi][2*nip+1], al[mi], b0o_, b1o_);
                }
            }
        }
    }
    #undef ISSUE

    #pragma unroll
    for (int mi = 0; mi < 2; mi++) {
        int r0 = m0 + warpM*32 + mi*16 + g;
        #pragma unroll
        for (int ni = 0; ni < 8; ni++) {
            int c = n0 + warpN*64 + ni*8 + tg*2;
            *(float2*)&C[(size_t)r0 * N + c] =
                make_float2(acc[mi][ni][0], acc[mi][ni][1]);
            *(float2*)&C[(size_t)(r0+8) * N + c] =
                make_float2(acc[mi][ni][2], acc[mi][ni][3]);
        }
    }
}

__global__ __launch_bounds__(256, 2)
void qkv_gemm_kernel() {
    gemm_hl_body<NTOK, E3, DMODEL>(g_xh, g_xl, g_wqh, g_qkv);
}
__global__ __launch_bounds__(256, 2)
void out_gemm_kernel(float* __restrict__ out) {
    gemm_hl_body<NTOK, DMODEL, DMODEL>(g_ah, g_al, g_woh, out);
}

// ---------------------------------------------------------------------------
// RoPE applied in-place to Q and K halves of g_qkv (unchanged, known-good).
// ---------------------------------------------------------------------------
__global__ void rope_kernel(const int* __restrict__ pos)
{
    int t = blockIdx.x * blockDim.x + threadIdx.x;
    const int total = NTOK * NHEADS * (DK / 2);
    if (t >= total) return;

    int i = t & 31;
    int h = (t >> 5) & (NHEADS - 1);
    int n = t >> 9;
    int s = n & (SEQ - 1);

    float p = (float)pos[s];
    float inv = expf(-((float)i / 32.0f) * 9.2103403719761836f);
    float ang = p * inv;
    float sn, cs;
    sincosf(ang, &sn, &cs);

    float* q = &g_qkv[(size_t)n * E3 + h * DK + 2 * i];
    float q1 = q[0], q2 = q[1];
    q[0] = q1 * cs - q2 * sn;
    q[1] = q1 * sn + q2 * cs;

    float* k = q + DMODEL;
    float k1 = k[0], k2 = k[1];
    k[0] = k1 * cs - k2 * sn;
    k[1] = k1 * sn + k2 * cs;
}

// ---------------------------------------------------------------------------
// Causal flash attention, fp16 hi/lo tensor cores (unchanged from R7).
// ---------------------------------------------------------------------------
__global__ __launch_bounds__(256)
void attn_mma_kernel()
{
    const int qt  = blockIdx.x;
    const int h   = blockIdx.y;
    const int b   = blockIdx.z;
    const int tid = threadIdx.x;
    const int lane = tid & 31;
    const int w   = tid >> 5;
    const int g   = lane >> 2;
    const int tg  = lane & 3;

    __shared__ __half sKh[2][64*72], sVh[2][64*72], sVl[2][64*72];

    const int qbase = qt * 128;
    const int row0 = qbase + w*16 + g;
    const int row1 = row0 + 8;
    const int wrowmax = qbase + w*16 + 15;
    const float scale = 0.125f;

    unsigned qh[4][4], ql[4][4];
    {
        const float* q0 = &g_qkv[((size_t)(b*SEQ) + row0)*E3 + h*DK];
        const float* q1 = &g_qkv[((size_t)(b*SEQ) + row1)*E3 + h*DK];
        #pragma unroll
        for (int kk = 0; kk < 4; kk++) {
            int d0 = kk*16 + 2*tg;
            float2 a0 = *(const float2*)&q0[d0];
            float2 a1 = *(const float2*)&q1[d0];
            float2 a2 = *(const float2*)&q0[d0+8];
            float2 a3 = *(const float2*)&q1[d0+8];
            qh[kk][0] = split_pack(a0.x*scale, a0.y*scale, ql[kk][0]);
            qh[kk][1] = split_pack(a1.x*scale, a1.y*scale, ql[kk][1]);
            qh[kk][2] = split_pack(a2.x*scale, a2.y*scale, ql[kk][2]);
            qh[kk][3] = split_pack(a3.x*scale, a3.y*scale, ql[kk][3]);
        }
    }

    float o[8][4] = {};
    float m0 = -1e30f, m1 = -1e30f, l0 = 0.f, l1 = 0.f;

    const int ntiles = 2*qt + 2;
    float4 pk[4], pv[4];

    #define GLT(kt_)                                                           \
        _Pragma("unroll")                                                      \
        for (int i = 0; i < 4; i++) {                                          \
            int idx = tid + i*256;                                             \
            int r = idx >> 4, c4 = (idx & 15) << 2;                            \
            size_t base = ((size_t)(b*SEQ) + (kt_)*64 + r)*E3 + h*DK + c4;     \
            pk[i] = *(const float4*)&g_qkv[base + DMODEL];                     \
            pv[i] = *(const float4*)&g_qkv[base + 2*DMODEL];                   \
        }

    #define STS_T(buf_)                                                        \
        _Pragma("unroll")                                                      \
        for (int i = 0; i < 4; i++) {                                          \
            int idx = tid + i*256;                                             \
            int r = idx >> 4, c4 = (idx & 15) << 2;                            \
            *(unsigned*)&sKh[buf_][r*72 + c4]     = pack_h(pk[i].x, pk[i].y);  \
            *(unsigned*)&sKh[buf_][r*72 + c4 + 2] = pack_h(pk[i].z, pk[i].w);  \
            float vf[4] = {pv[i].x, pv[i].y, pv[i].z, pv[i].w};                \
            _Pragma("unroll")                                                  \
            for (int j = 0; j < 4; j++) {                                      \
                __half vh = __float2half_rn(vf[j]);                            \
                __half vl = __float2half_rn(vf[j] - __half2float(vh));         \
                sVh[buf_][(c4+j)*72 + r] = vh;                                 \
                sVl[buf_][(c4+j)*72 + r] = vl;                                 \
            }                                                                  \
        }

    GLT(0);
    STS_T(0);
    __syncthreads();

    for (int kt = 0; kt < ntiles; kt++) {
        const int kvbase = kt * 64;
        const int buf = kt & 1;

        if (kt + 1 < ntiles) { GLT(kt + 1); }

        if (kvbase <= wrowmax) {
            float sc[8][4] = {};

            #pragma unroll
            for (int kk = 0; kk < 4; kk++) {
                int ko = kk*16 + 2*tg;
                #pragma unroll
                for (int ni = 0; ni < 8; ni++) {
                    int rb = (ni*8 + g)*72 + ko;
                    unsigned b0h = *(const unsigned*)&sKh[buf][rb];
                    unsigned b1h = *(const unsigned*)&sKh[buf][rb + 8];
                    MMA16816(sc[ni], qh[kk], b0h, b1h);
                    MMA16816(sc[ni], ql[kk], b0h, b1h);
                }
            }

            if (kvbase + 63 > row0) {
                #pragma unroll
                for (int ni = 0; ni < 8; ni++) {
                    int c = kvbase + ni*8 + 2*tg;
                    if (c     > row0) sc[ni][0] = -1e30f;
                    if (c + 1 > row0) sc[ni][1] = -1e30f;
                    if (c     > row1) sc[ni][2] = -1e30f;
                    if (c + 1 > row1) sc[ni][3] = -1e30f;
                }
            }

            float t0 = -1e30f, t1 = -1e30f;
            #pragma unroll
            for (int ni = 0; ni < 8; ni++) {
                t0 = fmaxf(t0, fmaxf(sc[ni][0], sc[ni][1]));
                t1 = fmaxf(t1, fmaxf(sc[ni][2], sc[ni][3]));
            }
            t0 = fmaxf(t0, __shfl_xor_sync(0xffffffffu, t0, 1));
            t0 = fmaxf(t0, __shfl_xor_sync(0xffffffffu, t0, 2));
            t1 = fmaxf(t1, __shfl_xor_sync(0xffffffffu, t1, 1));
            t1 = fmaxf(t1, __shfl_xor_sync(0xffffffffu, t1, 2));

            float m0n = fmaxf(m0, t0), m1n = fmaxf(m1, t1);
            float c0 = __expf(m0 - m0n), c1 = __expf(m1 - m1n);
            m0 = m0n; m1 = m1n;
            l0 *= c0;  l1 *= c1;
            #pragma unroll
            for (int ni = 0; ni < 8; ni++) {
                o[ni][0] *= c0; o[ni][1] *= c0;
                o[ni][2] *= c1; o[ni][3] *= c1;
            }

            #pragma unroll
            for (int ni = 0; ni < 8; ni++) {
                sc[ni][0] = __expf(sc[ni][0] - m0);
                sc[ni][1] = __expf(sc[ni][1] - m0);
                sc[ni][2] = __expf(sc[ni][2] - m1);
                sc[ni][3] = __expf(sc[ni][3] - m1);
                l0 += sc[ni][0] + sc[ni][1];
                l1 += sc[ni][2] + sc[ni][3];
            }

            #pragma unroll
            for (int kk = 0; kk < 4; kk++) {
                unsigned ph[4];
                ph[0] = pack_h(sc[2*kk][0],   sc[2*kk][1]);
                ph[1] = pack_h(sc[2*kk][2],   sc[2*kk][3]);
                ph[2] = pack_h(sc[2*kk+1][0], sc[2*kk+1][1]);
                ph[3] = pack_h(sc[2*kk+1][2], sc[2*kk+1][3]);
                int ko = kk*16 + 2*tg;
                #pragma unroll
                for (int nd = 0; nd < 8; nd++) {
                    int rb = (nd*8 + g)*72 + ko;
                    unsigned b0h = *(const unsigned*)&sVh[buf][rb];
                    unsigned b1h = *(const unsigned*)&sVh[buf][rb + 8];
                    unsigned b0l = *(const unsigned*)&sVl[buf][rb];
                    unsigned b1l = *(const unsigned*)&sVl[buf][rb + 8];
                    MMA16816(o[nd], ph, b0h, b1h);
                    MMA16816(o[nd], ph, b0l, b1l);
                }
            }
        }

        if (kt + 1 < ntiles) { STS_T(buf ^ 1); }
        __syncthreads();
    }
    #undef GLT
    #undef STS_T

    l0 += __shfl_xor_sync(0xffffffffu, l0, 1);
    l0 += __shfl_xor_sync(0xffffffffu, l0, 2);
    l1 += __shfl_xor_sync(0xffffffffu, l1, 1);
    l1 += __shfl_xor_sync(0xffffffffu, l1, 2);
    float inv0 = 1.f / l0, inv1 = 1.f / l1;

    size_t base0 = ((size_t)(b*SEQ) + row0)*DMODEL + h*DK;
    size_t base1 = ((size_t)(b*SEQ) + row1)*DMODEL + h*DK;
    #pragma unroll
    for (int nd = 0; nd < 8; nd++) {
        int c = nd*8 + 2*tg;
        unsigned lo;
        unsigned hi = split_pack(o[nd][0]*inv0, o[nd][1]*inv0, lo);
        *(unsigned*)&g_ah[base0 + c] = hi;
        *(unsigned*)&g_al[base0 + c] = lo;
        hi = split_pack(o[nd][2]*inv1, o[nd][3]*inv1, lo);
        *(unsigned*)&g_ah[base1 + c] = hi;
        *(unsigned*)&g_al[base1 + c] = lo;
    }
}

// ---------------------------------------------------------------------------
extern "C" void kernel_launch(void* const* d_in, const int* in_sizes, int n_in,
                              void* d_out, int out_size)
{
    const float* x      = (const float*)d_in[0];
    const int*   pos    = (const int*)d_in[1];
    const float* w_qkv  = (const float*)d_in[2];
    const float* w_o    = (const float*)d_in[3];
    float*       out    = (float*)d_out;

    cudaFuncSetAttribute(qkv_gemm_kernel,
                         cudaFuncAttributeMaxDynamicSharedMemorySize, GEMM_SMEM);
    cudaFuncSetAttribute(out_gemm_kernel,
                         cudaFuncAttributeMaxDynamicSharedMemorySize, GEMM_SMEM);

    // 0) fp16 splits (x hi/lo; weights hi only)
    cvt_x_kernel <<<(NTOK*DMODEL/4 + 255)/256, 256>>>(x);
    cvt_wq_kernel<<<(E3*DMODEL/4   + 255)/256, 256>>>(w_qkv);
    cvt_wo_kernel<<<(DMODEL*DMODEL/4 + 255)/256, 256>>>(w_o);

    // 1) QKV projection
    {
        dim3 grid(E3 / 128, NTOK / 128);
        qkv_gemm_kernel<<<grid, 256, GEMM_SMEM>>>();
    }
    // 2) RoPE
    {
        int total = NTOK * NHEADS * (DK / 2);
        rope_kernel<<<(total + 255) / 256, 256>>>(pos);
    }
    // 3) Causal flash attention (writes hi/lo split directly)
    {
        dim3 grid(SEQ / 128, NHEADS, BATCH);
        attn_mma_kernel<<<grid, 256>>>();
    }
    // 4) Output projection
    {
        dim3 grid(DMODEL / 128, NTOK / 128);
        out_gemm_kernel<<<grid, 256, GEMM_SMEM>>>(out);
    }
}

// round 10
// speedup vs baseline: 3.8991x; 1.0643x over previous
#include <cuda_runtime.h>
#include <cuda_fp16.h>
#include <math.h>

#define BATCH   2
#define SEQ     2048
#define DMODEL  1024
#define NHEADS  16
#define DK      64
#define NTOK    (BATCH*SEQ)      /* 4096 */
#define E3      (3*DMODEL)       /* 3072 */
#define NTQ     (SEQ/128)        /* 16 q-tiles */

// Scratch (allocation-free rule: __device__ globals)
__device__ float  g_qkv[(size_t)NTOK * E3];
__device__ __half g_xh[(size_t)NTOK * DMODEL],  g_xl[(size_t)NTOK * DMODEL];
__device__ __half g_wqh[(size_t)E3 * DMODEL];
__device__ __half g_woh[(size_t)DMODEL*DMODEL];
__device__ __half g_ah[(size_t)NTOK * DMODEL],  g_al[(size_t)NTOK * DMODEL];

// ---------------------------------------------------------------------------
// fp16 hi/lo helpers
// ---------------------------------------------------------------------------
__device__ __forceinline__ void split_store(float4 v, __half* dh, __half* dl)
{
    __half2 h01 = __floats2half2_rn(v.x, v.y);
    __half2 h23 = __floats2half2_rn(v.z, v.w);
    float2 f01 = __half22float2(h01);
    float2 f23 = __half22float2(h23);
    __half2 l01 = __floats2half2_rn(v.x - f01.x, v.y - f01.y);
    __half2 l23 = __floats2half2_rn(v.z - f23.x, v.w - f23.y);
    *(__half2*)&dh[0] = h01;  *(__half2*)&dh[2] = h23;
    *(__half2*)&dl[0] = l01;  *(__half2*)&dl[2] = l23;
}

__device__ __forceinline__ unsigned split_pack(float a, float b, unsigned& lo)
{
    __half2 h = __floats2half2_rn(a, b);
    float2 f = __half22float2(h);
    __half2 l = __floats2half2_rn(a - f.x, b - f.y);
    lo = *reinterpret_cast<unsigned*>(&l);
    return *reinterpret_cast<unsigned*>(&h);
}

__device__ __forceinline__ unsigned pack_h(float a, float b)
{
    __half2 h = __floats2half2_rn(a, b);
    return *reinterpret_cast<unsigned*>(&h);
}

__global__ void cvt_x_kernel(const float* __restrict__ x) {
    int i = blockIdx.x * blockDim.x + threadIdx.x;
    if (i >= NTOK * DMODEL / 4) return;
    split_store(((const float4*)x)[i], g_xh + (size_t)i*4, g_xl + (size_t)i*4);
}
__global__ void cvt_wq_kernel(const float* __restrict__ w) {
    int i = blockIdx.x * blockDim.x + threadIdx.x;
    if (i >= E3 * DMODEL / 4) return;
    float4 v = ((const float4*)w)[i];
    *(__half2*)&g_wqh[(size_t)i*4]     = __floats2half2_rn(v.x, v.y);
    *(__half2*)&g_wqh[(size_t)i*4 + 2] = __floats2half2_rn(v.z, v.w);
}
__global__ void cvt_wo_kernel(const float* __restrict__ w) {
    int i = blockIdx.x * blockDim.x + threadIdx.x;
    if (i >= DMODEL * DMODEL / 4) return;
    float4 v = ((const float4*)w)[i];
    *(__half2*)&g_woh[(size_t)i*4]     = __floats2half2_rn(v.x, v.y);
    *(__half2*)&g_woh[(size_t)i*4 + 2] = __floats2half2_rn(v.z, v.w);
}

// ---------------------------------------------------------------------------
#define MMA16816(d, a, b0, b1)                                                 \
    asm volatile("mma.sync.aligned.m16n8k16.row.col.f32.f16.f16.f32 "          \
                 "{%0,%1,%2,%3}, {%4,%5,%6,%7}, {%8,%9}, {%0,%1,%2,%3};"       \
                 : "+f"(d[0]), "+f"(d[1]), "+f"(d[2]), "+f"(d[3])              \
                 : "r"(a[0]), "r"(a[1]), "r"(a[2]), "r"(a[3]), "r"(b0), "r"(b1))

#define LDSM4(r0, r1, r2, r3, addr)                                            \
    asm volatile("ldmatrix.sync.aligned.m8n8.x4.shared.b16 {%0,%1,%2,%3}, [%4];" \
                 : "=r"(r0), "=r"(r1), "=r"(r2), "=r"(r3) : "r"(addr))

#define CP16(dst_u32, gptr)                                                    \
    asm volatile("cp.async.cg.shared.global [%0], [%1], 16;"                   \
                 :: "r"(dst_u32), "l"(gptr))
#define CP_COMMIT() asm volatile("cp.async.commit_group;" ::: "memory")
#define CP_WAIT1()  asm volatile("cp.async.wait_group 1;" ::: "memory")

// ---------------------------------------------------------------------------
// fp16 (hi/lo A, hi B) tensor-core GEMM: C = A*B^T, fp32 accum, 2-pass.
// R9: incrementing global pointers (no per-chunk 64-bit address recompute).
// ---------------------------------------------------------------------------
#define ARR_HALVES (128*40)
#define STG_HALVES (3*ARR_HALVES)
#define GEMM_SMEM  (3*STG_HALVES*2)   /* 92160 bytes */

template<int M, int N, int K>
__device__ __forceinline__ void gemm_hl_body(const __half* __restrict__ Ah,
                                             const __half* __restrict__ Al,
                                             const __half* __restrict__ Bh,
                                             float* __restrict__ C)
{
    extern __shared__ __half dynsmem[];
    const unsigned sbase = (unsigned)__cvta_generic_to_shared(dynsmem);

    const int tid  = threadIdx.x;
    const int lane = tid & 31;
    const int wid  = tid >> 5;
    const int warpM = wid & 3;
    const int warpN = wid >> 2;
    const int m0 = blockIdx.y * 128;
    const int n0 = blockIdx.x * 128;
    const int g  = lane >> 2;
    const int tg = lane & 3;

    float acc[2][8][4] = {};

    const int r0c = tid >> 2, r1c = (tid + 256) >> 2;
    const int cc  = (tid & 3) << 3;

    // incrementing global pointers (advance 32 halves per chunk)
    const __half* pA0 = &Ah[(size_t)(m0 + r0c) * K + cc];
    const __half* pA1 = &Ah[(size_t)(m0 + r1c) * K + cc];
    const __half* pL0 = &Al[(size_t)(m0 + r0c) * K + cc];
    const __half* pL1 = &Al[(size_t)(m0 + r1c) * K + cc];
    const __half* pB0 = &Bh[(size_t)(n0 + r0c) * K + cc];
    const __half* pB1 = &Bh[(size_t)(n0 + r1c) * K + cc];
    const unsigned d0b = (unsigned)(r0c * 40 + cc) * 2;
    const unsigned d1b = (unsigned)(r1c * 40 + cc) * 2;

    const unsigned lm_off = ((unsigned)((lane & 15) * 40 + ((lane >> 4) << 3))) * 2;
    const unsigned a_base = sbase + (unsigned)(warpM * 32) * 80 + lm_off;
    const unsigned b_base = sbase + (unsigned)(warpN * 64) * 80 + lm_off;

    #define ISSUE(s)                                                            \
        do {                                                                    \
            unsigned sb = sbase + (unsigned)(s) * (STG_HALVES * 2);             \
            CP16(sb + d0b,                    pA0);                             \
            CP16(sb + d1b,                    pA1);                             \
            CP16(sb + d0b + ARR_HALVES*2,     pL0);                             \
            CP16(sb + d1b + ARR_HALVES*2,     pL1);                             \
            CP16(sb + d0b + 2*ARR_HALVES*2,   pB0);                             \
            CP16(sb + d1b + 2*ARR_HALVES*2,   pB1);                             \
            pA0 += 32; pA1 += 32; pL0 += 32; pL1 += 32; pB0 += 32; pB1 += 32;   \
        } while (0)

    const int nch = K / 32;
    ISSUE(0);  CP_COMMIT();
    ISSUE(1);  CP_COMMIT();

    for (int ch = 0; ch < nch; ch++) {
        CP_WAIT1();
        __syncthreads();

        if (ch + 2 < nch) { ISSUE((ch + 2) % 3); }
        CP_COMMIT();

        const unsigned st = (unsigned)(ch % 3) * (STG_HALVES * 2);

        #pragma unroll
        for (int ks = 0; ks < 2; ks++) {
            const unsigned kb2 = (unsigned)(ks * 16) * 2;
            unsigned ah[2][4], al[2][4];
            #pragma unroll
            for (int mi = 0; mi < 2; mi++) {
                unsigned aa = a_base + st + (unsigned)(mi * 16) * 80 + kb2;
                LDSM4(ah[mi][0], ah[mi][1], ah[mi][2], ah[mi][3], aa);
                LDSM4(al[mi][0], al[mi][1], al[mi][2], al[mi][3],
                      aa + ARR_HALVES * 2);
            }
            #pragma unroll
            for (int nip = 0; nip < 4; nip++) {
                unsigned ba = b_base + st + 2*ARR_HALVES*2
                            + (unsigned)(nip * 16) * 80 + kb2;
                unsigned b0e, b0o_, b1e, b1o_;
                LDSM4(b0e, b0o_, b1e, b1o_, ba);
                #pragma unroll
                for (int mi = 0; mi < 2; mi++) {
                    MMA16816(acc[mi][2*nip],   ah[mi], b0e, b1e);
                    MMA16816(acc[mi][2*nip],   al[mi], b0e, b1e);
                    MMA16816(acc[mi][2*nip+1], ah[mi], b0o_, b1o_);
                    MMA16816(acc[mi][2*nip+1], al[mi], b0o_, b1o_);
                }
            }
        }
    }
    #undef ISSUE

    #pragma unroll
    for (int mi = 0; mi < 2; mi++) {
        int r0 = m0 + warpM*32 + mi*16 + g;
        #pragma unroll
        for (int ni = 0; ni < 8; ni++) {
            int c = n0 + warpN*64 + ni*8 + tg*2;
            *(float2*)&C[(size_t)r0 * N + c] =
                make_float2(acc[mi][ni][0], acc[mi][ni][1]);
            *(float2*)&C[(size_t)(r0+8) * N + c] =
                make_float2(acc[mi][ni][2], acc[mi][ni][3]);
        }
    }
}

__global__ __launch_bounds__(256, 2)
void qkv_gemm_kernel() {
    gemm_hl_body<NTOK, E3, DMODEL>(g_xh, g_xl, g_wqh, g_qkv);
}
__global__ __launch_bounds__(256, 2)
void out_gemm_kernel(float* __restrict__ out) {
    gemm_hl_body<NTOK, DMODEL, DMODEL>(g_ah, g_al, g_woh, out);
}

// ---------------------------------------------------------------------------
// RoPE applied in-place to Q and K halves of g_qkv (unchanged, known-good).
// ---------------------------------------------------------------------------
__global__ void rope_kernel(const int* __restrict__ pos)
{
    int t = blockIdx.x * blockDim.x + threadIdx.x;
    const int total = NTOK * NHEADS * (DK / 2);
    if (t >= total) return;

    int i = t & 31;
    int h = (t >> 5) & (NHEADS - 1);
    int n = t >> 9;
    int s = n & (SEQ - 1);

    float p = (float)pos[s];
    float inv = expf(-((float)i / 32.0f) * 9.2103403719761836f);
    float ang = p * inv;
    float sn, cs;
    sincosf(ang, &sn, &cs);

    float* q = &g_qkv[(size_t)n * E3 + h * DK + 2 * i];
    float q1 = q[0], q2 = q[1];
    q[0] = q1 * cs - q2 * sn;
    q[1] = q1 * sn + q2 * cs;

    float* k = q + DMODEL;
    float k1 = k[0], k2 = k[1];
    k[0] = k1 * cs - k2 * sn;
    k[1] = k1 * sn + k2 * cs;
}

// ---------------------------------------------------------------------------
// Causal flash attention, fp16 hi/lo tensor cores.
// R9: each block processes the q-tile PAIR (bx, NTQ-1-bx) -> uniform work
// (34 half-tiles per block), grid.x = NTQ/2. Softmax in log2 domain (exp2f,
// log2e folded into scale).
// ---------------------------------------------------------------------------
__global__ __launch_bounds__(256)
void attn_mma_kernel()
{
    const int h   = blockIdx.y;
    const int b   = blockIdx.z;
    const int tid = threadIdx.x;
    const int lane = tid & 31;
    const int w   = tid >> 5;
    const int g   = lane >> 2;
    const int tg  = lane & 3;

    __shared__ __half sKh[2][64*72], sVh[2][64*72], sVl[2][64*72];

    const float scale = 0.125f * 1.44269504088896f;   // 1/sqrt(64) * log2(e)

    float4 pk[4], pv[4];

    #define GLT(kt_)                                                           \
        _Pragma("unroll")                                                      \
        for (int i = 0; i < 4; i++) {                                          \
            int idx = tid + i*256;                                             \
            int r = idx >> 4, c4 = (idx & 15) << 2;                            \
            size_t base = ((size_t)(b*SEQ) + (kt_)*64 + r)*E3 + h*DK + c4;     \
            pk[i] = *(const float4*)&g_qkv[base + DMODEL];                     \
            pv[i] = *(const float4*)&g_qkv[base + 2*DMODEL];                   \
        }

    #define STS_T(buf_)                                                        \
        _Pragma("unroll")                                                      \
        for (int i = 0; i < 4; i++) {                                          \
            int idx = tid + i*256;                                             \
            int r = idx >> 4, c4 = (idx & 15) << 2;                            \
            *(unsigned*)&sKh[buf_][r*72 + c4]     = pack_h(pk[i].x, pk[i].y);  \
            *(unsigned*)&sKh[buf_][r*72 + c4 + 2] = pack_h(pk[i].z, pk[i].w);  \
            float vf[4] = {pv[i].x, pv[i].y, pv[i].z, pv[i].w};                \
            _Pragma("unroll")                                                  \
            for (int j = 0; j < 4; j++) {                                      \
                __half vh = __float2half_rn(vf[j]);                            \
                __half vl = __float2half_rn(vf[j] - __half2float(vh));         \
                sVh[buf_][(c4+j)*72 + r] = vh;                                 \
                sVl[buf_][(c4+j)*72 + r] = vl;                                 \
            }                                                                  \
        }

    #pragma unroll 1
    for (int half = 0; half < 2; half++) {
        const int qt = half ? (NTQ - 1 - blockIdx.x) : blockIdx.x;
        const int qbase = qt * 128;
        const int row0 = qbase + w*16 + g;
        const int row1 = row0 + 8;
        const int wrowmax = qbase + w*16 + 15;

        unsigned qh[4][4], ql[4][4];
        {
            const float* q0 = &g_qkv[((size_t)(b*SEQ) + row0)*E3 + h*DK];
            const float* q1 = &g_qkv[((size_t)(b*SEQ) + row1)*E3 + h*DK];
            #pragma unroll
            for (int kk = 0; kk < 4; kk++) {
                int d0 = kk*16 + 2*tg;
                float2 a0 = *(const float2*)&q0[d0];
                float2 a1 = *(const float2*)&q1[d0];
                float2 a2 = *(const float2*)&q0[d0+8];
                float2 a3 = *(const float2*)&q1[d0+8];
                qh[kk][0] = split_pack(a0.x*scale, a0.y*scale, ql[kk][0]);
                qh[kk][1] = split_pack(a1.x*scale, a1.y*scale, ql[kk][1]);
                qh[kk][2] = split_pack(a2.x*scale, a2.y*scale, ql[kk][2]);
                qh[kk][3] = split_pack(a3.x*scale, a3.y*scale, ql[kk][3]);
            }
        }

        float o[8][4] = {};
        float m0 = -1e30f, m1 = -1e30f, l0 = 0.f, l1 = 0.f;

        const int ntiles = 2*qt + 2;

        GLT(0);
        STS_T(0);
        __syncthreads();

        for (int kt = 0; kt < ntiles; kt++) {
            const int kvbase = kt * 64;
            const int buf = kt & 1;

            if (kt + 1 < ntiles) { GLT(kt + 1); }

            if (kvbase <= wrowmax) {
                float sc[8][4] = {};

                #pragma unroll
                for (int kk = 0; kk < 4; kk++) {
                    int ko = kk*16 + 2*tg;
                    #pragma unroll
                    for (int ni = 0; ni < 8; ni++) {
                        int rb = (ni*8 + g)*72 + ko;
                        unsigned b0h = *(const unsigned*)&sKh[buf][rb];
                        unsigned b1h = *(const unsigned*)&sKh[buf][rb + 8];
                        MMA16816(sc[ni], qh[kk], b0h, b1h);
                        MMA16816(sc[ni], ql[kk], b0h, b1h);
                    }
                }

                if (kvbase + 63 > row0) {
                    #pragma unroll
                    for (int ni = 0; ni < 8; ni++) {
                        int c = kvbase + ni*8 + 2*tg;
                        if (c     > row0) sc[ni][0] = -1e30f;
                        if (c + 1 > row0) sc[ni][1] = -1e30f;
                        if (c     > row1) sc[ni][2] = -1e30f;
                        if (c + 1 > row1) sc[ni][3] = -1e30f;
                    }
                }

                float t0 = -1e30f, t1 = -1e30f;
                #pragma unroll
                for (int ni = 0; ni < 8; ni++) {
                    t0 = fmaxf(t0, fmaxf(sc[ni][0], sc[ni][1]));
                    t1 = fmaxf(t1, fmaxf(sc[ni][2], sc[ni][3]));
                }
                t0 = fmaxf(t0, __shfl_xor_sync(0xffffffffu, t0, 1));
                t0 = fmaxf(t0, __shfl_xor_sync(0xffffffffu, t0, 2));
                t1 = fmaxf(t1, __shfl_xor_sync(0xffffffffu, t1, 1));
                t1 = fmaxf(t1, __shfl_xor_sync(0xffffffffu, t1, 2));

                float m0n = fmaxf(m0, t0), m1n = fmaxf(m1, t1);
                float c0 = exp2f(m0 - m0n), c1 = exp2f(m1 - m1n);
                m0 = m0n; m1 = m1n;
                l0 *= c0;  l1 *= c1;
                #pragma unroll
                for (int ni = 0; ni < 8; ni++) {
                    o[ni][0] *= c0; o[ni][1] *= c0;
                    o[ni][2] *= c1; o[ni][3] *= c1;
                }

                #pragma unroll
                for (int ni = 0; ni < 8; ni++) {
                    sc[ni][0] = exp2f(sc[ni][0] - m0);
                    sc[ni][1] = exp2f(sc[ni][1] - m0);
                    sc[ni][2] = exp2f(sc[ni][2] - m1);
                    sc[ni][3] = exp2f(sc[ni][3] - m1);
                    l0 += sc[ni][0] + sc[ni][1];
                    l1 += sc[ni][2] + sc[ni][3];
                }

                #pragma unroll
                for (int kk = 0; kk < 4; kk++) {
                    unsigned ph[4];
                    ph[0] = pack_h(sc[2*kk][0],   sc[2*kk][1]);
                    ph[1] = pack_h(sc[2*kk][2],   sc[2*kk][3]);
                    ph[2] = pack_h(sc[2*kk+1][0], sc[2*kk+1][1]);
                    ph[3] = pack_h(sc[2*kk+1][2], sc[2*kk+1][3]);
                    int ko = kk*16 + 2*tg;
                    #pragma unroll
                    for (int nd = 0; nd < 8; nd++) {
                        int rb = (nd*8 + g)*72 + ko;
                        unsigned b0h = *(const unsigned*)&sVh[buf][rb];
                        unsigned b1h = *(const unsigned*)&sVh[buf][rb + 8];
                        unsigned b0l = *(const unsigned*)&sVl[buf][rb];
                        unsigned b1l = *(const unsigned*)&sVl[buf][rb + 8];
                        MMA16816(o[nd], ph, b0h, b1h);
                        MMA16816(o[nd], ph, b0l, b1l);
                    }
                }
            }

            if (kt + 1 < ntiles) { STS_T(buf ^ 1); }
            __syncthreads();
        }

        l0 += __shfl_xor_sync(0xffffffffu, l0, 1);
        l0 += __shfl_xor_sync(0xffffffffu, l0, 2);
        l1 += __shfl_xor_sync(0xffffffffu, l1, 1);
        l1 += __shfl_xor_sync(0xffffffffu, l1, 2);
        float inv0 = 1.f / l0, inv1 = 1.f / l1;

        size_t base0 = ((size_t)(b*SEQ) + row0)*DMODEL + h*DK;
        size_t base1 = ((size_t)(b*SEQ) + row1)*DMODEL + h*DK;
        #pragma unroll
        for (int nd = 0; nd < 8; nd++) {
            int c = nd*8 + 2*tg;
            unsigned lo;
            unsigned hi = split_pack(o[nd][0]*inv0, o[nd][1]*inv0, lo);
            *(unsigned*)&g_ah[base0 + c] = hi;
            *(unsigned*)&g_al[base0 + c] = lo;
            hi = split_pack(o[nd][2]*inv1, o[nd][3]*inv1, lo);
            *(unsigned*)&g_ah[base1 + c] = hi;
            *(unsigned*)&g_al[base1 + c] = lo;
        }
    }
    #undef GLT
    #undef STS_T
}

// ---------------------------------------------------------------------------
extern "C" void kernel_launch(void* const* d_in, const int* in_sizes, int n_in,
                              void* d_out, int out_size)
{
    const float* x      = (const float*)d_in[0];
    const int*   pos    = (const int*)d_in[1];
    const float* w_qkv  = (const float*)d_in[2];
    const float* w_o    = (const float*)d_in[3];
    float*       out    = (float*)d_out;

    cudaFuncSetAttribute(qkv_gemm_kernel,
                         cudaFuncAttributeMaxDynamicSharedMemorySize, GEMM_SMEM);
    cudaFuncSetAttribute(out_gemm_kernel,
                         cudaFuncAttributeMaxDynamicSharedMemorySize, GEMM_SMEM);

    // 0) fp16 splits (x hi/lo; weights hi only)
    cvt_x_kernel <<<(NTOK*DMODEL/4 + 255)/256, 256>>>(x);
    cvt_wq_kernel<<<(E3*DMODEL/4   + 255)/256, 256>>>(w_qkv);
    cvt_wo_kernel<<<(DMODEL*DMODEL/4 + 255)/256, 256>>>(w_o);

    // 1) QKV projection
    {
        dim3 grid(E3 / 128, NTOK / 128);
        qkv_gemm_kernel<<<grid, 256, GEMM_SMEM>>>();
    }
    // 2) RoPE
    {
        int total = NTOK * NHEADS * (DK / 2);
        rope_kernel<<<(total + 255) / 256, 256>>>(pos);
    }
    // 3) Causal flash attention (paired q-tiles, uniform work per block)
    {
        dim3 grid(NTQ / 2, NHEADS, BATCH);
        attn_mma_kernel<<<grid, 256>>>();
    }
    // 4) Output projection
    {
        dim3 grid(DMODEL / 128, NTOK / 128);
        out_gemm_kernel<<<grid, 256, GEMM_SMEM>>>(out);
    }
}

// round 11
// speedup vs baseline: 5.1893x; 1.3309x over previous
#include <cuda_runtime.h>
#include <cuda_fp16.h>
#include <math.h>

#define BATCH   2
#define SEQ     2048
#define DMODEL  1024
#define NHEADS  16
#define DK      64
#define NTOK    (BATCH*SEQ)      /* 4096 */
#define E3      (3*DMODEL)       /* 3072 */
#define NTQ     (SEQ/128)        /* 16 q-tiles */

// Scratch (allocation-free rule: __device__ globals)
__device__ float  g_qkv[(size_t)NTOK * E3];
__device__ __half g_xh[(size_t)NTOK * DMODEL];
__device__ __half g_wqh[(size_t)E3 * DMODEL];
__device__ __half g_woh[(size_t)DMODEL*DMODEL];
__device__ __half g_ah[(size_t)NTOK * DMODEL];

// ---------------------------------------------------------------------------
// fp16 helpers
// ---------------------------------------------------------------------------
__device__ __forceinline__ unsigned split_pack(float a, float b, unsigned& lo)
{
    __half2 h = __floats2half2_rn(a, b);
    float2 f = __half22float2(h);
    __half2 l = __floats2half2_rn(a - f.x, b - f.y);
    lo = *reinterpret_cast<unsigned*>(&l);
    return *reinterpret_cast<unsigned*>(&h);
}

__device__ __forceinline__ unsigned pack_h(float a, float b)
{
    __half2 h = __floats2half2_rn(a, b);
    return *reinterpret_cast<unsigned*>(&h);
}

__global__ void cvt_x_kernel(const float* __restrict__ x) {
    int i = blockIdx.x * blockDim.x + threadIdx.x;
    if (i >= NTOK * DMODEL / 4) return;
    float4 v = ((const float4*)x)[i];
    *(__half2*)&g_xh[(size_t)i*4]     = __floats2half2_rn(v.x, v.y);
    *(__half2*)&g_xh[(size_t)i*4 + 2] = __floats2half2_rn(v.z, v.w);
}
__global__ void cvt_wq_kernel(const float* __restrict__ w) {
    int i = blockIdx.x * blockDim.x + threadIdx.x;
    if (i >= E3 * DMODEL / 4) return;
    float4 v = ((const float4*)w)[i];
    *(__half2*)&g_wqh[(size_t)i*4]     = __floats2half2_rn(v.x, v.y);
    *(__half2*)&g_wqh[(size_t)i*4 + 2] = __floats2half2_rn(v.z, v.w);
}
__global__ void cvt_wo_kernel(const float* __restrict__ w) {
    int i = blockIdx.x * blockDim.x + threadIdx.x;
    if (i >= DMODEL * DMODEL / 4) return;
    float4 v = ((const float4*)w)[i];
    *(__half2*)&g_woh[(size_t)i*4]     = __floats2half2_rn(v.x, v.y);
    *(__half2*)&g_woh[(size_t)i*4 + 2] = __floats2half2_rn(v.z, v.w);
}

// ---------------------------------------------------------------------------
#define MMA16816(d, a, b0, b1)                                                 \
    asm volatile("mma.sync.aligned.m16n8k16.row.col.f32.f16.f16.f32 "          \
                 "{%0,%1,%2,%3}, {%4,%5,%6,%7}, {%8,%9}, {%0,%1,%2,%3};"       \
                 : "+f"(d[0]), "+f"(d[1]), "+f"(d[2]), "+f"(d[3])              \
                 : "r"(a[0]), "r"(a[1]), "r"(a[2]), "r"(a[3]), "r"(b0), "r"(b1))

#define LDSM4(r0, r1, r2, r3, addr)                                            \
    asm volatile("ldmatrix.sync.aligned.m8n8.x4.shared.b16 {%0,%1,%2,%3}, [%4];" \
                 : "=r"(r0), "=r"(r1), "=r"(r2), "=r"(r3) : "r"(addr))

#define CP16(dst_u32, gptr)                                                    \
    asm volatile("cp.async.cg.shared.global [%0], [%1], 16;"                   \
                 :: "r"(dst_u32), "l"(gptr))
#define CP_COMMIT() asm volatile("cp.async.commit_group;" ::: "memory")
#define CP_WAIT1()  asm volatile("cp.async.wait_group 1;" ::: "memory")

// ---------------------------------------------------------------------------
// fp16 tensor-core GEMM: C = A*B^T, fp32 accum, single-pass (Ah x Bh).
// 3-stage cp.async pipeline, ldmatrix.x4 fragment loads, 128x128x32 tiles.
// ---------------------------------------------------------------------------
#define ARR_HALVES (128*40)
#define STG_HALVES (2*ARR_HALVES)
#define GEMM_SMEM  (3*STG_HALVES*2)   /* 61440 bytes */

template<int M, int N, int K>
__device__ __forceinline__ void gemm_h_body(const __half* __restrict__ Ah,
                                            const __half* __restrict__ Bh,
                                            float* __restrict__ C)
{
    extern __shared__ __half dynsmem[];
    const unsigned sbase = (unsigned)__cvta_generic_to_shared(dynsmem);

    const int tid  = threadIdx.x;
    const int lane = tid & 31;
    const int wid  = tid >> 5;
    const int warpM = wid & 3;
    const int warpN = wid >> 2;
    const int m0 = blockIdx.y * 128;
    const int n0 = blockIdx.x * 128;
    const int g  = lane >> 2;
    const int tg = lane & 3;

    float acc[2][8][4] = {};

    const int r0c = tid >> 2, r1c = (tid + 256) >> 2;
    const int cc  = (tid & 3) << 3;

    const __half* pA0 = &Ah[(size_t)(m0 + r0c) * K + cc];
    const __half* pA1 = &Ah[(size_t)(m0 + r1c) * K + cc];
    const __half* pB0 = &Bh[(size_t)(n0 + r0c) * K + cc];
    const __half* pB1 = &Bh[(size_t)(n0 + r1c) * K + cc];
    const unsigned d0b = (unsigned)(r0c * 40 + cc) * 2;
    const unsigned d1b = (unsigned)(r1c * 40 + cc) * 2;

    const unsigned lm_off = ((unsigned)((lane & 15) * 40 + ((lane >> 4) << 3))) * 2;
    const unsigned a_base = sbase + (unsigned)(warpM * 32) * 80 + lm_off;
    const unsigned b_base = sbase + (unsigned)(warpN * 64) * 80 + lm_off;

    #define ISSUE(s)                                                            \
        do {                                                                    \
            unsigned sb = sbase + (unsigned)(s) * (STG_HALVES * 2);             \
            CP16(sb + d0b,                  pA0);                               \
            CP16(sb + d1b,                  pA1);                               \
            CP16(sb + d0b + ARR_HALVES*2,   pB0);                               \
            CP16(sb + d1b + ARR_HALVES*2,   pB1);                               \
            pA0 += 32; pA1 += 32; pB0 += 32; pB1 += 32;                         \
        } while (0)

    const int nch = K / 32;
    ISSUE(0);  CP_COMMIT();
    ISSUE(1);  CP_COMMIT();

    for (int ch = 0; ch < nch; ch++) {
        CP_WAIT1();
        __syncthreads();

        if (ch + 2 < nch) { ISSUE((ch + 2) % 3); }
        CP_COMMIT();

        const unsigned st = (unsigned)(ch % 3) * (STG_HALVES * 2);

        #pragma unroll
        for (int ks = 0; ks < 2; ks++) {
            const unsigned kb2 = (unsigned)(ks * 16) * 2;
            unsigned ah[2][4];
            #pragma unroll
            for (int mi = 0; mi < 2; mi++) {
                unsigned aa = a_base + st + (unsigned)(mi * 16) * 80 + kb2;
                LDSM4(ah[mi][0], ah[mi][1], ah[mi][2], ah[mi][3], aa);
            }
            #pragma unroll
            for (int nip = 0; nip < 4; nip++) {
                unsigned ba = b_base + st + ARR_HALVES*2
                            + (unsigned)(nip * 16) * 80 + kb2;
                unsigned b0e, b0o_, b1e, b1o_;
                LDSM4(b0e, b0o_, b1e, b1o_, ba);
                #pragma unroll
                for (int mi = 0; mi < 2; mi++) {
                    MMA16816(acc[mi][2*nip],   ah[mi], b0e, b1e);
                    MMA16816(acc[mi][2*nip+1], ah[mi], b0o_, b1o_);
                }
            }
        }
    }
    #undef ISSUE

    #pragma unroll
    for (int mi = 0; mi < 2; mi++) {
        int r0 = m0 + warpM*32 + mi*16 + g;
        #pragma unroll
        for (int ni = 0; ni < 8; ni++) {
            int c = n0 + warpN*64 + ni*8 + tg*2;
            *(float2*)&C[(size_t)r0 * N + c] =
                make_float2(acc[mi][ni][0], acc[mi][ni][1]);
            *(float2*)&C[(size_t)(r0+8) * N + c] =
                make_float2(acc[mi][ni][2], acc[mi][ni][3]);
        }
    }
}

__global__ __launch_bounds__(256, 2)
void qkv_gemm_kernel() {
    gemm_h_body<NTOK, E3, DMODEL>(g_xh, g_wqh, g_qkv);
}
__global__ __launch_bounds__(256, 2)
void out_gemm_kernel(float* __restrict__ out) {
    gemm_h_body<NTOK, DMODEL, DMODEL>(g_ah, g_woh, out);
}

// ---------------------------------------------------------------------------
// RoPE applied in-place to Q and K halves of g_qkv (unchanged, known-good).
// ---------------------------------------------------------------------------
__global__ void rope_kernel(const int* __restrict__ pos)
{
    int t = blockIdx.x * blockDim.x + threadIdx.x;
    const int total = NTOK * NHEADS * (DK / 2);
    if (t >= total) return;

    int i = t & 31;
    int h = (t >> 5) & (NHEADS - 1);
    int n = t >> 9;
    int s = n & (SEQ - 1);

    float p = (float)pos[s];
    float inv = expf(-((float)i / 32.0f) * 9.2103403719761836f);
    float ang = p * inv;
    float sn, cs;
    sincosf(ang, &sn, &cs);

    float* q = &g_qkv[(size_t)n * E3 + h * DK + 2 * i];
    float q1 = q[0], q2 = q[1];
    q[0] = q1 * cs - q2 * sn;
    q[1] = q1 * sn + q2 * cs;

    float* k = q + DMODEL;
    float k1 = k[0], k2 = k[1];
    k[0] = k1 * cs - k2 * sn;
    k[1] = k1 * sn + k2 * cs;
}

// ---------------------------------------------------------------------------
// Causal flash attention, fp16 hi/lo tensor cores (paired q-tiles, exp2).
// Epilogue writes fp16 hi only (out GEMM is 1-pass now).
// ---------------------------------------------------------------------------
__global__ __launch_bounds__(256)
void attn_mma_kernel()
{
    const int h   = blockIdx.y;
    const int b   = blockIdx.z;
    const int tid = threadIdx.x;
    const int lane = tid & 31;
    const int w   = tid >> 5;
    const int g   = lane >> 2;
    const int tg  = lane & 3;

    __shared__ __half sKh[2][64*72], sVh[2][64*72], sVl[2][64*72];

    const float scale = 0.125f * 1.44269504088896f;   // 1/sqrt(64) * log2(e)

    float4 pk[4], pv[4];

    #define GLT(kt_)                                                           \
        _Pragma("unroll")                                                      \
        for (int i = 0; i < 4; i++) {                                          \
            int idx = tid + i*256;                                             \
            int r = idx >> 4, c4 = (idx & 15) << 2;                            \
            size_t base = ((size_t)(b*SEQ) + (kt_)*64 + r)*E3 + h*DK + c4;     \
            pk[i] = *(const float4*)&g_qkv[base + DMODEL];                     \
            pv[i] = *(const float4*)&g_qkv[base + 2*DMODEL];                   \
        }

    #define STS_T(buf_)                                                        \
        _Pragma("unroll")                                                      \
        for (int i = 0; i < 4; i++) {                                          \
            int idx = tid + i*256;                                             \
            int r = idx >> 4, c4 = (idx & 15) << 2;                            \
            *(unsigned*)&sKh[buf_][r*72 + c4]     = pack_h(pk[i].x, pk[i].y);  \
            *(unsigned*)&sKh[buf_][r*72 + c4 + 2] = pack_h(pk[i].z, pk[i].w);  \
            float vf[4] = {pv[i].x, pv[i].y, pv[i].z, pv[i].w};                \
            _Pragma("unroll")                                                  \
            for (int j = 0; j < 4; j++) {                                      \
                __half vh = __float2half_rn(vf[j]);                            \
                __half vl = __float2half_rn(vf[j] - __half2float(vh));         \
                sVh[buf_][(c4+j)*72 + r] = vh;                                 \
                sVl[buf_][(c4+j)*72 + r] = vl;                                 \
            }                                                                  \
        }

    #pragma unroll 1
    for (int half = 0; half < 2; half++) {
        const int qt = half ? (NTQ - 1 - blockIdx.x) : blockIdx.x;
        const int qbase = qt * 128;
        const int row0 = qbase + w*16 + g;
        const int row1 = row0 + 8;
        const int wrowmax = qbase + w*16 + 15;

        unsigned qh[4][4], ql[4][4];
        {
            const float* q0 = &g_qkv[((size_t)(b*SEQ) + row0)*E3 + h*DK];
            const float* q1 = &g_qkv[((size_t)(b*SEQ) + row1)*E3 + h*DK];
            #pragma unroll
            for (int kk = 0; kk < 4; kk++) {
                int d0 = kk*16 + 2*tg;
                float2 a0 = *(const float2*)&q0[d0];
                float2 a1 = *(const float2*)&q1[d0];
                float2 a2 = *(const float2*)&q0[d0+8];
                float2 a3 = *(const float2*)&q1[d0+8];
                qh[kk][0] = split_pack(a0.x*scale, a0.y*scale, ql[kk][0]);
                qh[kk][1] = split_pack(a1.x*scale, a1.y*scale, ql[kk][1]);
                qh[kk][2] = split_pack(a2.x*scale, a2.y*scale, ql[kk][2]);
                qh[kk][3] = split_pack(a3.x*scale, a3.y*scale, ql[kk][3]);
            }
        }

        float o[8][4] = {};
        float m0 = -1e30f, m1 = -1e30f, l0 = 0.f, l1 = 0.f;

        const int ntiles = 2*qt + 2;

        GLT(0);
        STS_T(0);
        __syncthreads();

        for (int kt = 0; kt < ntiles; kt++) {
            const int kvbase = kt * 64;
            const int buf = kt & 1;

            if (kt + 1 < ntiles) { GLT(kt + 1); }

            if (kvbase <= wrowmax) {
                float sc[8][4] = {};

                #pragma unroll
                for (int kk = 0; kk < 4; kk++) {
                    int ko = kk*16 + 2*tg;
                    #pragma unroll
                    for (int ni = 0; ni < 8; ni++) {
                        int rb = (ni*8 + g)*72 + ko;
                        unsigned b0h = *(const unsigned*)&sKh[buf][rb];
                        unsigned b1h = *(const unsigned*)&sKh[buf][rb + 8];
                        MMA16816(sc[ni], qh[kk], b0h, b1h);
                        MMA16816(sc[ni], ql[kk], b0h, b1h);
                    }
                }

                if (kvbase + 63 > row0) {
                    #pragma unroll
                    for (int ni = 0; ni < 8; ni++) {
                        int c = kvbase + ni*8 + 2*tg;
                        if (c     > row0) sc[ni][0] = -1e30f;
                        if (c + 1 > row0) sc[ni][1] = -1e30f;
                        if (c     > row1) sc[ni][2] = -1e30f;
                        if (c + 1 > row1) sc[ni][3] = -1e30f;
                    }
                }

                float t0 = -1e30f, t1 = -1e30f;
                #pragma unroll
                for (int ni = 0; ni < 8; ni++) {
                    t0 = fmaxf(t0, fmaxf(sc[ni][0], sc[ni][1]));
                    t1 = fmaxf(t1, fmaxf(sc[ni][2], sc[ni][3]));
                }
                t0 = fmaxf(t0, __shfl_xor_sync(0xffffffffu, t0, 1));
                t0 = fmaxf(t0, __shfl_xor_sync(0xffffffffu, t0, 2));
                t1 = fmaxf(t1, __shfl_xor_sync(0xffffffffu, t1, 1));
                t1 = fmaxf(t1, __shfl_xor_sync(0xffffffffu, t1, 2));

                float m0n = fmaxf(m0, t0), m1n = fmaxf(m1, t1);
                float c0 = exp2f(m0 - m0n), c1 = exp2f(m1 - m1n);
                m0 = m0n; m1 = m1n;
                l0 *= c0;  l1 *= c1;
                #pragma unroll
                for (int ni = 0; ni < 8; ni++) {
                    o[ni][0] *= c0; o[ni][1] *= c0;
                    o[ni][2] *= c1; o[ni][3] *= c1;
                }

                #pragma unroll
                for (int ni = 0; ni < 8; ni++) {
                    sc[ni][0] = exp2f(sc[ni][0] - m0);
                    sc[ni][1] = exp2f(sc[ni][1] - m0);
                    sc[ni][2] = exp2f(sc[ni][2] - m1);
                    sc[ni][3] = exp2f(sc[ni][3] - m1);
                    l0 += sc[ni][0] + sc[ni][1];
                    l1 += sc[ni][2] + sc[ni][3];
                }

                #pragma unroll
                for (int kk = 0; kk < 4; kk++) {
                    unsigned ph[4];
                    ph[0] = pack_h(sc[2*kk][0],   sc[2*kk][1]);
                    ph[1] = pack_h(sc[2*kk][2],   sc[2*kk][3]);
                    ph[2] = pack_h(sc[2*kk+1][0], sc[2*kk+1][1]);
                    ph[3] = pack_h(sc[2*kk+1][2], sc[2*kk+1][3]);
                    int ko = kk*16 + 2*tg;
                    #pragma unroll
                    for (int nd = 0; nd < 8; nd++) {
                        int rb = (nd*8 + g)*72 + ko;
                        unsigned b0h = *(const unsigned*)&sVh[buf][rb];
                        unsigned b1h = *(const unsigned*)&sVh[buf][rb + 8];
                        unsigned b0l = *(const unsigned*)&sVl[buf][rb];
                        unsigned b1l = *(const unsigned*)&sVl[buf][rb + 8];
                        MMA16816(o[nd], ph, b0h, b1h);
                        MMA16816(o[nd], ph, b0l, b1l);
                    }
                }
            }

            if (kt + 1 < ntiles) { STS_T(buf ^ 1); }
            __syncthreads();
        }

        l0 += __shfl_xor_sync(0xffffffffu, l0, 1);
        l0 += __shfl_xor_sync(0xffffffffu, l0, 2);
        l1 += __shfl_xor_sync(0xffffffffu, l1, 1);
        l1 += __shfl_xor_sync(0xffffffffu, l1, 2);
        float inv0 = 1.f / l0, inv1 = 1.f / l1;

        size_t base0 = ((size_t)(b*SEQ) + row0)*DMODEL + h*DK;
        size_t base1 = ((size_t)(b*SEQ) + row1)*DMODEL + h*DK;
        #pragma unroll
        for (int nd = 0; nd < 8; nd++) {
            int c = nd*8 + 2*tg;
            *(unsigned*)&g_ah[base0 + c] = pack_h(o[nd][0]*inv0, o[nd][1]*inv0);
            *(unsigned*)&g_ah[base1 + c] = pack_h(o[nd][2]*inv1, o[nd][3]*inv1);
        }
    }
    #undef GLT
    #undef STS_T
}

// ---------------------------------------------------------------------------
extern "C" void kernel_launch(void* const* d_in, const int* in_sizes, int n_in,
                              void* d_out, int out_size)
{
    const float* x      = (const float*)d_in[0];
    const int*   pos    = (const int*)d_in[1];
    const float* w_qkv  = (const float*)d_in[2];
    const float* w_o    = (const float*)d_in[3];
    float*       out    = (float*)d_out;

    cudaFuncSetAttribute(qkv_gemm_kernel,
                         cudaFuncAttributeMaxDynamicSharedMemorySize, GEMM_SMEM);
    cudaFuncSetAttribute(out_gemm_kernel,
                         cudaFuncAttributeMaxDynamicSharedMemorySize, GEMM_SMEM);

    // 0) fp16 converts
    cvt_x_kernel <<<(NTOK*DMODEL/4 + 255)/256, 256>>>(x);
    cvt_wq_kernel<<<(E3*DMODEL/4   + 255)/256, 256>>>(w_qkv);
    cvt_wo_kernel<<<(DMODEL*DMODEL/4 + 255)/256, 256>>>(w_o);

    // 1) QKV projection (1-pass fp16)
    {
        dim3 grid(E3 / 128, NTOK / 128);
        qkv_gemm_kernel<<<grid, 256, GEMM_SMEM>>>();
    }
    // 2) RoPE
    {
        int total = NTOK * NHEADS * (DK / 2);
        rope_kernel<<<(total + 255) / 256, 256>>>(pos);
    }
    // 3) Causal flash attention (paired q-tiles)
    {
        dim3 grid(NTQ / 2, NHEADS, BATCH);
        attn_mma_kernel<<<grid, 256>>>();
    }
    // 4) Output projection (1-pass fp16)
    {
        dim3 grid(DMODEL / 128, NTOK / 128);
        out_gemm_kernel<<<grid, 256, GEMM_SMEM>>>(out);
    }
}

// round 12
// speedup vs baseline: 6.0704x; 1.1698x over previous
#include <cuda_runtime.h>
#include <cuda_fp16.h>
#include <math.h>

#define BATCH   2
#define SEQ     2048
#define DMODEL  1024
#define NHEADS  16
#define DK      64
#define NTOK    (BATCH*SEQ)      /* 4096 */
#define E3      (3*DMODEL)       /* 3072 */
#define NTQ     (SEQ/128)        /* 16 q-tiles */

// Scratch (allocation-free rule: __device__ globals)
__device__ float  g_qkv[(size_t)NTOK * E3];
__device__ __half g_xh[(size_t)NTOK * DMODEL];
__device__ __half g_wqh[(size_t)E3 * DMODEL];
__device__ __half g_woh[(size_t)DMODEL*DMODEL];
__device__ __half g_ah[(size_t)NTOK * DMODEL];

// ---------------------------------------------------------------------------
// fp16 helpers
// ---------------------------------------------------------------------------
__device__ __forceinline__ unsigned split_pack(float a, float b, unsigned& lo)
{
    __half2 h = __floats2half2_rn(a, b);
    float2 f = __half22float2(h);
    __half2 l = __floats2half2_rn(a - f.x, b - f.y);
    lo = *reinterpret_cast<unsigned*>(&l);
    return *reinterpret_cast<unsigned*>(&h);
}

__device__ __forceinline__ unsigned pack_h(float a, float b)
{
    __half2 h = __floats2half2_rn(a, b);
    return *reinterpret_cast<unsigned*>(&h);
}

__global__ void cvt_x_kernel(const float* __restrict__ x) {
    int i = blockIdx.x * blockDim.x + threadIdx.x;
    if (i >= NTOK * DMODEL / 4) return;
    float4 v = ((const float4*)x)[i];
    *(__half2*)&g_xh[(size_t)i*4]     = __floats2half2_rn(v.x, v.y);
    *(__half2*)&g_xh[(size_t)i*4 + 2] = __floats2half2_rn(v.z, v.w);
}
__global__ void cvt_wq_kernel(const float* __restrict__ w) {
    int i = blockIdx.x * blockDim.x + threadIdx.x;
    if (i >= E3 * DMODEL / 4) return;
    float4 v = ((const float4*)w)[i];
    *(__half2*)&g_wqh[(size_t)i*4]     = __floats2half2_rn(v.x, v.y);
    *(__half2*)&g_wqh[(size_t)i*4 + 2] = __floats2half2_rn(v.z, v.w);
}
__global__ void cvt_wo_kernel(const float* __restrict__ w) {
    int i = blockIdx.x * blockDim.x + threadIdx.x;
    if (i >= DMODEL * DMODEL / 4) return;
    float4 v = ((const float4*)w)[i];
    *(__half2*)&g_woh[(size_t)i*4]     = __floats2half2_rn(v.x, v.y);
    *(__half2*)&g_woh[(size_t)i*4 + 2] = __floats2half2_rn(v.z, v.w);
}

// ---------------------------------------------------------------------------
#define MMA16816(d, a, b0, b1)                                                 \
    asm volatile("mma.sync.aligned.m16n8k16.row.col.f32.f16.f16.f32 "          \
                 "{%0,%1,%2,%3}, {%4,%5,%6,%7}, {%8,%9}, {%0,%1,%2,%3};"       \
                 : "+f"(d[0]), "+f"(d[1]), "+f"(d[2]), "+f"(d[3])              \
                 : "r"(a[0]), "r"(a[1]), "r"(a[2]), "r"(a[3]), "r"(b0), "r"(b1))

#define LDSM4(r0, r1, r2, r3, addr)                                            \
    asm volatile("ldmatrix.sync.aligned.m8n8.x4.shared.b16 {%0,%1,%2,%3}, [%4];" \
                 : "=r"(r0), "=r"(r1), "=r"(r2), "=r"(r3) : "r"(addr))

#define CP16(dst_u32, gptr)                                                    \
    asm volatile("cp.async.cg.shared.global [%0], [%1], 16;"                   \
                 :: "r"(dst_u32), "l"(gptr))
#define CP_COMMIT() asm volatile("cp.async.commit_group;" ::: "memory")
#define CP_WAIT1()  asm volatile("cp.async.wait_group 1;" ::: "memory")

// ---------------------------------------------------------------------------
// fp16 tensor-core GEMM: C = A*B^T, fp32 accum, single-pass (unchanged R10).
// ---------------------------------------------------------------------------
#define ARR_HALVES (128*40)
#define STG_HALVES (2*ARR_HALVES)
#define GEMM_SMEM  (3*STG_HALVES*2)   /* 61440 bytes */

template<int M, int N, int K>
__device__ __forceinline__ void gemm_h_body(const __half* __restrict__ Ah,
                                            const __half* __restrict__ Bh,
                                            float* __restrict__ C)
{
    extern __shared__ __half dynsmem[];
    const unsigned sbase = (unsigned)__cvta_generic_to_shared(dynsmem);

    const int tid  = threadIdx.x;
    const int lane = tid & 31;
    const int wid  = tid >> 5;
    const int warpM = wid & 3;
    const int warpN = wid >> 2;
    const int m0 = blockIdx.y * 128;
    const int n0 = blockIdx.x * 128;
    const int g  = lane >> 2;
    const int tg = lane & 3;

    float acc[2][8][4] = {};

    const int r0c = tid >> 2, r1c = (tid + 256) >> 2;
    const int cc  = (tid & 3) << 3;

    const __half* pA0 = &Ah[(size_t)(m0 + r0c) * K + cc];
    const __half* pA1 = &Ah[(size_t)(m0 + r1c) * K + cc];
    const __half* pB0 = &Bh[(size_t)(n0 + r0c) * K + cc];
    const __half* pB1 = &Bh[(size_t)(n0 + r1c) * K + cc];
    const unsigned d0b = (unsigned)(r0c * 40 + cc) * 2;
    const unsigned d1b = (unsigned)(r1c * 40 + cc) * 2;

    const unsigned lm_off = ((unsigned)((lane & 15) * 40 + ((lane >> 4) << 3))) * 2;
    const unsigned a_base = sbase + (unsigned)(warpM * 32) * 80 + lm_off;
    const unsigned b_base = sbase + (unsigned)(warpN * 64) * 80 + lm_off;

    #define ISSUE(s)                                                            \
        do {                                                                    \
            unsigned sb = sbase + (unsigned)(s) * (STG_HALVES * 2);             \
            CP16(sb + d0b,                  pA0);                               \
            CP16(sb + d1b,                  pA1);                               \
            CP16(sb + d0b + ARR_HALVES*2,   pB0);                               \
            CP16(sb + d1b + ARR_HALVES*2,   pB1);                               \
            pA0 += 32; pA1 += 32; pB0 += 32; pB1 += 32;                         \
        } while (0)

    const int nch = K / 32;
    ISSUE(0);  CP_COMMIT();
    ISSUE(1);  CP_COMMIT();

    for (int ch = 0; ch < nch; ch++) {
        CP_WAIT1();
        __syncthreads();

        if (ch + 2 < nch) { ISSUE((ch + 2) % 3); }
        CP_COMMIT();

        const unsigned st = (unsigned)(ch % 3) * (STG_HALVES * 2);

        #pragma unroll
        for (int ks = 0; ks < 2; ks++) {
            const unsigned kb2 = (unsigned)(ks * 16) * 2;
            unsigned ah[2][4];
            #pragma unroll
            for (int mi = 0; mi < 2; mi++) {
                unsigned aa = a_base + st + (unsigned)(mi * 16) * 80 + kb2;
                LDSM4(ah[mi][0], ah[mi][1], ah[mi][2], ah[mi][3], aa);
            }
            #pragma unroll
            for (int nip = 0; nip < 4; nip++) {
                unsigned ba = b_base + st + ARR_HALVES*2
                            + (unsigned)(nip * 16) * 80 + kb2;
                unsigned b0e, b0o_, b1e, b1o_;
                LDSM4(b0e, b0o_, b1e, b1o_, ba);
                #pragma unroll
                for (int mi = 0; mi < 2; mi++) {
                    MMA16816(acc[mi][2*nip],   ah[mi], b0e, b1e);
                    MMA16816(acc[mi][2*nip+1], ah[mi], b0o_, b1o_);
                }
            }
        }
    }
    #undef ISSUE

    #pragma unroll
    for (int mi = 0; mi < 2; mi++) {
        int r0 = m0 + warpM*32 + mi*16 + g;
        #pragma unroll
        for (int ni = 0; ni < 8; ni++) {
            int c = n0 + warpN*64 + ni*8 + tg*2;
            *(float2*)&C[(size_t)r0 * N + c] =
                make_float2(acc[mi][ni][0], acc[mi][ni][1]);
            *(float2*)&C[(size_t)(r0+8) * N + c] =
                make_float2(acc[mi][ni][2], acc[mi][ni][3]);
        }
    }
}

__global__ __launch_bounds__(256, 2)
void qkv_gemm_kernel() {
    gemm_h_body<NTOK, E3, DMODEL>(g_xh, g_wqh, g_qkv);
}
__global__ __launch_bounds__(256, 2)
void out_gemm_kernel(float* __restrict__ out) {
    gemm_h_body<NTOK, DMODEL, DMODEL>(g_ah, g_woh, out);
}

// ---------------------------------------------------------------------------
// RoPE applied in-place to Q and K halves of g_qkv (unchanged, known-good).
// ---------------------------------------------------------------------------
__global__ void rope_kernel(const int* __restrict__ pos)
{
    int t = blockIdx.x * blockDim.x + threadIdx.x;
    const int total = NTOK * NHEADS * (DK / 2);
    if (t >= total) return;

    int i = t & 31;
    int h = (t >> 5) & (NHEADS - 1);
    int n = t >> 9;
    int s = n & (SEQ - 1);

    float p = (float)pos[s];
    float inv = expf(-((float)i / 32.0f) * 9.2103403719761836f);
    float ang = p * inv;
    float sn, cs;
    sincosf(ang, &sn, &cs);

    float* q = &g_qkv[(size_t)n * E3 + h * DK + 2 * i];
    float q1 = q[0], q2 = q[1];
    q[0] = q1 * cs - q2 * sn;
    q[1] = q1 * sn + q2 * cs;

    float* k = q + DMODEL;
    float k1 = k[0], k2 = k[1];
    k[0] = k1 * cs - k2 * sn;
    k[1] = k1 * sn + k2 * cs;
}

// ---------------------------------------------------------------------------
// Causal flash attention, fp16 tensor cores (paired q-tiles, exp2).
// R11: PV single-pass (V hi only) — sVl array, its transposed stores and the
// lo-mma pass removed. QK stays 2-pass (Q hi/lo x K hi). smem 55KB -> 36KB.
// ---------------------------------------------------------------------------
__global__ __launch_bounds__(256)
void attn_mma_kernel()
{
    const int h   = blockIdx.y;
    const int b   = blockIdx.z;
    const int tid = threadIdx.x;
    const int lane = tid & 31;
    const int w   = tid >> 5;
    const int g   = lane >> 2;
    const int tg  = lane & 3;

    __shared__ __half sKh[2][64*72], sVh[2][64*72];

    const float scale = 0.125f * 1.44269504088896f;   // 1/sqrt(64) * log2(e)

    float4 pk[4], pv[4];

    #define GLT(kt_)                                                           \
        _Pragma("unroll")                                                      \
        for (int i = 0; i < 4; i++) {                                          \
            int idx = tid + i*256;                                             \
            int r = idx >> 4, c4 = (idx & 15) << 2;                            \
            size_t base = ((size_t)(b*SEQ) + (kt_)*64 + r)*E3 + h*DK + c4;     \
            pk[i] = *(const float4*)&g_qkv[base + DMODEL];                     \
            pv[i] = *(const float4*)&g_qkv[base + 2*DMODEL];                   \
        }

    #define STS_T(buf_)                                                        \
        _Pragma("unroll")                                                      \
        for (int i = 0; i < 4; i++) {                                          \
            int idx = tid + i*256;                                             \
            int r = idx >> 4, c4 = (idx & 15) << 2;                            \
            *(unsigned*)&sKh[buf_][r*72 + c4]     = pack_h(pk[i].x, pk[i].y);  \
            *(unsigned*)&sKh[buf_][r*72 + c4 + 2] = pack_h(pk[i].z, pk[i].w);  \
            float vf[4] = {pv[i].x, pv[i].y, pv[i].z, pv[i].w};                \
            _Pragma("unroll")                                                  \
            for (int j = 0; j < 4; j++) {                                      \
                sVh[buf_][(c4+j)*72 + r] = __float2half_rn(vf[j]);             \
            }                                                                  \
        }

    #pragma unroll 1
    for (int half = 0; half < 2; half++) {
        const int qt = half ? (NTQ - 1 - blockIdx.x) : blockIdx.x;
        const int qbase = qt * 128;
        const int row0 = qbase + w*16 + g;
        const int row1 = row0 + 8;
        const int wrowmax = qbase + w*16 + 15;

        unsigned qh[4][4], ql[4][4];
        {
            const float* q0 = &g_qkv[((size_t)(b*SEQ) + row0)*E3 + h*DK];
            const float* q1 = &g_qkv[((size_t)(b*SEQ) + row1)*E3 + h*DK];
            #pragma unroll
            for (int kk = 0; kk < 4; kk++) {
                int d0 = kk*16 + 2*tg;
                float2 a0 = *(const float2*)&q0[d0];
                float2 a1 = *(const float2*)&q1[d0];
                float2 a2 = *(const float2*)&q0[d0+8];
                float2 a3 = *(const float2*)&q1[d0+8];
                qh[kk][0] = split_pack(a0.x*scale, a0.y*scale, ql[kk][0]);
                qh[kk][1] = split_pack(a1.x*scale, a1.y*scale, ql[kk][1]);
                qh[kk][2] = split_pack(a2.x*scale, a2.y*scale, ql[kk][2]);
                qh[kk][3] = split_pack(a3.x*scale, a3.y*scale, ql[kk][3]);
            }
        }

        float o[8][4] = {};
        float m0 = -1e30f, m1 = -1e30f, l0 = 0.f, l1 = 0.f;

        const int ntiles = 2*qt + 2;

        GLT(0);
        STS_T(0);
        __syncthreads();

        for (int kt = 0; kt < ntiles; kt++) {
            const int kvbase = kt * 64;
            const int buf = kt & 1;

            if (kt + 1 < ntiles) { GLT(kt + 1); }

            if (kvbase <= wrowmax) {
                float sc[8][4] = {};

                #pragma unroll
                for (int kk = 0; kk < 4; kk++) {
                    int ko = kk*16 + 2*tg;
                    #pragma unroll
                    for (int ni = 0; ni < 8; ni++) {
                        int rb = (ni*8 + g)*72 + ko;
                        unsigned b0h = *(const unsigned*)&sKh[buf][rb];
                        unsigned b1h = *(const unsigned*)&sKh[buf][rb + 8];
                        MMA16816(sc[ni], qh[kk], b0h, b1h);
                        MMA16816(sc[ni], ql[kk], b0h, b1h);
                    }
                }

                if (kvbase + 63 > row0) {
                    #pragma unroll
                    for (int ni = 0; ni < 8; ni++) {
                        int c = kvbase + ni*8 + 2*tg;
                        if (c     > row0) sc[ni][0] = -1e30f;
                        if (c + 1 > row0) sc[ni][1] = -1e30f;
                        if (c     > row1) sc[ni][2] = -1e30f;
                        if (c + 1 > row1) sc[ni][3] = -1e30f;
                    }
                }

                float t0 = -1e30f, t1 = -1e30f;
                #pragma unroll
                for (int ni = 0; ni < 8; ni++) {
                    t0 = fmaxf(t0, fmaxf(sc[ni][0], sc[ni][1]));
                    t1 = fmaxf(t1, fmaxf(sc[ni][2], sc[ni][3]));
                }
                t0 = fmaxf(t0, __shfl_xor_sync(0xffffffffu, t0, 1));
                t0 = fmaxf(t0, __shfl_xor_sync(0xffffffffu, t0, 2));
                t1 = fmaxf(t1, __shfl_xor_sync(0xffffffffu, t1, 1));
                t1 = fmaxf(t1, __shfl_xor_sync(0xffffffffu, t1, 2));

                float m0n = fmaxf(m0, t0), m1n = fmaxf(m1, t1);
                float c0 = exp2f(m0 - m0n), c1 = exp2f(m1 - m1n);
                m0 = m0n; m1 = m1n;
                l0 *= c0;  l1 *= c1;
                #pragma unroll
                for (int ni = 0; ni < 8; ni++) {
                    o[ni][0] *= c0; o[ni][1] *= c0;
                    o[ni][2] *= c1; o[ni][3] *= c1;
                }

                #pragma unroll
                for (int ni = 0; ni < 8; ni++) {
                    sc[ni][0] = exp2f(sc[ni][0] - m0);
                    sc[ni][1] = exp2f(sc[ni][1] - m0);
                    sc[ni][2] = exp2f(sc[ni][2] - m1);
                    sc[ni][3] = exp2f(sc[ni][3] - m1);
                    l0 += sc[ni][0] + sc[ni][1];
                    l1 += sc[ni][2] + sc[ni][3];
                }

                #pragma unroll
                for (int kk = 0; kk < 4; kk++) {
                    unsigned ph[4];
                    ph[0] = pack_h(sc[2*kk][0],   sc[2*kk][1]);
                    ph[1] = pack_h(sc[2*kk][2],   sc[2*kk][3]);
                    ph[2] = pack_h(sc[2*kk+1][0], sc[2*kk+1][1]);
                    ph[3] = pack_h(sc[2*kk+1][2], sc[2*kk+1][3]);
                    int ko = kk*16 + 2*tg;
                    #pragma unroll
                    for (int nd = 0; nd < 8; nd++) {
                        int rb = (nd*8 + g)*72 + ko;
                        unsigned b0h = *(const unsigned*)&sVh[buf][rb];
                        unsigned b1h = *(const unsigned*)&sVh[buf][rb + 8];
                        MMA16816(o[nd], ph, b0h, b1h);
                    }
                }
            }

            if (kt + 1 < ntiles) { STS_T(buf ^ 1); }
            __syncthreads();
        }

        l0 += __shfl_xor_sync(0xffffffffu, l0, 1);
        l0 += __shfl_xor_sync(0xffffffffu, l0, 2);
        l1 += __shfl_xor_sync(0xffffffffu, l1, 1);
        l1 += __shfl_xor_sync(0xffffffffu, l1, 2);
        float inv0 = 1.f / l0, inv1 = 1.f / l1;

        size_t base0 = ((size_t)(b*SEQ) + row0)*DMODEL + h*DK;
        size_t base1 = ((size_t)(b*SEQ) + row1)*DMODEL + h*DK;
        #pragma unroll
        for (int nd = 0; nd < 8; nd++) {
            int c = nd*8 + 2*tg;
            *(unsigned*)&g_ah[base0 + c] = pack_h(o[nd][0]*inv0, o[nd][1]*inv0);
            *(unsigned*)&g_ah[base1 + c] = pack_h(o[nd][2]*inv1, o[nd][3]*inv1);
        }
    }
    #undef GLT
    #undef STS_T
}

// ---------------------------------------------------------------------------
extern "C" void kernel_launch(void* const* d_in, const int* in_sizes, int n_in,
                              void* d_out, int out_size)
{
    const float* x      = (const float*)d_in[0];
    const int*   pos    = (const int*)d_in[1];
    const float* w_qkv  = (const float*)d_in[2];
    const float* w_o    = (const float*)d_in[3];
    float*       out    = (float*)d_out;

    cudaFuncSetAttribute(qkv_gemm_kernel,
                         cudaFuncAttributeMaxDynamicSharedMemorySize, GEMM_SMEM);
    cudaFuncSetAttribute(out_gemm_kernel,
                         cudaFuncAttributeMaxDynamicSharedMemorySize, GEMM_SMEM);

    // 0) fp16 converts
    cvt_x_kernel <<<(NTOK*DMODEL/4 + 255)/256, 256>>>(x);
    cvt_wq_kernel<<<(E3*DMODEL/4   + 255)/256, 256>>>(w_qkv);
    cvt_wo_kernel<<<(DMODEL*DMODEL/4 + 255)/256, 256>>>(w_o);

    // 1) QKV projection (1-pass fp16)
    {
        dim3 grid(E3 / 128, NTOK / 128);
        qkv_gemm_kernel<<<grid, 256, GEMM_SMEM>>>();
    }
    // 2) RoPE
    {
        int total = NTOK * NHEADS * (DK / 2);
        rope_kernel<<<(total + 255) / 256, 256>>>(pos);
    }
    // 3) Causal flash attention (paired q-tiles, PV 1-pass)
    {
        dim3 grid(NTQ / 2, NHEADS, BATCH);
        attn_mma_kernel<<<grid, 256>>>();
    }
    // 4) Output projection (1-pass fp16)
    {
        dim3 grid(DMODEL / 128, NTOK / 128);
        out_gemm_kernel<<<grid, 256, GEMM_SMEM>>>(out);
    }
}

// round 13
// speedup vs baseline: 6.4958x; 1.0701x over previous
#include <cuda_runtime.h>
#include <cuda_fp16.h>
#include <math.h>

#define BATCH   2
#define SEQ     2048
#define DMODEL  1024
#define NHEADS  16
#define DK      64
#define NTOK    (BATCH*SEQ)      /* 4096 */
#define E3      (3*DMODEL)       /* 3072 */
#define NTQ     (SEQ/128)        /* 16 q-tiles */

// Scratch (allocation-free rule: __device__ globals)
__device__ float  g_qf32[(size_t)NTOK * DMODEL];   // roped Q, fp32
__device__ __half g_kh[(size_t)NTOK * DMODEL];     // roped K, fp16
__device__ __half g_vh[(size_t)NTOK * DMODEL];     // V, fp16
__device__ __half g_xh[(size_t)NTOK * DMODEL];
__device__ __half g_wqh[(size_t)E3 * DMODEL];
__device__ __half g_woh[(size_t)DMODEL*DMODEL];
__device__ __half g_ah[(size_t)NTOK * DMODEL];

// ---------------------------------------------------------------------------
// fp16 helpers
// ---------------------------------------------------------------------------
__device__ __forceinline__ unsigned split_pack(float a, float b, unsigned& lo)
{
    __half2 h = __floats2half2_rn(a, b);
    float2 f = __half22float2(h);
    __half2 l = __floats2half2_rn(a - f.x, b - f.y);
    lo = *reinterpret_cast<unsigned*>(&l);
    return *reinterpret_cast<unsigned*>(&h);
}

__device__ __forceinline__ unsigned pack_h(float a, float b)
{
    __half2 h = __floats2half2_rn(a, b);
    return *reinterpret_cast<unsigned*>(&h);
}

__global__ void cvt_x_kernel(const float* __restrict__ x) {
    int i = blockIdx.x * blockDim.x + threadIdx.x;
    if (i >= NTOK * DMODEL / 4) return;
    float4 v = ((const float4*)x)[i];
    *(__half2*)&g_xh[(size_t)i*4]     = __floats2half2_rn(v.x, v.y);
    *(__half2*)&g_xh[(size_t)i*4 + 2] = __floats2half2_rn(v.z, v.w);
}
__global__ void cvt_wq_kernel(const float* __restrict__ w) {
    int i = blockIdx.x * blockDim.x + threadIdx.x;
    if (i >= E3 * DMODEL / 4) return;
    float4 v = ((const float4*)w)[i];
    *(__half2*)&g_wqh[(size_t)i*4]     = __floats2half2_rn(v.x, v.y);
    *(__half2*)&g_wqh[(size_t)i*4 + 2] = __floats2half2_rn(v.z, v.w);
}
__global__ void cvt_wo_kernel(const float* __restrict__ w) {
    int i = blockIdx.x * blockDim.x + threadIdx.x;
    if (i >= DMODEL * DMODEL / 4) return;
    float4 v = ((const float4*)w)[i];
    *(__half2*)&g_woh[(size_t)i*4]     = __floats2half2_rn(v.x, v.y);
    *(__half2*)&g_woh[(size_t)i*4 + 2] = __floats2half2_rn(v.z, v.w);
}

// ---------------------------------------------------------------------------
#define MMA16816(d, a, b0, b1)                                                 \
    asm volatile("mma.sync.aligned.m16n8k16.row.col.f32.f16.f16.f32 "          \
                 "{%0,%1,%2,%3}, {%4,%5,%6,%7}, {%8,%9}, {%0,%1,%2,%3};"       \
                 : "+f"(d[0]), "+f"(d[1]), "+f"(d[2]), "+f"(d[3])              \
                 : "r"(a[0]), "r"(a[1]), "r"(a[2]), "r"(a[3]), "r"(b0), "r"(b1))

#define LDSM4(r0, r1, r2, r3, addr)                                            \
    asm volatile("ldmatrix.sync.aligned.m8n8.x4.shared.b16 {%0,%1,%2,%3}, [%4];" \
                 : "=r"(r0), "=r"(r1), "=r"(r2), "=r"(r3) : "r"(addr))

#define CP16(dst_u32, gptr)                                                    \
    asm volatile("cp.async.cg.shared.global [%0], [%1], 16;"                   \
                 :: "r"(dst_u32), "l"(gptr))
#define CP_COMMIT() asm volatile("cp.async.commit_group;" ::: "memory")
#define CP_WAIT1()  asm volatile("cp.async.wait_group 1;" ::: "memory")

// ---------------------------------------------------------------------------
// fp16 GEMM mainloop (shared by qkv and out kernels via macro): computes the
// 128x128 fp32 accumulator tile for C = A*B^T. 3-stage cp.async + ldmatrix.
// ---------------------------------------------------------------------------
#define ARR_HALVES (128*40)
#define STG_HALVES (2*ARR_HALVES)
#define GEMM_SMEM  (3*STG_HALVES*2)   /* 61440 bytes */

#define GEMM_MAINLOOP(Ah, Bh, Kdim)                                            \
    extern __shared__ __half dynsmem[];                                        \
    const unsigned sbase = (unsigned)__cvta_generic_to_shared(dynsmem);        \
    const int tid  = threadIdx.x;                                              \
    const int lane = tid & 31;                                                 \
    const int wid  = tid >> 5;                                                 \
    const int warpM = wid & 3;                                                 \
    const int warpN = wid >> 2;                                                \
    const int m0 = blockIdx.y * 128;                                           \
    const int n0 = blockIdx.x * 128;                                           \
    const int g  = lane >> 2;                                                  \
    const int tg = lane & 3;                                                   \
    float acc[2][8][4] = {};                                                   \
    const int r0c = tid >> 2, r1c = (tid + 256) >> 2;                          \
    const int cc  = (tid & 3) << 3;                                            \
    const __half* pA0 = &Ah[(size_t)(m0 + r0c) * Kdim + cc];                   \
    const __half* pA1 = &Ah[(size_t)(m0 + r1c) * Kdim + cc];                   \
    const __half* pB0 = &Bh[(size_t)(n0 + r0c) * Kdim + cc];                   \
    const __half* pB1 = &Bh[(size_t)(n0 + r1c) * Kdim + cc];                   \
    const unsigned d0b = (unsigned)(r0c * 40 + cc) * 2;                        \
    const unsigned d1b = (unsigned)(r1c * 40 + cc) * 2;                        \
    const unsigned lm_off =                                                    \
        ((unsigned)((lane & 15) * 40 + ((lane >> 4) << 3))) * 2;               \
    const unsigned a_base = sbase + (unsigned)(warpM * 32) * 80 + lm_off;      \
    const unsigned b_base = sbase + (unsigned)(warpN * 64) * 80 + lm_off;      \
    const int nch = Kdim / 32;                                                 \
    ISSUE(0);  CP_COMMIT();                                                    \
    ISSUE(1);  CP_COMMIT();                                                    \
    for (int ch = 0; ch < nch; ch++) {                                         \
        CP_WAIT1();                                                            \
        __syncthreads();                                                       \
        if (ch + 2 < nch) { ISSUE((ch + 2) % 3); }                             \
        CP_COMMIT();                                                           \
        const unsigned st = (unsigned)(ch % 3) * (STG_HALVES * 2);             \
        _Pragma("unroll")                                                      \
        for (int ks = 0; ks < 2; ks++) {                                       \
            const unsigned kb2 = (unsigned)(ks * 16) * 2;                      \
            unsigned ah[2][4];                                                 \
            _Pragma("unroll")                                                  \
            for (int mi = 0; mi < 2; mi++) {                                   \
                unsigned aa = a_base + st + (unsigned)(mi * 16) * 80 + kb2;    \
                LDSM4(ah[mi][0], ah[mi][1], ah[mi][2], ah[mi][3], aa);         \
            }                                                                  \
            _Pragma("unroll")                                                  \
            for (int nip = 0; nip < 4; nip++) {                                \
                unsigned ba = b_base + st + ARR_HALVES*2                       \
                            + (unsigned)(nip * 16) * 80 + kb2;                 \
                unsigned b0e, b0o_, b1e, b1o_;                                 \
                LDSM4(b0e, b0o_, b1e, b1o_, ba);                               \
                _Pragma("unroll")                                              \
                for (int mi = 0; mi < 2; mi++) {                               \
                    MMA16816(acc[mi][2*nip],   ah[mi], b0e, b1e);              \
                    MMA16816(acc[mi][2*nip+1], ah[mi], b0o_, b1o_);            \
                }                                                              \
            }                                                                  \
        }                                                                      \
    }

#define ISSUE(s)                                                               \
    do {                                                                       \
        unsigned sb = sbase + (unsigned)(s) * (STG_HALVES * 2);                \
        CP16(sb + d0b,                  pA0);                                  \
        CP16(sb + d1b,                  pA1);                                  \
        CP16(sb + d0b + ARR_HALVES*2,   pB0);                                  \
        CP16(sb + d1b + ARR_HALVES*2,   pB1);                                  \
        pA0 += 32; pA1 += 32; pB0 += 32; pB1 += 32;                            \
    } while (0)

// ---------------------------------------------------------------------------
// QKV GEMM with fused RoPE + dtype-split epilogue.
// Column block region (uniform per block): bx<8 -> Q (rope, fp32),
// 8..15 -> K (rope, fp16), 16..23 -> V (fp16).
// ---------------------------------------------------------------------------
__global__ __launch_bounds__(256, 2)
void qkv_gemm_kernel(const int* __restrict__ pos)
{
    GEMM_MAINLOOP(g_xh, g_wqh, DMODEL)

    const int region = (blockIdx.x * 128) >> 10;   // 0=Q, 1=K, 2=V

    #pragma unroll
    for (int mi = 0; mi < 2; mi++) {
        int r0 = m0 + warpM*32 + mi*16 + g;
        float p0 = (float)pos[r0 & (SEQ-1)];
        float p1 = (float)pos[(r0+8) & (SEQ-1)];
        #pragma unroll
        for (int ni = 0; ni < 8; ni++) {
            int cg  = n0 + warpN*64 + ni*8 + tg*2;
            int col = cg & (DMODEL-1);
            float x0 = acc[mi][ni][0], y0 = acc[mi][ni][1];
            float x1 = acc[mi][ni][2], y1 = acc[mi][ni][3];
            if (region < 2) {   // rope for Q and K
                int i = (col & 63) >> 1;
                float inv = expf(-((float)i * (1.0f/32.0f)) * 9.2103403719761836f);
                float sn0, cs0, sn1, cs1;
                sincosf(p0 * inv, &sn0, &cs0);
                sincosf(p1 * inv, &sn1, &cs1);
                float t;
                t = x0*cs0 - y0*sn0; y0 = x0*sn0 + y0*cs0; x0 = t;
                t = x1*cs1 - y1*sn1; y1 = x1*sn1 + y1*cs1; x1 = t;
            }
            size_t o0 = (size_t)r0 * DMODEL + col;
            size_t o1 = (size_t)(r0+8) * DMODEL + col;
            if (region == 0) {
                *(float2*)&g_qf32[o0] = make_float2(x0, y0);
                *(float2*)&g_qf32[o1] = make_float2(x1, y1);
            } else if (region == 1) {
                *(unsigned*)&g_kh[o0] = pack_h(x0, y0);
                *(unsigned*)&g_kh[o1] = pack_h(x1, y1);
            } else {
                *(unsigned*)&g_vh[o0] = pack_h(x0, y0);
                *(unsigned*)&g_vh[o1] = pack_h(x1, y1);
            }
        }
    }
}

// ---------------------------------------------------------------------------
// Output GEMM (generic fp32 epilogue).
// ---------------------------------------------------------------------------
__global__ __launch_bounds__(256, 2)
void out_gemm_kernel(float* __restrict__ out)
{
    GEMM_MAINLOOP(g_ah, g_woh, DMODEL)

    #pragma unroll
    for (int mi = 0; mi < 2; mi++) {
        int r0 = m0 + warpM*32 + mi*16 + g;
        #pragma unroll
        for (int ni = 0; ni < 8; ni++) {
            int c = n0 + warpN*64 + ni*8 + tg*2;
            *(float2*)&out[(size_t)r0 * DMODEL + c] =
                make_float2(acc[mi][ni][0], acc[mi][ni][1]);
            *(float2*)&out[(size_t)(r0+8) * DMODEL + c] =
                make_float2(acc[mi][ni][2], acc[mi][ni][3]);
        }
    }
}
#undef ISSUE

// ---------------------------------------------------------------------------
// Causal flash attention, fp16 tensor cores (paired q-tiles, exp2).
// R12: K/V read as pre-converted fp16 (g_kh/g_vh) — tile staging is a pure
// copy (K) / transpose (V), no per-tile float->half conversion. Q from g_qf32.
// ---------------------------------------------------------------------------
__global__ __launch_bounds__(256)
void attn_mma_kernel()
{
    const int h   = blockIdx.y;
    const int b   = blockIdx.z;
    const int tid = threadIdx.x;
    const int lane = tid & 31;
    const int w   = tid >> 5;
    const int g   = lane >> 2;
    const int tg  = lane & 3;

    __shared__ __half sKh[2][64*72], sVh[2][64*72];

    const float scale = 0.125f * 1.44269504088896f;   // 1/sqrt(64) * log2(e)

    uint4 pk2[2], pv2[2];

    #define GLT(kt_)                                                           \
        _Pragma("unroll")                                                      \
        for (int i = 0; i < 2; i++) {                                          \
            int idx = tid + i*256;                                             \
            int r = idx >> 3, c8 = (idx & 7) << 3;                             \
            size_t base = ((size_t)(b*SEQ) + (kt_)*64 + r)*DMODEL + h*DK + c8; \
            pk2[i] = *(const uint4*)&g_kh[base];                               \
            pv2[i] = *(const uint4*)&g_vh[base];                               \
        }

    #define STS_T(buf_)                                                        \
        _Pragma("unroll")                                                      \
        for (int i = 0; i < 2; i++) {                                          \
            int idx = tid + i*256;                                             \
            int r = idx >> 3, c8 = (idx & 7) << 3;                             \
            *(uint4*)&sKh[buf_][r*72 + c8] = pk2[i];                           \
            const __half* vh = (const __half*)&pv2[i];                         \
            _Pragma("unroll")                                                  \
            for (int j = 0; j < 8; j++) {                                      \
                sVh[buf_][(c8+j)*72 + r] = vh[j];                              \
            }                                                                  \
        }

    #pragma unroll 1
    for (int half = 0; half < 2; half++) {
        const int qt = half ? (NTQ - 1 - blockIdx.x) : blockIdx.x;
        const int qbase = qt * 128;
        const int row0 = qbase + w*16 + g;
        const int row1 = row0 + 8;
        const int wrowmax = qbase + w*16 + 15;

        unsigned qh[4][4], ql[4][4];
        {
            const float* q0 = &g_qf32[((size_t)(b*SEQ) + row0)*DMODEL + h*DK];
            const float* q1 = &g_qf32[((size_t)(b*SEQ) + row1)*DMODEL + h*DK];
            #pragma unroll
            for (int kk = 0; kk < 4; kk++) {
                int d0 = kk*16 + 2*tg;
                float2 a0 = *(const float2*)&q0[d0];
                float2 a1 = *(const float2*)&q1[d0];
                float2 a2 = *(const float2*)&q0[d0+8];
                float2 a3 = *(const float2*)&q1[d0+8];
                qh[kk][0] = split_pack(a0.x*scale, a0.y*scale, ql[kk][0]);
                qh[kk][1] = split_pack(a1.x*scale, a1.y*scale, ql[kk][1]);
                qh[kk][2] = split_pack(a2.x*scale, a2.y*scale, ql[kk][2]);
                qh[kk][3] = split_pack(a3.x*scale, a3.y*scale, ql[kk][3]);
            }
        }

        float o[8][4] = {};
        float m0 = -1e30f, m1 = -1e30f, l0 = 0.f, l1 = 0.f;

        const int ntiles = 2*qt + 2;

        GLT(0);
        STS_T(0);
        __syncthreads();

        for (int kt = 0; kt < ntiles; kt++) {
            const int kvbase = kt * 64;
            const int buf = kt & 1;

            if (kt + 1 < ntiles) { GLT(kt + 1); }

            if (kvbase <= wrowmax) {
                float sc[8][4] = {};

                #pragma unroll
                for (int kk = 0; kk < 4; kk++) {
                    int ko = kk*16 + 2*tg;
                    #pragma unroll
                    for (int ni = 0; ni < 8; ni++) {
                        int rb = (ni*8 + g)*72 + ko;
                        unsigned b0h = *(const unsigned*)&sKh[buf][rb];
                        unsigned b1h = *(const unsigned*)&sKh[buf][rb + 8];
                        MMA16816(sc[ni], qh[kk], b0h, b1h);
                        MMA16816(sc[ni], ql[kk], b0h, b1h);
                    }
                }

                if (kvbase + 63 > row0) {
                    #pragma unroll
                    for (int ni = 0; ni < 8; ni++) {
                        int c = kvbase + ni*8 + 2*tg;
                        if (c     > row0) sc[ni][0] = -1e30f;
                        if (c + 1 > row0) sc[ni][1] = -1e30f;
                        if (c     > row1) sc[ni][2] = -1e30f;
                        if (c + 1 > row1) sc[ni][3] = -1e30f;
                    }
                }

                float t0 = -1e30f, t1 = -1e30f;
                #pragma unroll
                for (int ni = 0; ni < 8; ni++) {
                    t0 = fmaxf(t0, fmaxf(sc[ni][0], sc[ni][1]));
                    t1 = fmaxf(t1, fmaxf(sc[ni][2], sc[ni][3]));
                }
                t0 = fmaxf(t0, __shfl_xor_sync(0xffffffffu, t0, 1));
                t0 = fmaxf(t0, __shfl_xor_sync(0xffffffffu, t0, 2));
                t1 = fmaxf(t1, __shfl_xor_sync(0xffffffffu, t1, 1));
                t1 = fmaxf(t1, __shfl_xor_sync(0xffffffffu, t1, 2));

                float m0n = fmaxf(m0, t0), m1n = fmaxf(m1, t1);
                float c0 = exp2f(m0 - m0n), c1 = exp2f(m1 - m1n);
                m0 = m0n; m1 = m1n;
                l0 *= c0;  l1 *= c1;
                #pragma unroll
                for (int ni = 0; ni < 8; ni++) {
                    o[ni][0] *= c0; o[ni][1] *= c0;
                    o[ni][2] *= c1; o[ni][3] *= c1;
                }

                #pragma unroll
                for (int ni = 0; ni < 8; ni++) {
                    sc[ni][0] = exp2f(sc[ni][0] - m0);
                    sc[ni][1] = exp2f(sc[ni][1] - m0);
                    sc[ni][2] = exp2f(sc[ni][2] - m1);
                    sc[ni][3] = exp2f(sc[ni][3] - m1);
                    l0 += sc[ni][0] + sc[ni][1];
                    l1 += sc[ni][2] + sc[ni][3];
                }

                #pragma unroll
                for (int kk = 0; kk < 4; kk++) {
                    unsigned ph[4];
                    ph[0] = pack_h(sc[2*kk][0],   sc[2*kk][1]);
                    ph[1] = pack_h(sc[2*kk][2],   sc[2*kk][3]);
                    ph[2] = pack_h(sc[2*kk+1][0], sc[2*kk+1][1]);
                    ph[3] = pack_h(sc[2*kk+1][2], sc[2*kk+1][3]);
                    int ko = kk*16 + 2*tg;
                    #pragma unroll
                    for (int nd = 0; nd < 8; nd++) {
                        int rb = (nd*8 + g)*72 + ko;
                        unsigned b0h = *(const unsigned*)&sVh[buf][rb];
                        unsigned b1h = *(const unsigned*)&sVh[buf][rb + 8];
                        MMA16816(o[nd], ph, b0h, b1h);
                    }
                }
            }

            if (kt + 1 < ntiles) { STS_T(buf ^ 1); }
            __syncthreads();
        }

        l0 += __shfl_xor_sync(0xffffffffu, l0, 1);
        l0 += __shfl_xor_sync(0xffffffffu, l0, 2);
        l1 += __shfl_xor_sync(0xffffffffu, l1, 1);
        l1 += __shfl_xor_sync(0xffffffffu, l1, 2);
        float inv0 = 1.f / l0, inv1 = 1.f / l1;

        size_t base0 = ((size_t)(b*SEQ) + row0)*DMODEL + h*DK;
        size_t base1 = ((size_t)(b*SEQ) + row1)*DMODEL + h*DK;
        #pragma unroll
        for (int nd = 0; nd < 8; nd++) {
            int c = nd*8 + 2*tg;
            *(unsigned*)&g_ah[base0 + c] = pack_h(o[nd][0]*inv0, o[nd][1]*inv0);
            *(unsigned*)&g_ah[base1 + c] = pack_h(o[nd][2]*inv1, o[nd][3]*inv1);
        }
    }
    #undef GLT
    #undef STS_T
}

// ---------------------------------------------------------------------------
extern "C" void kernel_launch(void* const* d_in, const int* in_sizes, int n_in,
                              void* d_out, int out_size)
{
    const float* x      = (const float*)d_in[0];
    const int*   pos    = (const int*)d_in[1];
    const float* w_qkv  = (const float*)d_in[2];
    const float* w_o    = (const float*)d_in[3];
    float*       out    = (float*)d_out;

    cudaFuncSetAttribute(qkv_gemm_kernel,
                         cudaFuncAttributeMaxDynamicSharedMemorySize, GEMM_SMEM);
    cudaFuncSetAttribute(out_gemm_kernel,
                         cudaFuncAttributeMaxDynamicSharedMemorySize, GEMM_SMEM);

    // 0) fp16 converts
    cvt_x_kernel <<<(NTOK*DMODEL/4 + 255)/256, 256>>>(x);
    cvt_wq_kernel<<<(E3*DMODEL/4   + 255)/256, 256>>>(w_qkv);
    cvt_wo_kernel<<<(DMODEL*DMODEL/4 + 255)/256, 256>>>(w_o);

    // 1) QKV projection + fused RoPE + dtype split (rope kernel eliminated)
    {
        dim3 grid(E3 / 128, NTOK / 128);
        qkv_gemm_kernel<<<grid, 256, GEMM_SMEM>>>(pos);
    }
    // 2) Causal flash attention (fp16 KV direct)
    {
        dim3 grid(NTQ / 2, NHEADS, BATCH);
        attn_mma_kernel<<<grid, 256>>>();
    }
    // 3) Output projection
    {
        dim3 grid(DMODEL / 128, NTOK / 128);
        out_gemm_kernel<<<grid, 256, GEMM_SMEM>>>(out);
    }
}

// round 14
// speedup vs baseline: 7.2041x; 1.1090x over previous
#include <cuda_runtime.h>
#include <cuda_fp16.h>
#include <math.h>

#define BATCH   2
#define SEQ     2048
#define DMODEL  1024
#define NHEADS  16
#define DK      64
#define NTOK    (BATCH*SEQ)      /* 4096 */
#define E3      (3*DMODEL)       /* 3072 */
#define NTQ     (SEQ/128)        /* 16 q-tiles */

// Scratch (allocation-free rule: __device__ globals)
__device__ float  g_qf32[(size_t)NTOK * DMODEL];   // roped Q, fp32
__device__ __half g_kh[(size_t)NTOK * DMODEL];     // roped K, fp16
__device__ __half g_vh[(size_t)NTOK * DMODEL];     // V, fp16
__device__ __half g_xh[(size_t)NTOK * DMODEL];
__device__ __half g_wqh[(size_t)E3 * DMODEL];
__device__ __half g_woh[(size_t)DMODEL*DMODEL];
__device__ __half g_ah[(size_t)NTOK * DMODEL];

// ---------------------------------------------------------------------------
// fp16 helpers
// ---------------------------------------------------------------------------
__device__ __forceinline__ unsigned pack_h(float a, float b)
{
    __half2 h = __floats2half2_rn(a, b);
    return *reinterpret_cast<unsigned*>(&h);
}

// one launch converts x, w_qkv, w_o to fp16 (segment-dispatched grid-stride)
#define CVT_NX  (NTOK*DMODEL/4)            /* 1048576 */
#define CVT_NQ  (E3*DMODEL/4)              /*  786432 */
#define CVT_NO  (DMODEL*DMODEL/4)          /*  262144 */
#define CVT_TOT (CVT_NX + CVT_NQ + CVT_NO)

__global__ void cvt_all_kernel(const float* __restrict__ x,
                               const float* __restrict__ wq,
                               const float* __restrict__ wo)
{
    int i = blockIdx.x * blockDim.x + threadIdx.x;
    if (i >= CVT_TOT) return;
    const float4* src;
    __half* dst;
    int j;
    if (i < CVT_NX)                { src = (const float4*)x;  dst = g_xh;  j = i; }
    else if (i < CVT_NX + CVT_NQ)  { src = (const float4*)wq; dst = g_wqh; j = i - CVT_NX; }
    else                           { src = (const float4*)wo; dst = g_woh; j = i - CVT_NX - CVT_NQ; }
    float4 v = src[j];
    *(__half2*)&dst[(size_t)j*4]     = __floats2half2_rn(v.x, v.y);
    *(__half2*)&dst[(size_t)j*4 + 2] = __floats2half2_rn(v.z, v.w);
}

// ---------------------------------------------------------------------------
#define MMA16816(d, a, b0, b1)                                                 \
    asm volatile("mma.sync.aligned.m16n8k16.row.col.f32.f16.f16.f32 "          \
                 "{%0,%1,%2,%3}, {%4,%5,%6,%7}, {%8,%9}, {%0,%1,%2,%3};"       \
                 : "+f"(d[0]), "+f"(d[1]), "+f"(d[2]), "+f"(d[3])              \
                 : "r"(a[0]), "r"(a[1]), "r"(a[2]), "r"(a[3]), "r"(b0), "r"(b1))

#define LDSM4(r0, r1, r2, r3, addr)                                            \
    asm volatile("ldmatrix.sync.aligned.m8n8.x4.shared.b16 {%0,%1,%2,%3}, [%4];" \
                 : "=r"(r0), "=r"(r1), "=r"(r2), "=r"(r3) : "r"(addr))

#define CP16(dst_u32, gptr)                                                    \
    asm volatile("cp.async.cg.shared.global [%0], [%1], 16;"                   \
                 :: "r"(dst_u32), "l"(gptr))
#define CP_COMMIT() asm volatile("cp.async.commit_group;" ::: "memory")
#define CP_WAIT1()  asm volatile("cp.async.wait_group 1;" ::: "memory")

// ---------------------------------------------------------------------------
// fp16 GEMM mainloop (shared macro): 128x128 fp32 accum tile, C = A*B^T.
// ---------------------------------------------------------------------------
#define ARR_HALVES (128*40)
#define STG_HALVES (2*ARR_HALVES)
#define GEMM_SMEM  (3*STG_HALVES*2)   /* 61440 bytes */

#define GEMM_MAINLOOP(Ah, Bh, Kdim)                                            \
    extern __shared__ __half dynsmem[];                                        \
    const unsigned sbase = (unsigned)__cvta_generic_to_shared(dynsmem);        \
    const int tid  = threadIdx.x;                                              \
    const int lane = tid & 31;                                                 \
    const int wid  = tid >> 5;                                                 \
    const int warpM = wid & 3;                                                 \
    const int warpN = wid >> 2;                                                \
    const int m0 = blockIdx.y * 128;                                           \
    const int n0 = blockIdx.x * 128;                                           \
    const int g  = lane >> 2;                                                  \
    const int tg = lane & 3;                                                   \
    float acc[2][8][4] = {};                                                   \
    const int r0c = tid >> 2, r1c = (tid + 256) >> 2;                          \
    const int cc  = (tid & 3) << 3;                                            \
    const __half* pA0 = &Ah[(size_t)(m0 + r0c) * Kdim + cc];                   \
    const __half* pA1 = &Ah[(size_t)(m0 + r1c) * Kdim + cc];                   \
    const __half* pB0 = &Bh[(size_t)(n0 + r0c) * Kdim + cc];                   \
    const __half* pB1 = &Bh[(size_t)(n0 + r1c) * Kdim + cc];                   \
    const unsigned d0b = (unsigned)(r0c * 40 + cc) * 2;                        \
    const unsigned d1b = (unsigned)(r1c * 40 + cc) * 2;                        \
    const unsigned lm_off =                                                    \
        ((unsigned)((lane & 15) * 40 + ((lane >> 4) << 3))) * 2;               \
    const unsigned a_base = sbase + (unsigned)(warpM * 32) * 80 + lm_off;      \
    const unsigned b_base = sbase + (unsigned)(warpN * 64) * 80 + lm_off;      \
    const int nch = Kdim / 32;                                                 \
    ISSUE(0);  CP_COMMIT();                                                    \
    ISSUE(1);  CP_COMMIT();                                                    \
    for (int ch = 0; ch < nch; ch++) {                                         \
        CP_WAIT1();                                                            \
        __syncthreads();                                                       \
        if (ch + 2 < nch) { ISSUE((ch + 2) % 3); }                             \
        CP_COMMIT();                                                           \
        const unsigned st = (unsigned)(ch % 3) * (STG_HALVES * 2);             \
        _Pragma("unroll")                                                      \
        for (int ks = 0; ks < 2; ks++) {                                       \
            const unsigned kb2 = (unsigned)(ks * 16) * 2;                      \
            unsigned ah[2][4];                                                 \
            _Pragma("unroll")                                                  \
            for (int mi = 0; mi < 2; mi++) {                                   \
                unsigned aa = a_base + st + (unsigned)(mi * 16) * 80 + kb2;    \
                LDSM4(ah[mi][0], ah[mi][1], ah[mi][2], ah[mi][3], aa);         \
            }                                                                  \
            _Pragma("unroll")                                                  \
            for (int nip = 0; nip < 4; nip++) {                                \
                unsigned ba = b_base + st + ARR_HALVES*2                       \
                            + (unsigned)(nip * 16) * 80 + kb2;                 \
                unsigned b0e, b0o_, b1e, b1o_;                                 \
                LDSM4(b0e, b0o_, b1e, b1o_, ba);                               \
                _Pragma("unroll")                                              \
                for (int mi = 0; mi < 2; mi++) {                               \
                    MMA16816(acc[mi][2*nip],   ah[mi], b0e, b1e);              \
                    MMA16816(acc[mi][2*nip+1], ah[mi], b0o_, b1o_);            \
                }                                                              \
            }                                                                  \
        }                                                                      \
    }

#define ISSUE(s)                                                               \
    do {                                                                       \
        unsigned sb = sbase + (unsigned)(s) * (STG_HALVES * 2);                \
        CP16(sb + d0b,                  pA0);                                  \
        CP16(sb + d1b,                  pA1);                                  \
        CP16(sb + d0b + ARR_HALVES*2,   pB0);                                  \
        CP16(sb + d1b + ARR_HALVES*2,   pB1);                                  \
        pA0 += 32; pA1 += 32; pB0 += 32; pB1 += 32;                            \
    } while (0)

// ---------------------------------------------------------------------------
// QKV GEMM with fused RoPE + dtype-split epilogue (unchanged R12).
// ---------------------------------------------------------------------------
__global__ __launch_bounds__(256, 2)
void qkv_gemm_kernel(const int* __restrict__ pos)
{
    GEMM_MAINLOOP(g_xh, g_wqh, DMODEL)

    const int region = (blockIdx.x * 128) >> 10;   // 0=Q, 1=K, 2=V

    #pragma unroll
    for (int mi = 0; mi < 2; mi++) {
        int r0 = m0 + warpM*32 + mi*16 + g;
        float p0 = (float)pos[r0 & (SEQ-1)];
        float p1 = (float)pos[(r0+8) & (SEQ-1)];
        #pragma unroll
        for (int ni = 0; ni < 8; ni++) {
            int cg  = n0 + warpN*64 + ni*8 + tg*2;
            int col = cg & (DMODEL-1);
            float x0 = acc[mi][ni][0], y0 = acc[mi][ni][1];
            float x1 = acc[mi][ni][2], y1 = acc[mi][ni][3];
            if (region < 2) {   // rope for Q and K
                int i = (col & 63) >> 1;
                float inv = expf(-((float)i * (1.0f/32.0f)) * 9.2103403719761836f);
                float sn0, cs0, sn1, cs1;
                sincosf(p0 * inv, &sn0, &cs0);
                sincosf(p1 * inv, &sn1, &cs1);
                float t;
                t = x0*cs0 - y0*sn0; y0 = x0*sn0 + y0*cs0; x0 = t;
                t = x1*cs1 - y1*sn1; y1 = x1*sn1 + y1*cs1; x1 = t;
            }
            size_t o0 = (size_t)r0 * DMODEL + col;
            size_t o1 = (size_t)(r0+8) * DMODEL + col;
            if (region == 0) {
                *(float2*)&g_qf32[o0] = make_float2(x0, y0);
                *(float2*)&g_qf32[o1] = make_float2(x1, y1);
            } else if (region == 1) {
                *(unsigned*)&g_kh[o0] = pack_h(x0, y0);
                *(unsigned*)&g_kh[o1] = pack_h(x1, y1);
            } else {
                *(unsigned*)&g_vh[o0] = pack_h(x0, y0);
                *(unsigned*)&g_vh[o1] = pack_h(x1, y1);
            }
        }
    }
}

// ---------------------------------------------------------------------------
// Output GEMM (generic fp32 epilogue).
// ---------------------------------------------------------------------------
__global__ __launch_bounds__(256, 2)
void out_gemm_kernel(float* __restrict__ out)
{
    GEMM_MAINLOOP(g_ah, g_woh, DMODEL)

    #pragma unroll
    for (int mi = 0; mi < 2; mi++) {
        int r0 = m0 + warpM*32 + mi*16 + g;
        #pragma unroll
        for (int ni = 0; ni < 8; ni++) {
            int c = n0 + warpN*64 + ni*8 + tg*2;
            *(float2*)&out[(size_t)r0 * DMODEL + c] =
                make_float2(acc[mi][ni][0], acc[mi][ni][1]);
            *(float2*)&out[(size_t)(r0+8) * DMODEL + c] =
                make_float2(acc[mi][ni][2], acc[mi][ni][3]);
        }
    }
}
#undef ISSUE

// ---------------------------------------------------------------------------
// Causal flash attention, fp16 tensor cores (paired q-tiles, exp2).
// R13: QK single-pass (Q hi only — ql registers and second mma pass removed).
// ---------------------------------------------------------------------------
__global__ __launch_bounds__(256)
void attn_mma_kernel()
{
    const int h   = blockIdx.y;
    const int b   = blockIdx.z;
    const int tid = threadIdx.x;
    const int lane = tid & 31;
    const int w   = tid >> 5;
    const int g   = lane >> 2;
    const int tg  = lane & 3;

    __shared__ __half sKh[2][64*72], sVh[2][64*72];

    const float scale = 0.125f * 1.44269504088896f;   // 1/sqrt(64) * log2(e)

    uint4 pk2[2], pv2[2];

    #define GLT(kt_)                                                           \
        _Pragma("unroll")                                                      \
        for (int i = 0; i < 2; i++) {                                          \
            int idx = tid + i*256;                                             \
            int r = idx >> 3, c8 = (idx & 7) << 3;                             \
            size_t base = ((size_t)(b*SEQ) + (kt_)*64 + r)*DMODEL + h*DK + c8; \
            pk2[i] = *(const uint4*)&g_kh[base];                               \
            pv2[i] = *(const uint4*)&g_vh[base];                               \
        }

    #define STS_T(buf_)                                                        \
        _Pragma("unroll")                                                      \
        for (int i = 0; i < 2; i++) {                                          \
            int idx = tid + i*256;                                             \
            int r = idx >> 3, c8 = (idx & 7) << 3;                             \
            *(uint4*)&sKh[buf_][r*72 + c8] = pk2[i];                           \
            const __half* vh = (const __half*)&pv2[i];                         \
            _Pragma("unroll")                                                  \
            for (int j = 0; j < 8; j++) {                                      \
                sVh[buf_][(c8+j)*72 + r] = vh[j];                              \
            }                                                                  \
        }

    #pragma unroll 1
    for (int half = 0; half < 2; half++) {
        const int qt = half ? (NTQ - 1 - blockIdx.x) : blockIdx.x;
        const int qbase = qt * 128;
        const int row0 = qbase + w*16 + g;
        const int row1 = row0 + 8;
        const int wrowmax = qbase + w*16 + 15;

        unsigned qh[4][4];
        {
            const float* q0 = &g_qf32[((size_t)(b*SEQ) + row0)*DMODEL + h*DK];
            const float* q1 = &g_qf32[((size_t)(b*SEQ) + row1)*DMODEL + h*DK];
            #pragma unroll
            for (int kk = 0; kk < 4; kk++) {
                int d0 = kk*16 + 2*tg;
                float2 a0 = *(const float2*)&q0[d0];
                float2 a1 = *(const float2*)&q1[d0];
                float2 a2 = *(const float2*)&q0[d0+8];
                float2 a3 = *(const float2*)&q1[d0+8];
                qh[kk][0] = pack_h(a0.x*scale, a0.y*scale);
                qh[kk][1] = pack_h(a1.x*scale, a1.y*scale);
                qh[kk][2] = pack_h(a2.x*scale, a2.y*scale);
                qh[kk][3] = pack_h(a3.x*scale, a3.y*scale);
            }
        }

        float o[8][4] = {};
        float m0 = -1e30f, m1 = -1e30f, l0 = 0.f, l1 = 0.f;

        const int ntiles = 2*qt + 2;

        GLT(0);
        STS_T(0);
        __syncthreads();

        for (int kt = 0; kt < ntiles; kt++) {
            const int kvbase = kt * 64;
            const int buf = kt & 1;

            if (kt + 1 < ntiles) { GLT(kt + 1); }

            if (kvbase <= wrowmax) {
                float sc[8][4] = {};

                #pragma unroll
                for (int kk = 0; kk < 4; kk++) {
                    int ko = kk*16 + 2*tg;
                    #pragma unroll
                    for (int ni = 0; ni < 8; ni++) {
                        int rb = (ni*8 + g)*72 + ko;
                        unsigned b0h = *(const unsigned*)&sKh[buf][rb];
                        unsigned b1h = *(const unsigned*)&sKh[buf][rb + 8];
                        MMA16816(sc[ni], qh[kk], b0h, b1h);
                    }
                }

                if (kvbase + 63 > row0) {
                    #pragma unroll
                    for (int ni = 0; ni < 8; ni++) {
                        int c = kvbase + ni*8 + 2*tg;
                        if (c     > row0) sc[ni][0] = -1e30f;
                        if (c + 1 > row0) sc[ni][1] = -1e30f;
                        if (c     > row1) sc[ni][2] = -1e30f;
                        if (c + 1 > row1) sc[ni][3] = -1e30f;
                    }
                }

                float t0 = -1e30f, t1 = -1e30f;
                #pragma unroll
                for (int ni = 0; ni < 8; ni++) {
                    t0 = fmaxf(t0, fmaxf(sc[ni][0], sc[ni][1]));
                    t1 = fmaxf(t1, fmaxf(sc[ni][2], sc[ni][3]));
                }
                t0 = fmaxf(t0, __shfl_xor_sync(0xffffffffu, t0, 1));
                t0 = fmaxf(t0, __shfl_xor_sync(0xffffffffu, t0, 2));
                t1 = fmaxf(t1, __shfl_xor_sync(0xffffffffu, t1, 1));
                t1 = fmaxf(t1, __shfl_xor_sync(0xffffffffu, t1, 2));

                float m0n = fmaxf(m0, t0), m1n = fmaxf(m1, t1);
                float c0 = exp2f(m0 - m0n), c1 = exp2f(m1 - m1n);
                m0 = m0n; m1 = m1n;
                l0 *= c0;  l1 *= c1;
                #pragma unroll
                for (int ni = 0; ni < 8; ni++) {
                    o[ni][0] *= c0; o[ni][1] *= c0;
                    o[ni][2] *= c1; o[ni][3] *= c1;
                }

                #pragma unroll
                for (int ni = 0; ni < 8; ni++) {
                    sc[ni][0] = exp2f(sc[ni][0] - m0);
                    sc[ni][1] = exp2f(sc[ni][1] - m0);
                    sc[ni][2] = exp2f(sc[ni][2] - m1);
                    sc[ni][3] = exp2f(sc[ni][3] - m1);
                    l0 += sc[ni][0] + sc[ni][1];
                    l1 += sc[ni][2] + sc[ni][3];
                }

                #pragma unroll
                for (int kk = 0; kk < 4; kk++) {
                    unsigned ph[4];
                    ph[0] = pack_h(sc[2*kk][0],   sc[2*kk][1]);
                    ph[1] = pack_h(sc[2*kk][2],   sc[2*kk][3]);
                    ph[2] = pack_h(sc[2*kk+1][0], sc[2*kk+1][1]);
                    ph[3] = pack_h(sc[2*kk+1][2], sc[2*kk+1][3]);
                    int ko = kk*16 + 2*tg;
                    #pragma unroll
                    for (int nd = 0; nd < 8; nd++) {
                        int rb = (nd*8 + g)*72 + ko;
                        unsigned b0h = *(const unsigned*)&sVh[buf][rb];
                        unsigned b1h = *(const unsigned*)&sVh[buf][rb + 8];
                        MMA16816(o[nd], ph, b0h, b1h);
                    }
                }
            }

            if (kt + 1 < ntiles) { STS_T(buf ^ 1); }
            __syncthreads();
        }

        l0 += __shfl_xor_sync(0xffffffffu, l0, 1);
        l0 += __shfl_xor_sync(0xffffffffu, l0, 2);
        l1 += __shfl_xor_sync(0xffffffffu, l1, 1);
        l1 += __shfl_xor_sync(0xffffffffu, l1, 2);
        float inv0 = 1.f / l0, inv1 = 1.f / l1;

        size_t base0 = ((size_t)(b*SEQ) + row0)*DMODEL + h*DK;
        size_t base1 = ((size_t)(b*SEQ) + row1)*DMODEL + h*DK;
        #pragma unroll
        for (int nd = 0; nd < 8; nd++) {
            int c = nd*8 + 2*tg;
            *(unsigned*)&g_ah[base0 + c] = pack_h(o[nd][0]*inv0, o[nd][1]*inv0);
            *(unsigned*)&g_ah[base1 + c] = pack_h(o[nd][2]*inv1, o[nd][3]*inv1);
        }
    }
    #undef GLT
    #undef STS_T
}

// ---------------------------------------------------------------------------
extern "C" void kernel_launch(void* const* d_in, const int* in_sizes, int n_in,
                              void* d_out, int out_size)
{
    const float* x      = (const float*)d_in[0];
    const int*   pos    = (const int*)d_in[1];
    const float* w_qkv  = (const float*)d_in[2];
    const float* w_o    = (const float*)d_in[3];
    float*       out    = (float*)d_out;

    cudaFuncSetAttribute(qkv_gemm_kernel,
                         cudaFuncAttributeMaxDynamicSharedMemorySize, GEMM_SMEM);
    cudaFuncSetAttribute(out_gemm_kernel,
                         cudaFuncAttributeMaxDynamicSharedMemorySize, GEMM_SMEM);

    // 0) fp16 converts (single fused launch)
    cvt_all_kernel<<<(CVT_TOT + 255)/256, 256>>>(x, w_qkv, w_o);

    // 1) QKV projection + fused RoPE + dtype split
    {
        dim3 grid(E3 / 128, NTOK / 128);
        qkv_gemm_kernel<<<grid, 256, GEMM_SMEM>>>(pos);
    }
    // 2) Causal flash attention
    {
        dim3 grid(NTQ / 2, NHEADS, BATCH);
        attn_mma_kernel<<<grid, 256>>>();
    }
    // 3) Output projection
    {
        dim3 grid(DMODEL / 128, NTOK / 128);
        out_gemm_kernel<<<grid, 256, GEMM_SMEM>>>(out);
    }
}

// round 15
// speedup vs baseline: 7.8541x; 1.0902x over previous
#include <cuda_runtime.h>
#include <cuda_fp16.h>
#include <math.h>

#define BATCH   2
#define SEQ     2048
#define DMODEL  1024
#define NHEADS  16
#define DK      64
#define NTOK    (BATCH*SEQ)      /* 4096 */
#define E3      (3*DMODEL)       /* 3072 */
#define NTQ     (SEQ/128)        /* 16 q-tiles */

// Scratch (allocation-free rule: __device__ globals)
__device__ float  g_qf32[(size_t)NTOK * DMODEL];   // roped Q, fp32
__device__ __half g_kh[(size_t)NTOK * DMODEL];     // roped K, fp16
__device__ __half g_vh[(size_t)NTOK * DMODEL];     // V, fp16
__device__ __half g_xh[(size_t)NTOK * DMODEL];
__device__ __half g_wqh[(size_t)E3 * DMODEL];
__device__ __half g_woh[(size_t)DMODEL*DMODEL];
__device__ __half g_ah[(size_t)NTOK * DMODEL];

// ---------------------------------------------------------------------------
__device__ __forceinline__ unsigned pack_h(float a, float b)
{
    __half2 h = __floats2half2_rn(a, b);
    return *reinterpret_cast<unsigned*>(&h);
}

// one launch converts x, w_qkv, w_o to fp16 (segment-dispatched)
#define CVT_NX  (NTOK*DMODEL/4)
#define CVT_NQ  (E3*DMODEL/4)
#define CVT_NO  (DMODEL*DMODEL/4)
#define CVT_TOT (CVT_NX + CVT_NQ + CVT_NO)

__global__ void cvt_all_kernel(const float* __restrict__ x,
                               const float* __restrict__ wq,
                               const float* __restrict__ wo)
{
    int i = blockIdx.x * blockDim.x + threadIdx.x;
    if (i >= CVT_TOT) return;
    const float4* src;
    __half* dst;
    int j;
    if (i < CVT_NX)                { src = (const float4*)x;  dst = g_xh;  j = i; }
    else if (i < CVT_NX + CVT_NQ)  { src = (const float4*)wq; dst = g_wqh; j = i - CVT_NX; }
    else                           { src = (const float4*)wo; dst = g_woh; j = i - CVT_NX - CVT_NQ; }
    float4 v = src[j];
    *(__half2*)&dst[(size_t)j*4]     = __floats2half2_rn(v.x, v.y);
    *(__half2*)&dst[(size_t)j*4 + 2] = __floats2half2_rn(v.z, v.w);
}

// ---------------------------------------------------------------------------
#define MMA16816(d, a, b0, b1)                                                 \
    asm volatile("mma.sync.aligned.m16n8k16.row.col.f32.f16.f16.f32 "          \
                 "{%0,%1,%2,%3}, {%4,%5,%6,%7}, {%8,%9}, {%0,%1,%2,%3};"       \
                 : "+f"(d[0]), "+f"(d[1]), "+f"(d[2]), "+f"(d[3])              \
                 : "r"(a[0]), "r"(a[1]), "r"(a[2]), "r"(a[3]), "r"(b0), "r"(b1))

#define LDSM4(r0, r1, r2, r3, addr)                                            \
    asm volatile("ldmatrix.sync.aligned.m8n8.x4.shared.b16 {%0,%1,%2,%3}, [%4];" \
                 : "=r"(r0), "=r"(r1), "=r"(r2), "=r"(r3) : "r"(addr))

#define LDSM4T(r0, r1, r2, r3, addr)                                           \
    asm volatile("ldmatrix.sync.aligned.m8n8.x4.trans.shared.b16 {%0,%1,%2,%3}, [%4];" \
                 : "=r"(r0), "=r"(r1), "=r"(r2), "=r"(r3) : "r"(addr))

#define CP16(dst_u32, gptr)                                                    \
    asm volatile("cp.async.cg.shared.global [%0], [%1], 16;"                   \
                 :: "r"(dst_u32), "l"(gptr))
#define CP_COMMIT() asm volatile("cp.async.commit_group;" ::: "memory")
#define CP_WAIT1()  asm volatile("cp.async.wait_group 1;" ::: "memory")

// ---------------------------------------------------------------------------
// fp16 GEMM mainloop (shared macro, unchanged from R13).
// ---------------------------------------------------------------------------
#define ARR_HALVES (128*40)
#define STG_HALVES (2*ARR_HALVES)
#define GEMM_SMEM  (3*STG_HALVES*2)   /* 61440 bytes */

#define GEMM_MAINLOOP(Ah, Bh, Kdim)                                            \
    extern __shared__ __half dynsmem[];                                        \
    const unsigned sbase = (unsigned)__cvta_generic_to_shared(dynsmem);        \
    const int tid  = threadIdx.x;                                              \
    const int lane = tid & 31;                                                 \
    const int wid  = tid >> 5;                                                 \
    const int warpM = wid & 3;                                                 \
    const int warpN = wid >> 2;                                                \
    const int m0 = blockIdx.y * 128;                                           \
    const int n0 = blockIdx.x * 128;                                           \
    const int g  = lane >> 2;                                                  \
    const int tg = lane & 3;                                                   \
    float acc[2][8][4] = {};                                                   \
    const int r0c = tid >> 2, r1c = (tid + 256) >> 2;                          \
    const int cc  = (tid & 3) << 3;                                            \
    const __half* pA0 = &Ah[(size_t)(m0 + r0c) * Kdim + cc];                   \
    const __half* pA1 = &Ah[(size_t)(m0 + r1c) * Kdim + cc];                   \
    const __half* pB0 = &Bh[(size_t)(n0 + r0c) * Kdim + cc];                   \
    const __half* pB1 = &Bh[(size_t)(n0 + r1c) * Kdim + cc];                   \
    const unsigned d0b = (unsigned)(r0c * 40 + cc) * 2;                        \
    const unsigned d1b = (unsigned)(r1c * 40 + cc) * 2;                        \
    const unsigned lm_off =                                                    \
        ((unsigned)((lane & 15) * 40 + ((lane >> 4) << 3))) * 2;               \
    const unsigned a_base = sbase + (unsigned)(warpM * 32) * 80 + lm_off;      \
    const unsigned b_base = sbase + (unsigned)(warpN * 64) * 80 + lm_off;      \
    const int nch = Kdim / 32;                                                 \
    ISSUE(0);  CP_COMMIT();                                                    \
    ISSUE(1);  CP_COMMIT();                                                    \
    for (int ch = 0; ch < nch; ch++) {                                         \
        CP_WAIT1();                                                            \
        __syncthreads();                                                       \
        if (ch + 2 < nch) { ISSUE((ch + 2) % 3); }                             \
        CP_COMMIT();                                                           \
        const unsigned st = (unsigned)(ch % 3) * (STG_HALVES * 2);             \
        _Pragma("unroll")                                                      \
        for (int ks = 0; ks < 2; ks++) {                                       \
            const unsigned kb2 = (unsigned)(ks * 16) * 2;                      \
            unsigned ah[2][4];                                                 \
            _Pragma("unroll")                                                  \
            for (int mi = 0; mi < 2; mi++) {                                   \
                unsigned aa = a_base + st + (unsigned)(mi * 16) * 80 + kb2;    \
                LDSM4(ah[mi][0], ah[mi][1], ah[mi][2], ah[mi][3], aa);         \
            }                                                                  \
            _Pragma("unroll")                                                  \
            for (int nip = 0; nip < 4; nip++) {                                \
                unsigned ba = b_base + st + ARR_HALVES*2                       \
                            + (unsigned)(nip * 16) * 80 + kb2;                 \
                unsigned b0e, b0o_, b1e, b1o_;                                 \
                LDSM4(b0e, b0o_, b1e, b1o_, ba);                               \
                _Pragma("unroll")                                              \
                for (int mi = 0; mi < 2; mi++) {                               \
                    MMA16816(acc[mi][2*nip],   ah[mi], b0e, b1e);              \
                    MMA16816(acc[mi][2*nip+1], ah[mi], b0o_, b1o_);            \
                }                                                              \
            }                                                                  \
        }                                                                      \
    }

#define ISSUE(s)                                                               \
    do {                                                                       \
        unsigned sb = sbase + (unsigned)(s) * (STG_HALVES * 2);                \
        CP16(sb + d0b,                  pA0);                                  \
        CP16(sb + d1b,                  pA1);                                  \
        CP16(sb + d0b + ARR_HALVES*2,   pB0);                                  \
        CP16(sb + d1b + ARR_HALVES*2,   pB1);                                  \
        pA0 += 32; pA1 += 32; pB0 += 32; pB1 += 32;                            \
    } while (0)

// ---------------------------------------------------------------------------
// QKV GEMM with fused RoPE + dtype-split epilogue (unchanged R12).
// ---------------------------------------------------------------------------
__global__ __launch_bounds__(256, 2)
void qkv_gemm_kernel(const int* __restrict__ pos)
{
    GEMM_MAINLOOP(g_xh, g_wqh, DMODEL)

    const int region = (blockIdx.x * 128) >> 10;   // 0=Q, 1=K, 2=V

    #pragma unroll
    for (int mi = 0; mi < 2; mi++) {
        int r0 = m0 + warpM*32 + mi*16 + g;
        float p0 = (float)pos[r0 & (SEQ-1)];
        float p1 = (float)pos[(r0+8) & (SEQ-1)];
        #pragma unroll
        for (int ni = 0; ni < 8; ni++) {
            int cg  = n0 + warpN*64 + ni*8 + tg*2;
            int col = cg & (DMODEL-1);
            float x0 = acc[mi][ni][0], y0 = acc[mi][ni][1];
            float x1 = acc[mi][ni][2], y1 = acc[mi][ni][3];
            if (region < 2) {   // rope for Q and K
                int i = (col & 63) >> 1;
                float inv = expf(-((float)i * (1.0f/32.0f)) * 9.2103403719761836f);
                float sn0, cs0, sn1, cs1;
                sincosf(p0 * inv, &sn0, &cs0);
                sincosf(p1 * inv, &sn1, &cs1);
                float t;
                t = x0*cs0 - y0*sn0; y0 = x0*sn0 + y0*cs0; x0 = t;
                t = x1*cs1 - y1*sn1; y1 = x1*sn1 + y1*cs1; x1 = t;
            }
            size_t o0 = (size_t)r0 * DMODEL + col;
            size_t o1 = (size_t)(r0+8) * DMODEL + col;
            if (region == 0) {
                *(float2*)&g_qf32[o0] = make_float2(x0, y0);
                *(float2*)&g_qf32[o1] = make_float2(x1, y1);
            } else if (region == 1) {
                *(unsigned*)&g_kh[o0] = pack_h(x0, y0);
                *(unsigned*)&g_kh[o1] = pack_h(x1, y1);
            } else {
                *(unsigned*)&g_vh[o0] = pack_h(x0, y0);
                *(unsigned*)&g_vh[o1] = pack_h(x1, y1);
            }
        }
    }
}

// ---------------------------------------------------------------------------
// Output GEMM (generic fp32 epilogue).
// ---------------------------------------------------------------------------
__global__ __launch_bounds__(256, 2)
void out_gemm_kernel(float* __restrict__ out)
{
    GEMM_MAINLOOP(g_ah, g_woh, DMODEL)

    #pragma unroll
    for (int mi = 0; mi < 2; mi++) {
        int r0 = m0 + warpM*32 + mi*16 + g;
        #pragma unroll
        for (int ni = 0; ni < 8; ni++) {
            int c = n0 + warpN*64 + ni*8 + tg*2;
            *(float2*)&out[(size_t)r0 * DMODEL + c] =
                make_float2(acc[mi][ni][0], acc[mi][ni][1]);
            *(float2*)&out[(size_t)(r0+8) * DMODEL + c] =
                make_float2(acc[mi][ni][2], acc[mi][ni][3]);
        }
    }
}
#undef ISSUE

// ---------------------------------------------------------------------------
// Causal flash attention, fp16 tensor cores (paired q-tiles, exp2).
// R14: V stored row-major (uint4 copy, scalar transpose deleted);
// K-fragments via ldmatrix.x4, V-fragments via ldmatrix.x4.trans.
// Identical mma sequence/rounding to R13.
// ---------------------------------------------------------------------------
__global__ __launch_bounds__(256)
void attn_mma_kernel()
{
    const int h   = blockIdx.y;
    const int b   = blockIdx.z;
    const int tid = threadIdx.x;
    const int lane = tid & 31;
    const int w   = tid >> 5;
    const int g   = lane >> 2;
    const int tg  = lane & 3;

    __shared__ __half sKh[2][64*72], sVh[2][64*72];

    const unsigned skh0 = (unsigned)__cvta_generic_to_shared(&sKh[0][0]);
    const unsigned skh1 = (unsigned)__cvta_generic_to_shared(&sKh[1][0]);
    const unsigned svh0 = (unsigned)__cvta_generic_to_shared(&sVh[0][0]);
    const unsigned svh1 = (unsigned)__cvta_generic_to_shared(&sVh[1][0]);

    // per-lane ldmatrix offsets (halves), derived from PTX fragment layout:
    // K (non-trans): mat m=l>>3: kv_local=(m>>1)*8+(l&7), d_local=(m&1)*8
    const unsigned koff = ((((lane >> 4) & 1) * 8 + (lane & 7)) * 72
                          + ((lane >> 3) & 1) * 8) * 2;
    // V (trans): mat m=l>>3: kv_local=(m&1)*8+(l&7), d_local=(m>>1)*8
    const unsigned voff = ((((lane >> 3) & 1) * 8 + (lane & 7)) * 72
                          + ((lane >> 4) & 1) * 8) * 2;

    const float scale = 0.125f * 1.44269504088896f;   // 1/sqrt(64) * log2(e)

    uint4 pk2[2], pv2[2];

    #define GLT(kt_)                                                           \
        _Pragma("unroll")                                                      \
        for (int i = 0; i < 2; i++) {                                          \
            int idx = tid + i*256;                                             \
            int r = idx >> 3, c8 = (idx & 7) << 3;                             \
            size_t base = ((size_t)(b*SEQ) + (kt_)*64 + r)*DMODEL + h*DK + c8; \
            pk2[i] = *(const uint4*)&g_kh[base];                               \
            pv2[i] = *(const uint4*)&g_vh[base];                               \
        }

    #define STS_T(buf_)                                                        \
        _Pragma("unroll")                                                      \
        for (int i = 0; i < 2; i++) {                                          \
            int idx = tid + i*256;                                             \
            int r = idx >> 3, c8 = (idx & 7) << 3;                             \
            *(uint4*)&sKh[buf_][r*72 + c8] = pk2[i];                           \
            *(uint4*)&sVh[buf_][r*72 + c8] = pv2[i];                           \
        }

    #pragma unroll 1
    for (int half = 0; half < 2; half++) {
        const int qt = half ? (NTQ - 1 - blockIdx.x) : blockIdx.x;
        const int qbase = qt * 128;
        const int row0 = qbase + w*16 + g;
        const int row1 = row0 + 8;
        const int wrowmax = qbase + w*16 + 15;

        unsigned qh[4][4];
        {
            const float* q0 = &g_qf32[((size_t)(b*SEQ) + row0)*DMODEL + h*DK];
            const float* q1 = &g_qf32[((size_t)(b*SEQ) + row1)*DMODEL + h*DK];
            #pragma unroll
            for (int kk = 0; kk < 4; kk++) {
                int d0 = kk*16 + 2*tg;
                float2 a0 = *(const float2*)&q0[d0];
                float2 a1 = *(const float2*)&q1[d0];
                float2 a2 = *(const float2*)&q0[d0+8];
                float2 a3 = *(const float2*)&q1[d0+8];
                qh[kk][0] = pack_h(a0.x*scale, a0.y*scale);
                qh[kk][1] = pack_h(a1.x*scale, a1.y*scale);
                qh[kk][2] = pack_h(a2.x*scale, a2.y*scale);
                qh[kk][3] = pack_h(a3.x*scale, a3.y*scale);
            }
        }

        float o[8][4] = {};
        float m0 = -1e30f, m1 = -1e30f, l0 = 0.f, l1 = 0.f;

        const int ntiles = 2*qt + 2;

        GLT(0);
        STS_T(0);
        __syncthreads();

        for (int kt = 0; kt < ntiles; kt++) {
            const int kvbase = kt * 64;
            const int buf = kt & 1;
            const unsigned kb = (buf ? skh1 : skh0) + koff;
            const unsigned vb = (buf ? svh1 : svh0) + voff;

            if (kt + 1 < ntiles) { GLT(kt + 1); }

            if (kvbase <= wrowmax) {
                float sc[8][4] = {};

                // QK^T: K frags via ldmatrix.x4 (2 n8-tiles x k16 per load)
                #pragma unroll
                for (int kk = 0; kk < 4; kk++) {
                    #pragma unroll
                    for (int ni = 0; ni < 8; ni += 2) {
                        unsigned bb0, bb1, bb2, bb3;
                        unsigned addr = kb + (unsigned)(ni*576 + kk*16) * 2;
                        LDSM4(bb0, bb1, bb2, bb3, addr);
                        MMA16816(sc[ni],   qh[kk], bb0, bb1);
                        MMA16816(sc[ni+1], qh[kk], bb2, bb3);
                    }
                }

                if (kvbase + 63 > row0) {
                    #pragma unroll
                    for (int ni = 0; ni < 8; ni++) {
                        int c = kvbase + ni*8 + 2*tg;
                        if (c     > row0) sc[ni][0] = -1e30f;
                        if (c + 1 > row0) sc[ni][1] = -1e30f;
                        if (c     > row1) sc[ni][2] = -1e30f;
                        if (c + 1 > row1) sc[ni][3] = -1e30f;
                    }
                }

                float t0 = -1e30f, t1 = -1e30f;
                #pragma unroll
                for (int ni = 0; ni < 8; ni++) {
                    t0 = fmaxf(t0, fmaxf(sc[ni][0], sc[ni][1]));
                    t1 = fmaxf(t1, fmaxf(sc[ni][2], sc[ni][3]));
                }
                t0 = fmaxf(t0, __shfl_xor_sync(0xffffffffu, t0, 1));
                t0 = fmaxf(t0, __shfl_xor_sync(0xffffffffu, t0, 2));
                t1 = fmaxf(t1, __shfl_xor_sync(0xffffffffu, t1, 1));
                t1 = fmaxf(t1, __shfl_xor_sync(0xffffffffu, t1, 2));

                float m0n = fmaxf(m0, t0), m1n = fmaxf(m1, t1);
                float c0 = exp2f(m0 - m0n), c1 = exp2f(m1 - m1n);
                m0 = m0n; m1 = m1n;
                l0 *= c0;  l1 *= c1;
                #pragma unroll
                for (int ni = 0; ni < 8; ni++) {
                    o[ni][0] *= c0; o[ni][1] *= c0;
                    o[ni][2] *= c1; o[ni][3] *= c1;
                }

                #pragma unroll
                for (int ni = 0; ni < 8; ni++) {
                    sc[ni][0] = exp2f(sc[ni][0] - m0);
                    sc[ni][1] = exp2f(sc[ni][1] - m0);
                    sc[ni][2] = exp2f(sc[ni][2] - m1);
                    sc[ni][3] = exp2f(sc[ni][3] - m1);
                    l0 += sc[ni][0] + sc[ni][1];
                    l1 += sc[ni][2] + sc[ni][3];
                }

                // PV: V frags via ldmatrix.x4.trans from row-major V
                #pragma unroll
                for (int kk = 0; kk < 4; kk++) {
                    unsigned ph[4];
                    ph[0] = pack_h(sc[2*kk][0],   sc[2*kk][1]);
                    ph[1] = pack_h(sc[2*kk][2],   sc[2*kk][3]);
                    ph[2] = pack_h(sc[2*kk+1][0], sc[2*kk+1][1]);
                    ph[3] = pack_h(sc[2*kk+1][2], sc[2*kk+1][3]);
                    #pragma unroll
                    for (int nd = 0; nd < 8; nd += 2) {
                        unsigned bb0, bb1, bb2, bb3;
                        unsigned addr = vb + (unsigned)(kk*16*72 + nd*8) * 2;
                        LDSM4T(bb0, bb1, bb2, bb3, addr);
                        MMA16816(o[nd],   ph, bb0, bb1);
                        MMA16816(o[nd+1], ph, bb2, bb3);
                    }
                }
            }

            if (kt + 1 < ntiles) { STS_T(buf ^ 1); }
            __syncthreads();
        }

        l0 += __shfl_xor_sync(0xffffffffu, l0, 1);
        l0 += __shfl_xor_sync(0xffffffffu, l0, 2);
        l1 += __shfl_xor_sync(0xffffffffu, l1, 1);
        l1 += __shfl_xor_sync(0xffffffffu, l1, 2);
        float inv0 = 1.f / l0, inv1 = 1.f / l1;

        size_t base0 = ((size_t)(b*SEQ) + row0)*DMODEL + h*DK;
        size_t base1 = ((size_t)(b*SEQ) + row1)*DMODEL + h*DK;
        #pragma unroll
        for (int nd = 0; nd < 8; nd++) {
            int c = nd*8 + 2*tg;
            *(unsigned*)&g_ah[base0 + c] = pack_h(o[nd][0]*inv0, o[nd][1]*inv0);
            *(unsigned*)&g_ah[base1 + c] = pack_h(o[nd][2]*inv1, o[nd][3]*inv1);
        }
    }
    #undef GLT
    #undef STS_T
}

// ---------------------------------------------------------------------------
extern "C" void kernel_launch(void* const* d_in, const int* in_sizes, int n_in,
                              void* d_out, int out_size)
{
    const float* x      = (const float*)d_in[0];
    const int*   pos    = (const int*)d_in[1];
    const float* w_qkv  = (const float*)d_in[2];
    const float* w_o    = (const float*)d_in[3];
    float*       out    = (float*)d_out;

    cudaFuncSetAttribute(qkv_gemm_kernel,
                         cudaFuncAttributeMaxDynamicSharedMemorySize, GEMM_SMEM);
    cudaFuncSetAttribute(out_gemm_kernel,
                         cudaFuncAttributeMaxDynamicSharedMemorySize, GEMM_SMEM);

    // 0) fp16 converts (single fused launch)
    cvt_all_kernel<<<(CVT_TOT + 255)/256, 256>>>(x, w_qkv, w_o);

    // 1) QKV projection + fused RoPE + dtype split
    {
        dim3 grid(E3 / 128, NTOK / 128);
        qkv_gemm_kernel<<<grid, 256, GEMM_SMEM>>>(pos);
    }
    // 2) Causal flash attention (ldmatrix fragment loads)
    {
        dim3 grid(NTQ / 2, NHEADS, BATCH);
        attn_mma_kernel<<<grid, 256>>>();
    }
    // 3) Output projection
    {
        dim3 grid(DMODEL / 128, NTOK / 128);
        out_gemm_kernel<<<grid, 256, GEMM_SMEM>>>(out);
    }
}